// round 6
// baseline (speedup 1.0000x reference)
#include <cuda_runtime.h>
#include <cuda_bf16.h>
#include <math.h>

// ---------------------------------------------------------------------------
// Problem constants: V=32000, E=512, H=512, L=2, B=8, S=512
// ---------------------------------------------------------------------------
#define SS   512
#define BB   8
#define EE   512
#define HH   512
#define D2   1024      // 2H
#define G4   2048      // 4H
#define VV   32000
#define NROW 4096      // B*S

// ---------------------------------------------------------------------------
// Device scratch (no cudaMalloc allowed)
// ---------------------------------------------------------------------------
__device__ float g_embx  [NROW * EE];     // embedded input
__device__ float g_xf    [NROW * G4];     // forward x-projection (gates pre-add)
__device__ float g_xb    [NROW * G4];     // backward x-projection
__device__ float g_hf    [NROW * HH];     // forward hidden states
__device__ float g_hb    [NROW * HH];     // backward hidden states
__device__ float g_lay   [NROW * D2];     // layer output / encoded
__device__ float g_query [NROW * D2];
__device__ float g_scores[BB * SS * SS];
__device__ float g_ctx   [NROW * D2];
__device__ float g_pre   [NROW * D2];
__device__ float g_ref   [NROW * D2];
__device__ float g_hpre  [NROW * HH];
__device__ float g_head  [NROW * HH];
__device__ float g_hcur  [2 * 2 * BB * HH];  // [dir][buf][unit*8+b]
__device__ int   g_len   [BB];
__device__ unsigned g_barcnt;

__device__ __forceinline__ float sigm(float x) { return 1.f / (1.f + expf(-x)); }

// ---------------------------------------------------------------------------
// lengths per batch
// ---------------------------------------------------------------------------
__global__ void len_kernel(const int* __restrict__ x, int* __restrict__ len) {
    __shared__ int red[512];
    int b = blockIdx.x, tid = threadIdx.x;
    red[tid] = (x[b * SS + tid] != 0) ? 1 : 0;
    __syncthreads();
    for (int s = 256; s > 0; s >>= 1) {
        if (tid < s) red[tid] += red[tid + s];
        __syncthreads();
    }
    if (tid == 0) len[b] = red[0];
}

// ---------------------------------------------------------------------------
// embedding gather: one block per row, 128 threads x float4 (512 floats)
// ---------------------------------------------------------------------------
__global__ void embed_kernel(const int* __restrict__ x, const float* __restrict__ emb,
                             float* __restrict__ out) {
    int r = blockIdx.x;
    long tok = (long)x[r];
    float4 v = ((const float4*)(emb + tok * EE))[threadIdx.x];
    ((float4*)(out + (long)r * EE))[threadIdx.x] = v;
}

// ---------------------------------------------------------------------------
// Generic fp32 GEMM: C[M,N] = A[M,K] @ W[K,N] (+bias) (+=C if accum)
// Tiles 128x64x16, 256 threads, 8x4 microtile. All dims divide evenly.
// Optional batching via blockIdx.z with long strides.
// ---------------------------------------------------------------------------
__global__ __launch_bounds__(256) void gemm_nn(
    const float* __restrict__ A, const float* __restrict__ W,
    const float* __restrict__ bias, float* __restrict__ C,
    int M, int N, int K, int lda, int ldw, int ldc,
    long sA, long sW, long sC, int accum)
{
    A += (long)blockIdx.z * sA;
    W += (long)blockIdx.z * sW;
    C += (long)blockIdx.z * sC;
    const int m0 = blockIdx.y * 128, n0 = blockIdx.x * 64;
    __shared__ float As[16][132];
    __shared__ float Bs[16][68];
    const int tid = threadIdx.x;
    const int tx = tid & 15, ty = tid >> 4;
    float acc[8][4];
#pragma unroll
    for (int i = 0; i < 8; i++)
#pragma unroll
        for (int j = 0; j < 4; j++) acc[i][j] = 0.f;

    for (int k0 = 0; k0 < K; k0 += 16) {
#pragma unroll
        for (int l = 0; l < 2; l++) {
            int f = tid * 2 + l;
            int row = f >> 2, q = f & 3;
            float4 v = *(const float4*)(A + (long)(m0 + row) * lda + k0 + q * 4);
            As[q * 4 + 0][row] = v.x; As[q * 4 + 1][row] = v.y;
            As[q * 4 + 2][row] = v.z; As[q * 4 + 3][row] = v.w;
        }
        {
            int row = tid >> 4, c4 = tid & 15;
            *(float4*)&Bs[row][c4 * 4] =
                *(const float4*)(W + (long)(k0 + row) * ldw + n0 + c4 * 4);
        }
        __syncthreads();
#pragma unroll
        for (int k = 0; k < 16; k++) {
            float4 b4 = *(const float4*)&Bs[k][tx * 4];
            float4 a0 = *(const float4*)&As[k][ty * 8];
            float4 a1 = *(const float4*)&As[k][ty * 8 + 4];
            float ar[8] = {a0.x, a0.y, a0.z, a0.w, a1.x, a1.y, a1.z, a1.w};
            float br[4] = {b4.x, b4.y, b4.z, b4.w};
#pragma unroll
            for (int i = 0; i < 8; i++)
#pragma unroll
                for (int j = 0; j < 4; j++)
                    acc[i][j] = fmaf(ar[i], br[j], acc[i][j]);
        }
        __syncthreads();
    }
    float4 bv = make_float4(0.f, 0.f, 0.f, 0.f);
    if (bias) bv = *(const float4*)(bias + n0 + tx * 4);
#pragma unroll
    for (int i = 0; i < 8; i++) {
        long off = (long)(m0 + ty * 8 + i) * ldc + n0 + tx * 4;
        float4 o;
        o.x = acc[i][0] + bv.x; o.y = acc[i][1] + bv.y;
        o.z = acc[i][2] + bv.z; o.w = acc[i][3] + bv.w;
        if (accum) {
            float4 c = *(const float4*)(C + off);
            o.x += c.x; o.y += c.y; o.z += c.z; o.w += c.w;
        }
        *(float4*)(C + off) = o;
    }
}

// ---------------------------------------------------------------------------
// Attention score GEMM (NT): Sc[b,m,n] = scale * dot(Q[b,m,:], E[b,n,:])
// 64x64 tiles, 256 threads, 4x4 microtile, K=1024.
// ---------------------------------------------------------------------------
__global__ __launch_bounds__(256) void gemm_nt_scores(
    const float* __restrict__ Q, const float* __restrict__ E,
    float* __restrict__ C)
{
    const int b = blockIdx.z;
    const float* Qb = Q + (long)b * SS * D2;
    const float* Eb = E + (long)b * SS * D2;
    float* Cb = C + (long)b * SS * SS;
    const int m0 = blockIdx.y * 64, n0 = blockIdx.x * 64;
    __shared__ float Qs[16][68];
    __shared__ float Es[16][68];
    const int tid = threadIdx.x;
    const int tx = tid & 15, ty = tid >> 4;
    float acc[4][4];
#pragma unroll
    for (int i = 0; i < 4; i++)
#pragma unroll
        for (int j = 0; j < 4; j++) acc[i][j] = 0.f;

    for (int k0 = 0; k0 < D2; k0 += 16) {
        int row = tid >> 2, q = tid & 3;
        float4 v = *(const float4*)(Qb + (long)(m0 + row) * D2 + k0 + q * 4);
        Qs[q * 4 + 0][row] = v.x; Qs[q * 4 + 1][row] = v.y;
        Qs[q * 4 + 2][row] = v.z; Qs[q * 4 + 3][row] = v.w;
        v = *(const float4*)(Eb + (long)(n0 + row) * D2 + k0 + q * 4);
        Es[q * 4 + 0][row] = v.x; Es[q * 4 + 1][row] = v.y;
        Es[q * 4 + 2][row] = v.z; Es[q * 4 + 3][row] = v.w;
        __syncthreads();
#pragma unroll
        for (int k = 0; k < 16; k++) {
            float4 a4 = *(const float4*)&Qs[k][ty * 4];
            float4 b4 = *(const float4*)&Es[k][tx * 4];
            float ar[4] = {a4.x, a4.y, a4.z, a4.w};
            float br[4] = {b4.x, b4.y, b4.z, b4.w};
#pragma unroll
            for (int i = 0; i < 4; i++)
#pragma unroll
                for (int j = 0; j < 4; j++)
                    acc[i][j] = fmaf(ar[i], br[j], acc[i][j]);
        }
        __syncthreads();
    }
    const float scale = 0.03125f;  // (2H)^-0.5 = 1/32
#pragma unroll
    for (int i = 0; i < 4; i++)
#pragma unroll
        for (int j = 0; j < 4; j++)
            Cb[(long)(m0 + ty * 4 + i) * SS + n0 + tx * 4 + j] = acc[i][j] * scale;
}

// ---------------------------------------------------------------------------
// Masked softmax per (b, q) row; rows with q >= len become all-zero.
// ---------------------------------------------------------------------------
__global__ void softmax_kernel(float* __restrict__ sc, const int* __restrict__ len) {
    const int q = blockIdx.x, b = blockIdx.y;
    float* row = sc + ((long)b * SS + q) * SS;
    const int L = len[b];
    const int t = threadIdx.x;
    __shared__ float red[256];
    if (q >= L) {
        for (int i = t; i < SS; i += 256) row[i] = 0.f;
        return;
    }
    float m = -3.402823466e38f;
    for (int i = t; i < L; i += 256) m = fmaxf(m, row[i]);
    red[t] = m; __syncthreads();
    for (int s = 128; s > 0; s >>= 1) {
        if (t < s) red[t] = fmaxf(red[t], red[t + s]);
        __syncthreads();
    }
    m = red[0]; __syncthreads();
    float sum = 0.f;
    for (int i = t; i < L; i += 256) sum += expf(row[i] - m);
    red[t] = sum; __syncthreads();
    for (int s = 128; s > 0; s >>= 1) {
        if (t < s) red[t] += red[t + s];
        __syncthreads();
    }
    float inv = 1.f / red[0];
    for (int i = t; i < SS; i += 256)
        row[i] = (i < L) ? expf(row[i] - m) * inv : 0.f;
}

// ---------------------------------------------------------------------------
// Build layer input: lay[r] = valid ? concat(hf[r], hb[r]) : 0
// ---------------------------------------------------------------------------
__global__ void build_lay(const float* __restrict__ hf, const float* __restrict__ hb,
                          const int* __restrict__ len, float* __restrict__ lay) {
    int r = blockIdx.x;
    int b = r >> 9, tt = r & 511;
    int active = tt < len[b];
    int t = threadIdx.x;
    for (int i = t; i < D2; i += 256) {
        float v = 0.f;
        if (active) v = (i < HH) ? hf[(long)r * HH + i] : hb[(long)r * HH + i - HH];
        lay[(long)r * D2 + i] = v;
    }
}

// ---------------------------------------------------------------------------
// refined = LN(encoded + tanh(pre)) masked by valid
// ---------------------------------------------------------------------------
__global__ void refine_ln(const float* __restrict__ enc, const float* __restrict__ pre,
                          const float* __restrict__ g, const float* __restrict__ bta,
                          const int* __restrict__ len, float* __restrict__ out) {
    int r = blockIdx.x;
    int b = r >> 9, tt = r & 511;
    int t = threadIdx.x;
    __shared__ float r1[256], r2[256];
    float v[4];
    float s = 0.f, s2 = 0.f;
#pragma unroll
    for (int i = 0; i < 4; i++) {
        int idx = t + i * 256;
        float xx = enc[(long)r * D2 + idx] + tanhf(pre[(long)r * D2 + idx]);
        v[i] = xx; s += xx; s2 += xx * xx;
    }
    r1[t] = s; r2[t] = s2; __syncthreads();
    for (int st = 128; st > 0; st >>= 1) {
        if (t < st) { r1[t] += r1[t + st]; r2[t] += r2[t + st]; }
        __syncthreads();
    }
    float mean = r1[0] * (1.f / 1024.f);
    float var = r2[0] * (1.f / 1024.f) - mean * mean;
    float inv = rsqrtf(var + 1e-5f);
    int active = tt < len[b];
#pragma unroll
    for (int i = 0; i < 4; i++) {
        int idx = t + i * 256;
        float o = (v[i] - mean) * inv * g[idx] + bta[idx];
        out[(long)r * D2 + idx] = active ? o : 0.f;
    }
}

// ---------------------------------------------------------------------------
// head = LN(gelu_exact(hpre))
// ---------------------------------------------------------------------------
__global__ void head_ln(const float* __restrict__ hpre, const float* __restrict__ g,
                        const float* __restrict__ bta, float* __restrict__ out) {
    int r = blockIdx.x;
    int t = threadIdx.x;
    __shared__ float r1[256], r2[256];
    float v[2];
    float s = 0.f, s2 = 0.f;
#pragma unroll
    for (int i = 0; i < 2; i++) {
        int idx = t + i * 256;
        float xx = hpre[(long)r * HH + idx];
        float ge = 0.5f * xx * (1.f + erff(xx * 0.70710678118654752f));
        v[i] = ge; s += ge; s2 += ge * ge;
    }
    r1[t] = s; r2[t] = s2; __syncthreads();
    for (int st = 128; st > 0; st >>= 1) {
        if (t < st) { r1[t] += r1[t + st]; r2[t] += r2[t + st]; }
        __syncthreads();
    }
    float mean = r1[0] * (1.f / 512.f);
    float var = r2[0] * (1.f / 512.f) - mean * mean;
    float inv = rsqrtf(var + 1e-5f);
#pragma unroll
    for (int i = 0; i < 2; i++) {
        int idx = t + i * 256;
        out[(long)r * HH + idx] = (v[i] - mean) * inv * g[idx] + bta[idx];
    }
}

// ---------------------------------------------------------------------------
// Reset grid barrier counter
// ---------------------------------------------------------------------------
__global__ void reset_bar() { g_barcnt = 0u; }

// ---------------------------------------------------------------------------
// Persistent BiLSTM scan. 256 blocks: 0-127 forward, 128-255 backward.
// Block kb owns hidden units [kb*4, kb*4+4) -> 16 gate columns.
// Recurrent weights cached in SMEM once; h exchanged via double-buffered
// global (L2) with a monotonic atomic grid barrier per step.
// Dynamic smem: Ws[16][512] + hsT[512][9] + part[128][33] + cst[32]
// NOTE: hsT row stride is 9 floats (36B) -> NEVER use vector loads on hsT;
// scalar LDS with odd stride is 16B-safe and bank-conflict-free (9 odd).
// ---------------------------------------------------------------------------
#define LSTM_SMEM_FLOATS (16 * 512 + 512 * 9 + 128 * 33 + 32)

__global__ __launch_bounds__(256, 2) void lstm_scan(
    const float* __restrict__ xf, const float* __restrict__ xb,
    const float* __restrict__ Wrf, const float* __restrict__ Wrb,
    const float* __restrict__ h0f, const float* __restrict__ c0f,
    const float* __restrict__ h0b, const float* __restrict__ c0b,
    float* __restrict__ houtf, float* __restrict__ houtb,
    float* __restrict__ hcur, const int* __restrict__ len)
{
    extern __shared__ float sm[];
    float* Ws   = sm;                       // [16][512] col-major recurrent weights
    float* hsT  = sm + 16 * 512;            // [512][9]  transposed h (pad 9)
    float* part = hsT + 512 * 9;            // [128][33] partial sums
    float* cst  = part + 128 * 33;          // [32] cell state (u*8+b)

    const int tid = threadIdx.x;
    const int dir = blockIdx.x >> 7;
    const int kb  = blockIdx.x & 127;
    const int j0  = kb * 4;
    const float* Wr = dir ? Wrb : Wrf;
    const float* xp = dir ? xb : xf;
    const float* h0 = dir ? h0b : h0f;
    const float* c0 = dir ? c0b : c0f;
    float* hout  = dir ? houtb : houtf;
    float* hbase = hcur + dir * (2 * BB * HH);

    // one-time weight stage: Ws[col][k] = Wr[k*2048 + gate*512 + j0 + unit]
    {
        int col = tid & 15;
        int gcol = (col >> 2) * 512 + j0 + (col & 3);
        for (int k = tid >> 4; k < 512; k += 16)
            Ws[col * 512 + k] = Wr[(long)k * G4 + gcol];
    }
    // init h/c
    if (tid < 32) {
        int u = tid >> 3, b = tid & 7;
        cst[u * 8 + b] = c0[j0 + u];
        __stcg(&hbase[(j0 + u) * 8 + b], h0[j0 + u]);
    }

    const int ks = tid & 31;
    const int bg = (tid >> 5) & 1;
    const int cg = tid >> 6;
    unsigned phase = 1;

    // grid barrier macro (monotonic counter)
#define GRIDBAR()                                                         \
    do {                                                                  \
        __syncthreads();                                                  \
        if (tid == 0) {                                                   \
            __threadfence();                                              \
            atomicAdd(&g_barcnt, 1u);                                     \
            unsigned tgt = 256u * phase;                                  \
            while (*(volatile unsigned*)&g_barcnt < tgt) {}               \
        }                                                                 \
        __syncthreads();                                                  \
        phase++;                                                          \
    } while (0)

    GRIDBAR();  // all init h visible

    for (int s = 0; s < SS; s++) {
        const float* hrd = hbase + (s & 1) * (BB * HH);
        float* hwr = hbase + ((s + 1) & 1) * (BB * HH);

        // stage h (all units, all batches) into smem, bypassing L1
        for (int f = tid; f < BB * HH; f += 256)
            hsT[(f >> 3) * 9 + (f & 7)] = __ldcg(hrd + f);
        __syncthreads();

        // GEMV: acc[c][j] over k-split
        float acc[4][4];
#pragma unroll
        for (int c = 0; c < 4; c++)
#pragma unroll
            for (int j = 0; j < 4; j++) acc[c][j] = 0.f;

#pragma unroll 4
        for (int i = 0; i < 16; i++) {
            int k = ks + 32 * i;
            // scalar loads: 36B row stride is not float4-safe; odd stride (9)
            // gives a bank permutation -> conflict-free
            float h0v = hsT[k * 9 + bg * 4 + 0];
            float h1v = hsT[k * 9 + bg * 4 + 1];
            float h2v = hsT[k * 9 + bg * 4 + 2];
            float h3v = hsT[k * 9 + bg * 4 + 3];
#pragma unroll
            for (int c = 0; c < 4; c++) {
                float w = Ws[(cg * 4 + c) * 512 + k];
                acc[c][0] = fmaf(w, h0v, acc[c][0]);
                acc[c][1] = fmaf(w, h1v, acc[c][1]);
                acc[c][2] = fmaf(w, h2v, acc[c][2]);
                acc[c][3] = fmaf(w, h3v, acc[c][3]);
            }
        }
#pragma unroll
        for (int c = 0; c < 4; c++)
#pragma unroll
            for (int j = 0; j < 4; j++)
                part[((cg * 4 + c) * 8 + bg * 4 + j) * 33 + ks] = acc[c][j];
        __syncthreads();

        const int t_real = dir ? (SS - 1 - s) : s;

        // reduce 32 k-splits + add x-projection
        if (tid < 128) {
            float ssum = 0.f;
#pragma unroll
            for (int i = 0; i < 32; i++) ssum += part[tid * 33 + i];
            int col = tid >> 3, b = tid & 7;
            int gg = col >> 2, u = col & 3;
            ssum += xp[((long)(b * SS + t_real)) * G4 + gg * 512 + j0 + u];
            part[tid * 33 + 32] = ssum;
        }
        __syncthreads();

        // LSTM pointwise update for own 4 units x 8 batches
        if (tid < 32) {
            int u = tid >> 3, b = tid & 7;
            float ig = part[((0  + u) * 8 + b) * 33 + 32];
            float fg = part[((4  + u) * 8 + b) * 33 + 32];
            float og = part[((8  + u) * 8 + b) * 33 + 32];
            float gg = part[((12 + u) * 8 + b) * 33 + 32];
            float cp = cst[u * 8 + b];
            float hp = hsT[(j0 + u) * 9 + b];
            float cn = sigm(fg) * cp + sigm(ig) * tanhf(gg);
            float hn = sigm(og) * tanhf(cn);
            int active = t_real < len[b];
            float h = active ? hn : hp;
            float c = active ? cn : cp;
            cst[u * 8 + b] = c;
            __stcg(&hwr[(j0 + u) * 8 + b], h);
            hout[((long)(b * SS + t_real)) * HH + j0 + u] = h;
        }
        GRIDBAR();
    }
#undef GRIDBAR
}

// ---------------------------------------------------------------------------
// Host driver
// ---------------------------------------------------------------------------
extern "C" void kernel_launch(void* const* d_in, const int* in_sizes, int n_in,
                              void* d_out, int out_size) {
    const int*   x    = (const int*)  d_in[0];
    const float* emb  = (const float*)d_in[1];
    const float* Wf0  = (const float*)d_in[2];
    const float* bf0  = (const float*)d_in[3];
    const float* Wb0  = (const float*)d_in[4];
    const float* bb0  = (const float*)d_in[5];
    const float* Wf1  = (const float*)d_in[6];
    const float* bf1  = (const float*)d_in[7];
    const float* Wb1  = (const float*)d_in[8];
    const float* bb1  = (const float*)d_in[9];
    const float* h0f  = (const float*)d_in[10];
    const float* c0f  = (const float*)d_in[11];
    const float* h0b  = (const float*)d_in[12];
    const float* c0b  = (const float*)d_in[13];
    const float* Wq   = (const float*)d_in[14];
    const float* bq   = (const float*)d_in[15];
    const float* Wao  = (const float*)d_in[16];
    const float* bao  = (const float*)d_in[17];
    const float* ln1g = (const float*)d_in[18];
    const float* ln1b = (const float*)d_in[19];
    const float* Wh   = (const float*)d_in[20];
    const float* bh   = (const float*)d_in[21];
    const float* ln2g = (const float*)d_in[22];
    const float* ln2b = (const float*)d_in[23];
    const float* Wp   = (const float*)d_in[24];
    const float* ob   = (const float*)d_in[25];
    float* out = (float*)d_out;

    float *embx, *xf, *xb, *hf, *hb, *lay, *query, *scores, *ctx, *pre, *ref,
          *hpre, *head, *hcur;
    int* len;
    cudaGetSymbolAddress((void**)&embx,   g_embx);
    cudaGetSymbolAddress((void**)&xf,     g_xf);
    cudaGetSymbolAddress((void**)&xb,     g_xb);
    cudaGetSymbolAddress((void**)&hf,     g_hf);
    cudaGetSymbolAddress((void**)&hb,     g_hb);
    cudaGetSymbolAddress((void**)&lay,    g_lay);
    cudaGetSymbolAddress((void**)&query,  g_query);
    cudaGetSymbolAddress((void**)&scores, g_scores);
    cudaGetSymbolAddress((void**)&ctx,    g_ctx);
    cudaGetSymbolAddress((void**)&pre,    g_pre);
    cudaGetSymbolAddress((void**)&ref,    g_ref);
    cudaGetSymbolAddress((void**)&hpre,   g_hpre);
    cudaGetSymbolAddress((void**)&head,   g_head);
    cudaGetSymbolAddress((void**)&hcur,   g_hcur);
    cudaGetSymbolAddress((void**)&len,    g_len);

    const int lstm_smem = LSTM_SMEM_FLOATS * 4;
    cudaFuncSetAttribute(lstm_scan, cudaFuncAttributeMaxDynamicSharedMemorySize,
                         lstm_smem);

    len_kernel<<<BB, 512>>>(x, len);
    embed_kernel<<<NROW, 128>>>(x, emb, embx);

    // ---- layer 0 ----
    {
        dim3 g(G4 / 64, NROW / 128, 1);
        gemm_nn<<<g, 256>>>(embx, Wf0, bf0, xf, NROW, G4, EE, EE, G4, G4, 0, 0, 0, 0);
        gemm_nn<<<g, 256>>>(embx, Wb0, bb0, xb, NROW, G4, EE, EE, G4, G4, 0, 0, 0, 0);
    }
    reset_bar<<<1, 1>>>();
    lstm_scan<<<256, 256, lstm_smem>>>(xf, xb,
                                       Wf0 + (long)EE * G4, Wb0 + (long)EE * G4,
                                       h0f, c0f, h0b, c0b, hf, hb, hcur, len);
    build_lay<<<NROW, 256>>>(hf, hb, len, lay);

    // ---- layer 1 ----
    {
        dim3 g(G4 / 64, NROW / 128, 1);
        gemm_nn<<<g, 256>>>(lay, Wf1, bf1, xf, NROW, G4, D2, D2, G4, G4, 0, 0, 0, 0);
        gemm_nn<<<g, 256>>>(lay, Wb1, bb1, xb, NROW, G4, D2, D2, G4, G4, 0, 0, 0, 0);
    }
    reset_bar<<<1, 1>>>();
    lstm_scan<<<256, 256, lstm_smem>>>(xf, xb,
                                       Wf1 + (long)D2 * G4, Wb1 + (long)D2 * G4,
                                       h0f + HH, c0f + HH, h0b + HH, c0b + HH,
                                       hf, hb, hcur, len);
    build_lay<<<NROW, 256>>>(hf, hb, len, lay);  // lay = encoded

    // ---- attention ----
    {
        dim3 g(D2 / 64, NROW / 128, 1);
        gemm_nn<<<g, 256>>>(lay, Wq, bq, query, NROW, D2, D2, D2, D2, D2, 0, 0, 0, 0);
    }
    {
        dim3 g(SS / 64, SS / 64, BB);
        gemm_nt_scores<<<g, 256>>>(query, lay, scores);
    }
    {
        dim3 g(SS, BB, 1);
        softmax_kernel<<<g, 256>>>(scores, len);
    }
    {
        dim3 g(D2 / 64, SS / 128, BB);
        gemm_nn<<<g, 256>>>(scores, lay, nullptr, ctx, SS, D2, SS, SS, D2, D2,
                            (long)SS * SS, (long)SS * D2, (long)SS * D2, 0);
    }
    // refined pre-activation: enc@Wao[:D2] + ctx@Wao[D2:] + bao
    {
        dim3 g(D2 / 64, NROW / 128, 1);
        gemm_nn<<<g, 256>>>(lay, Wao, bao, pre, NROW, D2, D2, D2, D2, D2, 0, 0, 0, 0);
        gemm_nn<<<g, 256>>>(ctx, Wao + (long)D2 * D2, nullptr, pre,
                            NROW, D2, D2, D2, D2, D2, 0, 0, 0, 1);
    }
    refine_ln<<<NROW, 256>>>(lay, pre, ln1g, ln1b, len, ref);

    // ---- head ----
    {
        dim3 g(HH / 64, NROW / 128, 1);
        gemm_nn<<<g, 256>>>(ref, Wh, bh, hpre, NROW, HH, D2, D2, HH, HH, 0, 0, 0, 0);
    }
    head_ln<<<NROW, 256>>>(hpre, ln2g, ln2b, head);

    // ---- vocab projection ----
    {
        dim3 g(VV / 64, NROW / 128, 1);
        gemm_nn<<<g, 256>>>(head, Wp, ob, out, NROW, VV, HH, HH, VV, VV, 0, 0, 0, 0);
    }
}

// round 7
// speedup vs baseline: 1.0955x; 1.0955x over previous
#include <cuda_runtime.h>
#include <cuda_bf16.h>
#include <math.h>

// ---------------------------------------------------------------------------
// Problem constants: V=32000, E=512, H=512, L=2, B=8, S=512
// ---------------------------------------------------------------------------
#define SS   512
#define BB   8
#define EE   512
#define HH   512
#define D2   1024      // 2H
#define G4   2048      // 4H
#define VV   32000
#define NROW 4096      // B*S

// ---------------------------------------------------------------------------
// Device scratch (no cudaMalloc allowed)
// ---------------------------------------------------------------------------
__device__ float g_embx  [NROW * EE];
__device__ float g_xf    [NROW * G4];
__device__ float g_xb    [NROW * G4];
__device__ float g_hf    [NROW * HH];
__device__ float g_hb    [NROW * HH];
__device__ float g_lay   [NROW * D2];
__device__ float g_query [NROW * D2];
__device__ float g_scores[BB * SS * SS];
__device__ float g_ctx   [NROW * D2];
__device__ float g_pre   [NROW * D2];
__device__ float g_ref   [NROW * D2];
__device__ float g_hpre  [NROW * HH];
__device__ float g_head  [NROW * HH];
__device__ float g_hcur  [2 * 2 * BB * HH];
__device__ int   g_len   [BB];
__device__ unsigned g_barcnt;

__device__ __forceinline__ float sigm(float x) { return 1.f / (1.f + expf(-x)); }

// ---------------------------------------------------------------------------
// lengths per batch
// ---------------------------------------------------------------------------
__global__ void len_kernel(const int* __restrict__ x, int* __restrict__ len) {
    __shared__ int red[512];
    int b = blockIdx.x, tid = threadIdx.x;
    red[tid] = (x[b * SS + tid] != 0) ? 1 : 0;
    __syncthreads();
    for (int s = 256; s > 0; s >>= 1) {
        if (tid < s) red[tid] += red[tid + s];
        __syncthreads();
    }
    if (tid == 0) len[b] = red[0];
}

// ---------------------------------------------------------------------------
// embedding gather
// ---------------------------------------------------------------------------
__global__ void embed_kernel(const int* __restrict__ x, const float* __restrict__ emb,
                             float* __restrict__ out) {
    int r = blockIdx.x;
    long tok = (long)x[r];
    float4 v = ((const float4*)(emb + tok * EE))[threadIdx.x];
    ((float4*)(out + (long)r * EE))[threadIdx.x] = v;
}

// ---------------------------------------------------------------------------
// fp32 GEMM: C[M,N] = A[M,K] @ W[K,N] (+bias) (+=C if accum)
// Tiles 128x128x16, 256 threads, 8x8 microtile (split-half addressing for
// conflict-free LDS.128), ping-pong double-buffered smem.
// M,N multiples of 128; K multiple of 16.
// ---------------------------------------------------------------------------
__global__ __launch_bounds__(256, 2) void gemm_nn(
    const float* __restrict__ A, const float* __restrict__ W,
    const float* __restrict__ bias, float* __restrict__ C,
    int M, int N, int K, int lda, int ldw, int ldc,
    long sA, long sW, long sC, int accum)
{
    A += (long)blockIdx.z * sA;
    W += (long)blockIdx.z * sW;
    C += (long)blockIdx.z * sC;
    const int m0 = blockIdx.y * 128, n0 = blockIdx.x * 128;
    __shared__ float As[2][16][132];
    __shared__ float Bs[2][16][132];
    const int tid = threadIdx.x;
    const int tx = tid & 15, ty = tid >> 4;

    // loader indices
    const int arow = tid >> 1;            // A row 0..127
    const int akq  = (tid & 1) * 8;       // A k-offset {0,8}
    const int brow = tid >> 4;            // B k-row 0..15
    const int bcol = (tid & 15) * 8;      // B col offset

    const float* Aptr = A + (long)(m0 + arow) * lda + akq;
    const float* Bptr = W + (long)brow * ldw + n0 + bcol;

    float4 pa0, pa1, pb0, pb1;

    // preload first tile
    pa0 = *(const float4*)(Aptr);
    pa1 = *(const float4*)(Aptr + 4);
    pb0 = *(const float4*)(Bptr);
    pb1 = *(const float4*)(Bptr + 4);
    {
        As[0][akq + 0][arow] = pa0.x; As[0][akq + 1][arow] = pa0.y;
        As[0][akq + 2][arow] = pa0.z; As[0][akq + 3][arow] = pa0.w;
        As[0][akq + 4][arow] = pa1.x; As[0][akq + 5][arow] = pa1.y;
        As[0][akq + 6][arow] = pa1.z; As[0][akq + 7][arow] = pa1.w;
        *(float4*)&Bs[0][brow][bcol]     = pb0;
        *(float4*)&Bs[0][brow][bcol + 4] = pb1;
    }
    __syncthreads();

    float acc[8][8];
#pragma unroll
    for (int i = 0; i < 8; i++)
#pragma unroll
        for (int j = 0; j < 8; j++) acc[i][j] = 0.f;

    int buf = 0;
    for (int k0 = 0; k0 < K; k0 += 16) {
        const int nxt = buf ^ 1;
        const bool more = (k0 + 16) < K;
        if (more) {
            pa0 = *(const float4*)(Aptr + k0 + 16);
            pa1 = *(const float4*)(Aptr + k0 + 20);
            pb0 = *(const float4*)(Bptr + (long)(k0 + 16) * ldw);
            pb1 = *(const float4*)(Bptr + (long)(k0 + 16) * ldw + 4);
        }
#pragma unroll
        for (int k = 0; k < 16; k++) {
            float4 a0 = *(const float4*)&As[buf][k][ty * 4];
            float4 a1 = *(const float4*)&As[buf][k][ty * 4 + 64];
            float4 b0 = *(const float4*)&Bs[buf][k][tx * 4];
            float4 b1 = *(const float4*)&Bs[buf][k][tx * 4 + 64];
            float ar[8] = {a0.x, a0.y, a0.z, a0.w, a1.x, a1.y, a1.z, a1.w};
            float br[8] = {b0.x, b0.y, b0.z, b0.w, b1.x, b1.y, b1.z, b1.w};
#pragma unroll
            for (int i = 0; i < 8; i++)
#pragma unroll
                for (int j = 0; j < 8; j++)
                    acc[i][j] = fmaf(ar[i], br[j], acc[i][j]);
        }
        if (more) {
            As[nxt][akq + 0][arow] = pa0.x; As[nxt][akq + 1][arow] = pa0.y;
            As[nxt][akq + 2][arow] = pa0.z; As[nxt][akq + 3][arow] = pa0.w;
            As[nxt][akq + 4][arow] = pa1.x; As[nxt][akq + 5][arow] = pa1.y;
            As[nxt][akq + 6][arow] = pa1.z; As[nxt][akq + 7][arow] = pa1.w;
            *(float4*)&Bs[nxt][brow][bcol]     = pb0;
            *(float4*)&Bs[nxt][brow][bcol + 4] = pb1;
        }
        __syncthreads();
        buf = nxt;
    }

    float4 bv0 = make_float4(0.f, 0.f, 0.f, 0.f);
    float4 bv1 = make_float4(0.f, 0.f, 0.f, 0.f);
    if (bias) {
        bv0 = *(const float4*)(bias + n0 + tx * 4);
        bv1 = *(const float4*)(bias + n0 + tx * 4 + 64);
    }
#pragma unroll
    for (int ih = 0; ih < 2; ih++) {
#pragma unroll
        for (int i = 0; i < 4; i++) {
            const int ri = ih * 4 + i;
            const int m = m0 + ih * 64 + ty * 4 + i;
            long off = (long)m * ldc + n0 + tx * 4;
            float4 o0, o1;
            o0.x = acc[ri][0] + bv0.x; o0.y = acc[ri][1] + bv0.y;
            o0.z = acc[ri][2] + bv0.z; o0.w = acc[ri][3] + bv0.w;
            o1.x = acc[ri][4] + bv1.x; o1.y = acc[ri][5] + bv1.y;
            o1.z = acc[ri][6] + bv1.z; o1.w = acc[ri][7] + bv1.w;
            if (accum) {
                float4 c0 = *(const float4*)(C + off);
                float4 c1 = *(const float4*)(C + off + 64);
                o0.x += c0.x; o0.y += c0.y; o0.z += c0.z; o0.w += c0.w;
                o1.x += c1.x; o1.y += c1.y; o1.z += c1.z; o1.w += c1.w;
            }
            *(float4*)(C + off)      = o0;
            *(float4*)(C + off + 64) = o1;
        }
    }
}

// ---------------------------------------------------------------------------
// Attention score GEMM (NT): Sc[b,m,n] = scale * dot(Q[b,m,:], E[b,n,:])
// ---------------------------------------------------------------------------
__global__ __launch_bounds__(256) void gemm_nt_scores(
    const float* __restrict__ Q, const float* __restrict__ E,
    float* __restrict__ C)
{
    const int b = blockIdx.z;
    const float* Qb = Q + (long)b * SS * D2;
    const float* Eb = E + (long)b * SS * D2;
    float* Cb = C + (long)b * SS * SS;
    const int m0 = blockIdx.y * 64, n0 = blockIdx.x * 64;
    __shared__ float Qs[16][68];
    __shared__ float Es[16][68];
    const int tid = threadIdx.x;
    const int tx = tid & 15, ty = tid >> 4;
    float acc[4][4];
#pragma unroll
    for (int i = 0; i < 4; i++)
#pragma unroll
        for (int j = 0; j < 4; j++) acc[i][j] = 0.f;

    for (int k0 = 0; k0 < D2; k0 += 16) {
        int row = tid >> 2, q = tid & 3;
        float4 v = *(const float4*)(Qb + (long)(m0 + row) * D2 + k0 + q * 4);
        Qs[q * 4 + 0][row] = v.x; Qs[q * 4 + 1][row] = v.y;
        Qs[q * 4 + 2][row] = v.z; Qs[q * 4 + 3][row] = v.w;
        v = *(const float4*)(Eb + (long)(n0 + row) * D2 + k0 + q * 4);
        Es[q * 4 + 0][row] = v.x; Es[q * 4 + 1][row] = v.y;
        Es[q * 4 + 2][row] = v.z; Es[q * 4 + 3][row] = v.w;
        __syncthreads();
#pragma unroll
        for (int k = 0; k < 16; k++) {
            float4 a4 = *(const float4*)&Qs[k][ty * 4];
            float4 b4 = *(const float4*)&Es[k][tx * 4];
            float ar[4] = {a4.x, a4.y, a4.z, a4.w};
            float br[4] = {b4.x, b4.y, b4.z, b4.w};
#pragma unroll
            for (int i = 0; i < 4; i++)
#pragma unroll
                for (int j = 0; j < 4; j++)
                    acc[i][j] = fmaf(ar[i], br[j], acc[i][j]);
        }
        __syncthreads();
    }
    const float scale = 0.03125f;
#pragma unroll
    for (int i = 0; i < 4; i++)
#pragma unroll
        for (int j = 0; j < 4; j++)
            Cb[(long)(m0 + ty * 4 + i) * SS + n0 + tx * 4 + j] = acc[i][j] * scale;
}

// ---------------------------------------------------------------------------
// Masked softmax per (b, q) row
// ---------------------------------------------------------------------------
__global__ void softmax_kernel(float* __restrict__ sc, const int* __restrict__ len) {
    const int q = blockIdx.x, b = blockIdx.y;
    float* row = sc + ((long)b * SS + q) * SS;
    const int L = len[b];
    const int t = threadIdx.x;
    __shared__ float red[256];
    if (q >= L) {
        for (int i = t; i < SS; i += 256) row[i] = 0.f;
        return;
    }
    float m = -3.402823466e38f;
    for (int i = t; i < L; i += 256) m = fmaxf(m, row[i]);
    red[t] = m; __syncthreads();
    for (int s = 128; s > 0; s >>= 1) {
        if (t < s) red[t] = fmaxf(red[t], red[t + s]);
        __syncthreads();
    }
    m = red[0]; __syncthreads();
    float sum = 0.f;
    for (int i = t; i < L; i += 256) sum += expf(row[i] - m);
    red[t] = sum; __syncthreads();
    for (int s = 128; s > 0; s >>= 1) {
        if (t < s) red[t] += red[t + s];
        __syncthreads();
    }
    float inv = 1.f / red[0];
    for (int i = t; i < SS; i += 256)
        row[i] = (i < L) ? expf(row[i] - m) * inv : 0.f;
}

// ---------------------------------------------------------------------------
// Build layer input
// ---------------------------------------------------------------------------
__global__ void build_lay(const float* __restrict__ hf, const float* __restrict__ hb,
                          const int* __restrict__ len, float* __restrict__ lay) {
    int r = blockIdx.x;
    int b = r >> 9, tt = r & 511;
    int active = tt < len[b];
    int t = threadIdx.x;
    for (int i = t; i < D2; i += 256) {
        float v = 0.f;
        if (active) v = (i < HH) ? hf[(long)r * HH + i] : hb[(long)r * HH + i - HH];
        lay[(long)r * D2 + i] = v;
    }
}

// ---------------------------------------------------------------------------
// refined = LN(encoded + tanh(pre)) masked by valid
// ---------------------------------------------------------------------------
__global__ void refine_ln(const float* __restrict__ enc, const float* __restrict__ pre,
                          const float* __restrict__ g, const float* __restrict__ bta,
                          const int* __restrict__ len, float* __restrict__ out) {
    int r = blockIdx.x;
    int b = r >> 9, tt = r & 511;
    int t = threadIdx.x;
    __shared__ float r1[256], r2[256];
    float v[4];
    float s = 0.f, s2 = 0.f;
#pragma unroll
    for (int i = 0; i < 4; i++) {
        int idx = t + i * 256;
        float xx = enc[(long)r * D2 + idx] + tanhf(pre[(long)r * D2 + idx]);
        v[i] = xx; s += xx; s2 += xx * xx;
    }
    r1[t] = s; r2[t] = s2; __syncthreads();
    for (int st = 128; st > 0; st >>= 1) {
        if (t < st) { r1[t] += r1[t + st]; r2[t] += r2[t + st]; }
        __syncthreads();
    }
    float mean = r1[0] * (1.f / 1024.f);
    float var = r2[0] * (1.f / 1024.f) - mean * mean;
    float inv = rsqrtf(var + 1e-5f);
    int active = tt < len[b];
#pragma unroll
    for (int i = 0; i < 4; i++) {
        int idx = t + i * 256;
        float o = (v[i] - mean) * inv * g[idx] + bta[idx];
        out[(long)r * D2 + idx] = active ? o : 0.f;
    }
}

// ---------------------------------------------------------------------------
// head = LN(gelu_exact(hpre))
// ---------------------------------------------------------------------------
__global__ void head_ln(const float* __restrict__ hpre, const float* __restrict__ g,
                        const float* __restrict__ bta, float* __restrict__ out) {
    int r = blockIdx.x;
    int t = threadIdx.x;
    __shared__ float r1[256], r2[256];
    float v[2];
    float s = 0.f, s2 = 0.f;
#pragma unroll
    for (int i = 0; i < 2; i++) {
        int idx = t + i * 256;
        float xx = hpre[(long)r * HH + idx];
        float ge = 0.5f * xx * (1.f + erff(xx * 0.70710678118654752f));
        v[i] = ge; s += ge; s2 += ge * ge;
    }
    r1[t] = s; r2[t] = s2; __syncthreads();
    for (int st = 128; st > 0; st >>= 1) {
        if (t < st) { r1[t] += r1[t + st]; r2[t] += r2[t + st]; }
        __syncthreads();
    }
    float mean = r1[0] * (1.f / 512.f);
    float var = r2[0] * (1.f / 512.f) - mean * mean;
    float inv = rsqrtf(var + 1e-5f);
#pragma unroll
    for (int i = 0; i < 2; i++) {
        int idx = t + i * 256;
        out[(long)r * HH + idx] = (v[i] - mean) * inv * g[idx] + bta[idx];
    }
}

// ---------------------------------------------------------------------------
// Reset grid barrier counter
// ---------------------------------------------------------------------------
__global__ void reset_bar() { g_barcnt = 0u; }

// ---------------------------------------------------------------------------
// Persistent BiLSTM scan (unchanged from R6 passing version).
// hsT row stride 9 floats -> scalar LDS only (odd stride: conflict-free).
// ---------------------------------------------------------------------------
#define LSTM_SMEM_FLOATS (16 * 512 + 512 * 9 + 128 * 33 + 32)

__global__ __launch_bounds__(256, 2) void lstm_scan(
    const float* __restrict__ xf, const float* __restrict__ xb,
    const float* __restrict__ Wrf, const float* __restrict__ Wrb,
    const float* __restrict__ h0f, const float* __restrict__ c0f,
    const float* __restrict__ h0b, const float* __restrict__ c0b,
    float* __restrict__ houtf, float* __restrict__ houtb,
    float* __restrict__ hcur, const int* __restrict__ len)
{
    extern __shared__ float sm[];
    float* Ws   = sm;
    float* hsT  = sm + 16 * 512;
    float* part = hsT + 512 * 9;
    float* cst  = part + 128 * 33;

    const int tid = threadIdx.x;
    const int dir = blockIdx.x >> 7;
    const int kb  = blockIdx.x & 127;
    const int j0  = kb * 4;
    const float* Wr = dir ? Wrb : Wrf;
    const float* xp = dir ? xb : xf;
    const float* h0 = dir ? h0b : h0f;
    const float* c0 = dir ? c0b : c0f;
    float* hout  = dir ? houtb : houtf;
    float* hbase = hcur + dir * (2 * BB * HH);

    {
        int col = tid & 15;
        int gcol = (col >> 2) * 512 + j0 + (col & 3);
        for (int k = tid >> 4; k < 512; k += 16)
            Ws[col * 512 + k] = Wr[(long)k * G4 + gcol];
    }
    if (tid < 32) {
        int u = tid >> 3, b = tid & 7;
        cst[u * 8 + b] = c0[j0 + u];
        __stcg(&hbase[(j0 + u) * 8 + b], h0[j0 + u]);
    }

    const int ks = tid & 31;
    const int bg = (tid >> 5) & 1;
    const int cg = tid >> 6;
    unsigned phase = 1;

#define GRIDBAR()                                                         \
    do {                                                                  \
        __syncthreads();                                                  \
        if (tid == 0) {                                                   \
            __threadfence();                                              \
            atomicAdd(&g_barcnt, 1u);                                     \
            unsigned tgt = 256u * phase;                                  \
            while (*(volatile unsigned*)&g_barcnt < tgt) {}               \
        }                                                                 \
        __syncthreads();                                                  \
        phase++;                                                          \
    } while (0)

    GRIDBAR();

    for (int s = 0; s < SS; s++) {
        const float* hrd = hbase + (s & 1) * (BB * HH);
        float* hwr = hbase + ((s + 1) & 1) * (BB * HH);

        for (int f = tid; f < BB * HH; f += 256)
            hsT[(f >> 3) * 9 + (f & 7)] = __ldcg(hrd + f);
        __syncthreads();

        float acc[4][4];
#pragma unroll
        for (int c = 0; c < 4; c++)
#pragma unroll
            for (int j = 0; j < 4; j++) acc[c][j] = 0.f;

#pragma unroll 4
        for (int i = 0; i < 16; i++) {
            int k = ks + 32 * i;
            float h0v = hsT[k * 9 + bg * 4 + 0];
            float h1v = hsT[k * 9 + bg * 4 + 1];
            float h2v = hsT[k * 9 + bg * 4 + 2];
            float h3v = hsT[k * 9 + bg * 4 + 3];
#pragma unroll
            for (int c = 0; c < 4; c++) {
                float w = Ws[(cg * 4 + c) * 512 + k];
                acc[c][0] = fmaf(w, h0v, acc[c][0]);
                acc[c][1] = fmaf(w, h1v, acc[c][1]);
                acc[c][2] = fmaf(w, h2v, acc[c][2]);
                acc[c][3] = fmaf(w, h3v, acc[c][3]);
            }
        }
#pragma unroll
        for (int c = 0; c < 4; c++)
#pragma unroll
            for (int j = 0; j < 4; j++)
                part[((cg * 4 + c) * 8 + bg * 4 + j) * 33 + ks] = acc[c][j];
        __syncthreads();

        const int t_real = dir ? (SS - 1 - s) : s;

        if (tid < 128) {
            float ssum = 0.f;
#pragma unroll
            for (int i = 0; i < 32; i++) ssum += part[tid * 33 + i];
            int col = tid >> 3, b = tid & 7;
            int gg = col >> 2, u = col & 3;
            ssum += xp[((long)(b * SS + t_real)) * G4 + gg * 512 + j0 + u];
            part[tid * 33 + 32] = ssum;
        }
        __syncthreads();

        if (tid < 32) {
            int u = tid >> 3, b = tid & 7;
            float ig = part[((0  + u) * 8 + b) * 33 + 32];
            float fg = part[((4  + u) * 8 + b) * 33 + 32];
            float og = part[((8  + u) * 8 + b) * 33 + 32];
            float gg = part[((12 + u) * 8 + b) * 33 + 32];
            float cp = cst[u * 8 + b];
            float hp = hsT[(j0 + u) * 9 + b];
            float cn = sigm(fg) * cp + sigm(ig) * tanhf(gg);
            float hn = sigm(og) * tanhf(cn);
            int active = t_real < len[b];
            float h = active ? hn : hp;
            float c = active ? cn : cp;
            cst[u * 8 + b] = c;
            __stcg(&hwr[(j0 + u) * 8 + b], h);
            hout[((long)(b * SS + t_real)) * HH + j0 + u] = h;
        }
        GRIDBAR();
    }
#undef GRIDBAR
}

// ---------------------------------------------------------------------------
// Host driver
// ---------------------------------------------------------------------------
extern "C" void kernel_launch(void* const* d_in, const int* in_sizes, int n_in,
                              void* d_out, int out_size) {
    const int*   x    = (const int*)  d_in[0];
    const float* emb  = (const float*)d_in[1];
    const float* Wf0  = (const float*)d_in[2];
    const float* bf0  = (const float*)d_in[3];
    const float* Wb0  = (const float*)d_in[4];
    const float* bb0  = (const float*)d_in[5];
    const float* Wf1  = (const float*)d_in[6];
    const float* bf1  = (const float*)d_in[7];
    const float* Wb1  = (const float*)d_in[8];
    const float* bb1  = (const float*)d_in[9];
    const float* h0f  = (const float*)d_in[10];
    const float* c0f  = (const float*)d_in[11];
    const float* h0b  = (const float*)d_in[12];
    const float* c0b  = (const float*)d_in[13];
    const float* Wq   = (const float*)d_in[14];
    const float* bq   = (const float*)d_in[15];
    const float* Wao  = (const float*)d_in[16];
    const float* bao  = (const float*)d_in[17];
    const float* ln1g = (const float*)d_in[18];
    const float* ln1b = (const float*)d_in[19];
    const float* Wh   = (const float*)d_in[20];
    const float* bh   = (const float*)d_in[21];
    const float* ln2g = (const float*)d_in[22];
    const float* ln2b = (const float*)d_in[23];
    const float* Wp   = (const float*)d_in[24];
    const float* ob   = (const float*)d_in[25];
    float* out = (float*)d_out;

    float *embx, *xf, *xb, *hf, *hb, *lay, *query, *scores, *ctx, *pre, *ref,
          *hpre, *head, *hcur;
    int* len;
    cudaGetSymbolAddress((void**)&embx,   g_embx);
    cudaGetSymbolAddress((void**)&xf,     g_xf);
    cudaGetSymbolAddress((void**)&xb,     g_xb);
    cudaGetSymbolAddress((void**)&hf,     g_hf);
    cudaGetSymbolAddress((void**)&hb,     g_hb);
    cudaGetSymbolAddress((void**)&lay,    g_lay);
    cudaGetSymbolAddress((void**)&query,  g_query);
    cudaGetSymbolAddress((void**)&scores, g_scores);
    cudaGetSymbolAddress((void**)&ctx,    g_ctx);
    cudaGetSymbolAddress((void**)&pre,    g_pre);
    cudaGetSymbolAddress((void**)&ref,    g_ref);
    cudaGetSymbolAddress((void**)&hpre,   g_hpre);
    cudaGetSymbolAddress((void**)&head,   g_head);
    cudaGetSymbolAddress((void**)&hcur,   g_hcur);
    cudaGetSymbolAddress((void**)&len,    g_len);

    const int lstm_smem = LSTM_SMEM_FLOATS * 4;
    cudaFuncSetAttribute(lstm_scan, cudaFuncAttributeMaxDynamicSharedMemorySize,
                         lstm_smem);

    len_kernel<<<BB, 512>>>(x, len);
    embed_kernel<<<NROW, 128>>>(x, emb, embx);

    // ---- layer 0 ----
    {
        dim3 g(G4 / 128, NROW / 128, 1);
        gemm_nn<<<g, 256>>>(embx, Wf0, bf0, xf, NROW, G4, EE, EE, G4, G4, 0, 0, 0, 0);
        gemm_nn<<<g, 256>>>(embx, Wb0, bb0, xb, NROW, G4, EE, EE, G4, G4, 0, 0, 0, 0);
    }
    reset_bar<<<1, 1>>>();
    lstm_scan<<<256, 256, lstm_smem>>>(xf, xb,
                                       Wf0 + (long)EE * G4, Wb0 + (long)EE * G4,
                                       h0f, c0f, h0b, c0b, hf, hb, hcur, len);
    build_lay<<<NROW, 256>>>(hf, hb, len, lay);

    // ---- layer 1 ----
    {
        dim3 g(G4 / 128, NROW / 128, 1);
        gemm_nn<<<g, 256>>>(lay, Wf1, bf1, xf, NROW, G4, D2, D2, G4, G4, 0, 0, 0, 0);
        gemm_nn<<<g, 256>>>(lay, Wb1, bb1, xb, NROW, G4, D2, D2, G4, G4, 0, 0, 0, 0);
    }
    reset_bar<<<1, 1>>>();
    lstm_scan<<<256, 256, lstm_smem>>>(xf, xb,
                                       Wf1 + (long)D2 * G4, Wb1 + (long)D2 * G4,
                                       h0f + HH, c0f + HH, h0b + HH, c0b + HH,
                                       hf, hb, hcur, len);
    build_lay<<<NROW, 256>>>(hf, hb, len, lay);  // lay = encoded

    // ---- attention ----
    {
        dim3 g(D2 / 128, NROW / 128, 1);
        gemm_nn<<<g, 256>>>(lay, Wq, bq, query, NROW, D2, D2, D2, D2, D2, 0, 0, 0, 0);
    }
    {
        dim3 g(SS / 64, SS / 64, BB);
        gemm_nt_scores<<<g, 256>>>(query, lay, scores);
    }
    {
        dim3 g(SS, BB, 1);
        softmax_kernel<<<g, 256>>>(scores, len);
    }
    {
        dim3 g(D2 / 128, SS / 128, BB);
        gemm_nn<<<g, 256>>>(scores, lay, nullptr, ctx, SS, D2, SS, SS, D2, D2,
                            (long)SS * SS, (long)SS * D2, (long)SS * D2, 0);
    }
    {
        dim3 g(D2 / 128, NROW / 128, 1);
        gemm_nn<<<g, 256>>>(lay, Wao, bao, pre, NROW, D2, D2, D2, D2, D2, 0, 0, 0, 0);
        gemm_nn<<<g, 256>>>(ctx, Wao + (long)D2 * D2, nullptr, pre,
                            NROW, D2, D2, D2, D2, D2, 0, 0, 0, 1);
    }
    refine_ln<<<NROW, 256>>>(lay, pre, ln1g, ln1b, len, ref);

    // ---- head ----
    {
        dim3 g(HH / 128, NROW / 128, 1);
        gemm_nn<<<g, 256>>>(ref, Wh, bh, hpre, NROW, HH, D2, D2, HH, HH, 0, 0, 0, 0);
    }
    head_ln<<<NROW, 256>>>(hpre, ln2g, ln2b, head);

    // ---- vocab projection ----
    {
        dim3 g(VV / 128, NROW / 128, 1);
        gemm_nn<<<g, 256>>>(head, Wp, ob, out, NROW, VV, HH, HH, VV, VV, 0, 0, 0, 0);
    }
}

// round 9
// speedup vs baseline: 1.2472x; 1.1385x over previous
#include <cuda_runtime.h>
#include <cuda_bf16.h>
#include <math.h>
#include <stdint.h>

// ---------------------------------------------------------------------------
// Problem constants: V=32000, E=512, H=512, L=2, B=8, S=512
// ---------------------------------------------------------------------------
#define SS   512
#define BB   8
#define EE   512
#define HH   512
#define D2   1024      // 2H
#define G4   2048      // 4H
#define VV   32000
#define NROW 4096      // B*S

// ---------------------------------------------------------------------------
// Device scratch (no cudaMalloc allowed)
// ---------------------------------------------------------------------------
__device__ float g_embx  [NROW * EE];
__device__ float g_xf    [NROW * G4];
__device__ float g_xb    [NROW * G4];
__device__ float g_hf    [NROW * HH];
__device__ float g_hb    [NROW * HH];
__device__ float g_lay   [NROW * D2];
__device__ float g_query [NROW * D2];
__device__ float g_scores[BB * SS * SS];
__device__ float g_ctx   [NROW * D2];
__device__ float g_pre   [NROW * D2];
__device__ float g_ref   [NROW * D2];
__device__ float g_hpre  [NROW * HH];
__device__ float g_hcur  [2 * 2 * BB * HH];
__device__ int   g_len   [BB];
__device__ unsigned g_barcnt;

// bf16 split operands for tensor-core Wp GEMM
__device__ __nv_bfloat16 g_hhi  [NROW * HH];
__device__ __nv_bfloat16 g_hlo  [NROW * HH];
__device__ __nv_bfloat16 g_wpthi[(long)VV * HH];
__device__ __nv_bfloat16 g_wptlo[(long)VV * HH];

__device__ __forceinline__ float sigm(float x) { return 1.f / (1.f + expf(-x)); }

__device__ __forceinline__ uint32_t smem_u32(const void* p) {
    uint32_t a;
    asm("{ .reg .u64 t; cvta.to.shared.u64 t, %1; cvt.u32.u64 %0, t; }"
        : "=r"(a) : "l"(p));
    return a;
}

// mma.sync bf16 (baseline PTX, works on sm_103 non-'a' target)
__device__ __forceinline__ void mma_bf16(float* c, const uint32_t* a,
                                         const uint32_t* b) {
    asm volatile(
        "mma.sync.aligned.m16n8k16.row.col.f32.bf16.bf16.f32 "
        "{%0,%1,%2,%3}, {%4,%5,%6,%7}, {%8,%9}, {%0,%1,%2,%3};"
        : "+f"(c[0]), "+f"(c[1]), "+f"(c[2]), "+f"(c[3])
        : "r"(a[0]), "r"(a[1]), "r"(a[2]), "r"(a[3]), "r"(b[0]), "r"(b[1]));
}

__device__ __forceinline__ void ldsm_x4(uint32_t& r0, uint32_t& r1,
                                        uint32_t& r2, uint32_t& r3,
                                        uint32_t addr) {
    asm volatile("ldmatrix.sync.aligned.m8n8.x4.shared.b16 {%0,%1,%2,%3}, [%4];"
                 : "=r"(r0), "=r"(r1), "=r"(r2), "=r"(r3) : "r"(addr));
}

// ---------------------------------------------------------------------------
// lengths per batch
// ---------------------------------------------------------------------------
__global__ void len_kernel(const int* __restrict__ x, int* __restrict__ len) {
    __shared__ int red[512];
    int b = blockIdx.x, tid = threadIdx.x;
    red[tid] = (x[b * SS + tid] != 0) ? 1 : 0;
    __syncthreads();
    for (int s = 256; s > 0; s >>= 1) {
        if (tid < s) red[tid] += red[tid + s];
        __syncthreads();
    }
    if (tid == 0) len[b] = red[0];
}

// ---------------------------------------------------------------------------
// embedding gather
// ---------------------------------------------------------------------------
__global__ void embed_kernel(const int* __restrict__ x, const float* __restrict__ emb,
                             float* __restrict__ out) {
    int r = blockIdx.x;
    long tok = (long)x[r];
    float4 v = ((const float4*)(emb + tok * EE))[threadIdx.x];
    ((float4*)(out + (long)r * EE))[threadIdx.x] = v;
}

// ---------------------------------------------------------------------------
// fp32 GEMM: 128x128x16 tiles, 256 threads, 8x8 microtile, double-buffered.
// ---------------------------------------------------------------------------
__global__ __launch_bounds__(256, 2) void gemm_nn(
    const float* __restrict__ A, const float* __restrict__ W,
    const float* __restrict__ bias, float* __restrict__ C,
    int M, int N, int K, int lda, int ldw, int ldc,
    long sA, long sW, long sC, int accum)
{
    A += (long)blockIdx.z * sA;
    W += (long)blockIdx.z * sW;
    C += (long)blockIdx.z * sC;
    const int m0 = blockIdx.y * 128, n0 = blockIdx.x * 128;
    __shared__ float As[2][16][132];
    __shared__ float Bs[2][16][132];
    const int tid = threadIdx.x;
    const int tx = tid & 15, ty = tid >> 4;

    const int arow = tid >> 1;
    const int akq  = (tid & 1) * 8;
    const int brow = tid >> 4;
    const int bcol = (tid & 15) * 8;

    const float* Aptr = A + (long)(m0 + arow) * lda + akq;
    const float* Bptr = W + (long)brow * ldw + n0 + bcol;

    float4 pa0, pa1, pb0, pb1;
    pa0 = *(const float4*)(Aptr);
    pa1 = *(const float4*)(Aptr + 4);
    pb0 = *(const float4*)(Bptr);
    pb1 = *(const float4*)(Bptr + 4);
    {
        As[0][akq + 0][arow] = pa0.x; As[0][akq + 1][arow] = pa0.y;
        As[0][akq + 2][arow] = pa0.z; As[0][akq + 3][arow] = pa0.w;
        As[0][akq + 4][arow] = pa1.x; As[0][akq + 5][arow] = pa1.y;
        As[0][akq + 6][arow] = pa1.z; As[0][akq + 7][arow] = pa1.w;
        *(float4*)&Bs[0][brow][bcol]     = pb0;
        *(float4*)&Bs[0][brow][bcol + 4] = pb1;
    }
    __syncthreads();

    float acc[8][8];
#pragma unroll
    for (int i = 0; i < 8; i++)
#pragma unroll
        for (int j = 0; j < 8; j++) acc[i][j] = 0.f;

    int buf = 0;
    for (int k0 = 0; k0 < K; k0 += 16) {
        const int nxt = buf ^ 1;
        const bool more = (k0 + 16) < K;
        if (more) {
            pa0 = *(const float4*)(Aptr + k0 + 16);
            pa1 = *(const float4*)(Aptr + k0 + 20);
            pb0 = *(const float4*)(Bptr + (long)(k0 + 16) * ldw);
            pb1 = *(const float4*)(Bptr + (long)(k0 + 16) * ldw + 4);
        }
#pragma unroll
        for (int k = 0; k < 16; k++) {
            float4 a0 = *(const float4*)&As[buf][k][ty * 4];
            float4 a1 = *(const float4*)&As[buf][k][ty * 4 + 64];
            float4 b0 = *(const float4*)&Bs[buf][k][tx * 4];
            float4 b1 = *(const float4*)&Bs[buf][k][tx * 4 + 64];
            float ar[8] = {a0.x, a0.y, a0.z, a0.w, a1.x, a1.y, a1.z, a1.w};
            float br[8] = {b0.x, b0.y, b0.z, b0.w, b1.x, b1.y, b1.z, b1.w};
#pragma unroll
            for (int i = 0; i < 8; i++)
#pragma unroll
                for (int j = 0; j < 8; j++)
                    acc[i][j] = fmaf(ar[i], br[j], acc[i][j]);
        }
        if (more) {
            As[nxt][akq + 0][arow] = pa0.x; As[nxt][akq + 1][arow] = pa0.y;
            As[nxt][akq + 2][arow] = pa0.z; As[nxt][akq + 3][arow] = pa0.w;
            As[nxt][akq + 4][arow] = pa1.x; As[nxt][akq + 5][arow] = pa1.y;
            As[nxt][akq + 6][arow] = pa1.z; As[nxt][akq + 7][arow] = pa1.w;
            *(float4*)&Bs[nxt][brow][bcol]     = pb0;
            *(float4*)&Bs[nxt][brow][bcol + 4] = pb1;
        }
        __syncthreads();
        buf = nxt;
    }

    float4 bv0 = make_float4(0.f, 0.f, 0.f, 0.f);
    float4 bv1 = make_float4(0.f, 0.f, 0.f, 0.f);
    if (bias) {
        bv0 = *(const float4*)(bias + n0 + tx * 4);
        bv1 = *(const float4*)(bias + n0 + tx * 4 + 64);
    }
#pragma unroll
    for (int ih = 0; ih < 2; ih++) {
#pragma unroll
        for (int i = 0; i < 4; i++) {
            const int ri = ih * 4 + i;
            const int m = m0 + ih * 64 + ty * 4 + i;
            long off = (long)m * ldc + n0 + tx * 4;
            float4 o0, o1;
            o0.x = acc[ri][0] + bv0.x; o0.y = acc[ri][1] + bv0.y;
            o0.z = acc[ri][2] + bv0.z; o0.w = acc[ri][3] + bv0.w;
            o1.x = acc[ri][4] + bv1.x; o1.y = acc[ri][5] + bv1.y;
            o1.z = acc[ri][6] + bv1.z; o1.w = acc[ri][7] + bv1.w;
            if (accum) {
                float4 c0 = *(const float4*)(C + off);
                float4 c1 = *(const float4*)(C + off + 64);
                o0.x += c0.x; o0.y += c0.y; o0.z += c0.z; o0.w += c0.w;
                o1.x += c1.x; o1.y += c1.y; o1.z += c1.z; o1.w += c1.w;
            }
            *(float4*)(C + off)      = o0;
            *(float4*)(C + off + 64) = o1;
        }
    }
}

// ---------------------------------------------------------------------------
// Attention score GEMM (NT)
// ---------------------------------------------------------------------------
__global__ __launch_bounds__(256) void gemm_nt_scores(
    const float* __restrict__ Q, const float* __restrict__ E,
    float* __restrict__ C)
{
    const int b = blockIdx.z;
    const float* Qb = Q + (long)b * SS * D2;
    const float* Eb = E + (long)b * SS * D2;
    float* Cb = C + (long)b * SS * SS;
    const int m0 = blockIdx.y * 64, n0 = blockIdx.x * 64;
    __shared__ float Qs[16][68];
    __shared__ float Es[16][68];
    const int tid = threadIdx.x;
    const int tx = tid & 15, ty = tid >> 4;
    float acc[4][4];
#pragma unroll
    for (int i = 0; i < 4; i++)
#pragma unroll
        for (int j = 0; j < 4; j++) acc[i][j] = 0.f;

    for (int k0 = 0; k0 < D2; k0 += 16) {
        int row = tid >> 2, q = tid & 3;
        float4 v = *(const float4*)(Qb + (long)(m0 + row) * D2 + k0 + q * 4);
        Qs[q * 4 + 0][row] = v.x; Qs[q * 4 + 1][row] = v.y;
        Qs[q * 4 + 2][row] = v.z; Qs[q * 4 + 3][row] = v.w;
        v = *(const float4*)(Eb + (long)(n0 + row) * D2 + k0 + q * 4);
        Es[q * 4 + 0][row] = v.x; Es[q * 4 + 1][row] = v.y;
        Es[q * 4 + 2][row] = v.z; Es[q * 4 + 3][row] = v.w;
        __syncthreads();
#pragma unroll
        for (int k = 0; k < 16; k++) {
            float4 a4 = *(const float4*)&Qs[k][ty * 4];
            float4 b4 = *(const float4*)&Es[k][tx * 4];
            float ar[4] = {a4.x, a4.y, a4.z, a4.w};
            float br[4] = {b4.x, b4.y, b4.z, b4.w};
#pragma unroll
            for (int i = 0; i < 4; i++)
#pragma unroll
                for (int j = 0; j < 4; j++)
                    acc[i][j] = fmaf(ar[i], br[j], acc[i][j]);
        }
        __syncthreads();
    }
    const float scale = 0.03125f;
#pragma unroll
    for (int i = 0; i < 4; i++)
#pragma unroll
        for (int j = 0; j < 4; j++)
            Cb[(long)(m0 + ty * 4 + i) * SS + n0 + tx * 4 + j] = acc[i][j] * scale;
}

// ---------------------------------------------------------------------------
// Masked softmax per (b, q) row
// ---------------------------------------------------------------------------
__global__ void softmax_kernel(float* __restrict__ sc, const int* __restrict__ len) {
    const int q = blockIdx.x, b = blockIdx.y;
    float* row = sc + ((long)b * SS + q) * SS;
    const int L = len[b];
    const int t = threadIdx.x;
    __shared__ float red[256];
    if (q >= L) {
        for (int i = t; i < SS; i += 256) row[i] = 0.f;
        return;
    }
    float m = -3.402823466e38f;
    for (int i = t; i < L; i += 256) m = fmaxf(m, row[i]);
    red[t] = m; __syncthreads();
    for (int s = 128; s > 0; s >>= 1) {
        if (t < s) red[t] = fmaxf(red[t], red[t + s]);
        __syncthreads();
    }
    m = red[0]; __syncthreads();
    float sum = 0.f;
    for (int i = t; i < L; i += 256) sum += expf(row[i] - m);
    red[t] = sum; __syncthreads();
    for (int s = 128; s > 0; s >>= 1) {
        if (t < s) red[t] += red[t + s];
        __syncthreads();
    }
    float inv = 1.f / red[0];
    for (int i = t; i < SS; i += 256)
        row[i] = (i < L) ? expf(row[i] - m) * inv : 0.f;
}

// ---------------------------------------------------------------------------
// Build layer input
// ---------------------------------------------------------------------------
__global__ void build_lay(const float* __restrict__ hf, const float* __restrict__ hb,
                          const int* __restrict__ len, float* __restrict__ lay) {
    int r = blockIdx.x;
    int b = r >> 9, tt = r & 511;
    int active = tt < len[b];
    int t = threadIdx.x;
    for (int i = t; i < D2; i += 256) {
        float v = 0.f;
        if (active) v = (i < HH) ? hf[(long)r * HH + i] : hb[(long)r * HH + i - HH];
        lay[(long)r * D2 + i] = v;
    }
}

// ---------------------------------------------------------------------------
// refined = LN(encoded + tanh(pre)) masked by valid
// ---------------------------------------------------------------------------
__global__ void refine_ln(const float* __restrict__ enc, const float* __restrict__ pre,
                          const float* __restrict__ g, const float* __restrict__ bta,
                          const int* __restrict__ len, float* __restrict__ out) {
    int r = blockIdx.x;
    int b = r >> 9, tt = r & 511;
    int t = threadIdx.x;
    __shared__ float r1[256], r2[256];
    float v[4];
    float s = 0.f, s2 = 0.f;
#pragma unroll
    for (int i = 0; i < 4; i++) {
        int idx = t + i * 256;
        float xx = enc[(long)r * D2 + idx] + tanhf(pre[(long)r * D2 + idx]);
        v[i] = xx; s += xx; s2 += xx * xx;
    }
    r1[t] = s; r2[t] = s2; __syncthreads();
    for (int st = 128; st > 0; st >>= 1) {
        if (t < st) { r1[t] += r1[t + st]; r2[t] += r2[t + st]; }
        __syncthreads();
    }
    float mean = r1[0] * (1.f / 1024.f);
    float var = r2[0] * (1.f / 1024.f) - mean * mean;
    float inv = rsqrtf(var + 1e-5f);
    int active = tt < len[b];
#pragma unroll
    for (int i = 0; i < 4; i++) {
        int idx = t + i * 256;
        float o = (v[i] - mean) * inv * g[idx] + bta[idx];
        out[(long)r * D2 + idx] = active ? o : 0.f;
    }
}

// ---------------------------------------------------------------------------
// head = LN(gelu_exact(hpre)) -> emit bf16 hi/lo split for tensor-core GEMM
// ---------------------------------------------------------------------------
__global__ void head_ln(const float* __restrict__ hpre, const float* __restrict__ g,
                        const float* __restrict__ bta,
                        __nv_bfloat16* __restrict__ hhi,
                        __nv_bfloat16* __restrict__ hlo) {
    int r = blockIdx.x;
    int t = threadIdx.x;
    __shared__ float r1[256], r2[256];
    float v[2];
    float s = 0.f, s2 = 0.f;
#pragma unroll
    for (int i = 0; i < 2; i++) {
        int idx = t + i * 256;
        float xx = hpre[(long)r * HH + idx];
        float ge = 0.5f * xx * (1.f + erff(xx * 0.70710678118654752f));
        v[i] = ge; s += ge; s2 += ge * ge;
    }
    r1[t] = s; r2[t] = s2; __syncthreads();
    for (int st = 128; st > 0; st >>= 1) {
        if (t < st) { r1[t] += r1[t + st]; r2[t] += r2[t + st]; }
        __syncthreads();
    }
    float mean = r1[0] * (1.f / 512.f);
    float var = r2[0] * (1.f / 512.f) - mean * mean;
    float inv = rsqrtf(var + 1e-5f);
#pragma unroll
    for (int i = 0; i < 2; i++) {
        int idx = t + i * 256;
        float o = (v[i] - mean) * inv * g[idx] + bta[idx];
        __nv_bfloat16 hi = __float2bfloat16(o);
        float lo = o - __bfloat162float(hi);
        hhi[(long)r * HH + idx] = hi;
        hlo[(long)r * HH + idx] = __float2bfloat16(lo);
    }
}

// ---------------------------------------------------------------------------
// Wp transpose + bf16 hi/lo split: Wp[K=512][N=32000] -> T{hi,lo}[N][K]
// ---------------------------------------------------------------------------
__global__ void wp_transpose(const float* __restrict__ Wp,
                             __nv_bfloat16* __restrict__ Thi,
                             __nv_bfloat16* __restrict__ Tlo) {
    __shared__ float tile[32][33];
    int n0 = blockIdx.x * 32, k0 = blockIdx.y * 32;
    int tx = threadIdx.x, ty = threadIdx.y;  // 32 x 8
#pragma unroll
    for (int i = 0; i < 4; i++)
        tile[ty + i * 8][tx] = Wp[(long)(k0 + ty + i * 8) * VV + n0 + tx];
    __syncthreads();
#pragma unroll
    for (int i = 0; i < 4; i++) {
        int n = n0 + ty + i * 8, k = k0 + tx;
        float v = tile[tx][ty + i * 8];
        __nv_bfloat16 hi = __float2bfloat16(v);
        float lo = v - __bfloat162float(hi);
        Thi[(long)n * HH + k] = hi;
        Tlo[(long)n * HH + k] = __float2bfloat16(lo);
    }
}

// ---------------------------------------------------------------------------
// mma.sync split-bf16 Wp GEMM: out[4096, 32000] = head @ Wp + bias
// D = Ahi*Bhi + Ahi*Blo + Alo*Bhi, fp32 accum.
// CTA tile 128x128, K-slab 32. 8 warps (4m x 2n), warp tile 32x64.
// SMEM rows padded to 40 bf16 (80B): 8-row ldmatrix fetch is bank-conflict-free
// (20*r mod 32 is a permutation over 8 rows x 4-word units).
// ---------------------------------------------------------------------------
#define WROW 40

__global__ __launch_bounds__(256, 1) void wp_gemm(
    const __nv_bfloat16* __restrict__ Ahi, const __nv_bfloat16* __restrict__ Alo,
    const __nv_bfloat16* __restrict__ Bhi, const __nv_bfloat16* __restrict__ Blo,
    const float* __restrict__ bias, float* __restrict__ C)
{
    __shared__ __nv_bfloat16 sAhi[128 * WROW], sAlo[128 * WROW];
    __shared__ __nv_bfloat16 sBhi[128 * WROW], sBlo[128 * WROW];

    const int tid  = threadIdx.x;
    const int warp = tid >> 5, lane = tid & 31;
    const int wm = (warp & 3) * 32;    // warp m-offset
    const int wn = (warp >> 2) * 64;   // warp n-offset
    const int m0 = blockIdx.x * 128, n0 = blockIdx.y * 128;

    // loader: row = tid>>1 (0..127), two 16B units (8 bf16 each)
    const int lr = tid >> 1;
    const int lu = (tid & 1) * 2;      // unit index 0 or 2 (of 4 per 32-elem row)
    const __nv_bfloat16* gAhi = Ahi + (long)(m0 + lr) * HH + lu * 8;
    const __nv_bfloat16* gAlo = Alo + (long)(m0 + lr) * HH + lu * 8;
    const __nv_bfloat16* gBhi = Bhi + (long)(n0 + lr) * HH + lu * 8;
    const __nv_bfloat16* gBlo = Blo + (long)(n0 + lr) * HH + lu * 8;
    const int so = lr * WROW + lu * 8;

    // ldmatrix source addresses (computed once)
    // A: row = wm + mt*16 + (lane&15), col = kh + ((lane>>4)<<3)
    const int a_r = (lane & 15);
    const int a_c = (lane >> 4) << 3;
    // B: row = wn + p*16 + ((lane>>4)<<3) + (lane&7), col = kh + (((lane>>3)&1)<<3)
    const int b_r = ((lane >> 4) << 3) + (lane & 7);
    const int b_c = ((lane >> 3) & 1) << 3;

    float acc[16][4];
#pragma unroll
    for (int i = 0; i < 16; i++)
#pragma unroll
        for (int j = 0; j < 4; j++) acc[i][j] = 0.f;

    uint4 pAh0, pAh1, pAl0, pAl1, pBh0, pBh1, pBl0, pBl1;
    pAh0 = *(const uint4*)(gAhi);     pAh1 = *(const uint4*)(gAhi + 8);
    pAl0 = *(const uint4*)(gAlo);     pAl1 = *(const uint4*)(gAlo + 8);
    pBh0 = *(const uint4*)(gBhi);     pBh1 = *(const uint4*)(gBhi + 8);
    pBl0 = *(const uint4*)(gBlo);     pBl1 = *(const uint4*)(gBlo + 8);

    for (int kb = 0; kb < 16; kb++) {
        *(uint4*)(sAhi + so) = pAh0;  *(uint4*)(sAhi + so + 8) = pAh1;
        *(uint4*)(sAlo + so) = pAl0;  *(uint4*)(sAlo + so + 8) = pAl1;
        *(uint4*)(sBhi + so) = pBh0;  *(uint4*)(sBhi + so + 8) = pBh1;
        *(uint4*)(sBlo + so) = pBl0;  *(uint4*)(sBlo + so + 8) = pBl1;
        __syncthreads();

        if (kb < 15) {
            int ko = (kb + 1) * 32;
            pAh0 = *(const uint4*)(gAhi + ko);  pAh1 = *(const uint4*)(gAhi + ko + 8);
            pAl0 = *(const uint4*)(gAlo + ko);  pAl1 = *(const uint4*)(gAlo + ko + 8);
            pBh0 = *(const uint4*)(gBhi + ko);  pBh1 = *(const uint4*)(gBhi + ko + 8);
            pBl0 = *(const uint4*)(gBlo + ko);  pBl1 = *(const uint4*)(gBlo + ko + 8);
        }

#pragma unroll
        for (int kh = 0; kh < 32; kh += 16) {
            uint32_t ah[2][4], al[2][4];
#pragma unroll
            for (int mt = 0; mt < 2; mt++) {
                int off = (wm + mt * 16 + a_r) * WROW + kh + a_c;
                ldsm_x4(ah[mt][0], ah[mt][1], ah[mt][2], ah[mt][3],
                        smem_u32(sAhi + off));
                ldsm_x4(al[mt][0], al[mt][1], al[mt][2], al[mt][3],
                        smem_u32(sAlo + off));
            }
            uint32_t bh[8][2], bl[8][2];
#pragma unroll
            for (int p = 0; p < 4; p++) {
                int off = (wn + p * 16 + b_r) * WROW + kh + b_c;
                ldsm_x4(bh[p * 2][0], bh[p * 2][1], bh[p * 2 + 1][0], bh[p * 2 + 1][1],
                        smem_u32(sBhi + off));
                ldsm_x4(bl[p * 2][0], bl[p * 2][1], bl[p * 2 + 1][0], bl[p * 2 + 1][1],
                        smem_u32(sBlo + off));
            }
#pragma unroll
            for (int mt = 0; mt < 2; mt++)
#pragma unroll
                for (int nt = 0; nt < 8; nt++) {
                    float* c = acc[mt * 8 + nt];
                    mma_bf16(c, ah[mt], bh[nt]);
                    mma_bf16(c, ah[mt], bl[nt]);
                    mma_bf16(c, al[mt], bh[nt]);
                }
        }
        __syncthreads();
    }

    // epilogue: acc[mt*8+nt] -> rows m0+wm+mt*16+{g,g+8}, cols n0+wn+nt*8+c2+{0,1}
    const int g  = lane >> 2;
    const int c2 = (lane & 3) * 2;
#pragma unroll
    for (int nt = 0; nt < 8; nt++) {
        const int col = n0 + wn + nt * 8 + c2;
        const float b0 = bias[col], b1 = bias[col + 1];
#pragma unroll
        for (int mt = 0; mt < 2; mt++) {
            const float* c = acc[mt * 8 + nt];
            const int r0 = m0 + wm + mt * 16 + g;
            float2 v0 = make_float2(c[0] + b0, c[1] + b1);
            float2 v1 = make_float2(c[2] + b0, c[3] + b1);
            *(float2*)(C + (long)r0 * VV + col)       = v0;
            *(float2*)(C + (long)(r0 + 8) * VV + col) = v1;
        }
    }
}

// ---------------------------------------------------------------------------
// Reset grid barrier counter
// ---------------------------------------------------------------------------
__global__ void reset_bar() { g_barcnt = 0u; }

// ---------------------------------------------------------------------------
// Persistent BiLSTM scan (unchanged from passing version).
// ---------------------------------------------------------------------------
#define LSTM_SMEM_FLOATS (16 * 512 + 512 * 9 + 128 * 33 + 32)

__global__ __launch_bounds__(256, 2) void lstm_scan(
    const float* __restrict__ xf, const float* __restrict__ xb,
    const float* __restrict__ Wrf, const float* __restrict__ Wrb,
    const float* __restrict__ h0f, const float* __restrict__ c0f,
    const float* __restrict__ h0b, const float* __restrict__ c0b,
    float* __restrict__ houtf, float* __restrict__ houtb,
    float* __restrict__ hcur, const int* __restrict__ len)
{
    extern __shared__ float sm[];
    float* Ws   = sm;
    float* hsT  = sm + 16 * 512;
    float* part = hsT + 512 * 9;
    float* cst  = part + 128 * 33;

    const int tid = threadIdx.x;
    const int dir = blockIdx.x >> 7;
    const int kb  = blockIdx.x & 127;
    const int j0  = kb * 4;
    const float* Wr = dir ? Wrb : Wrf;
    const float* xp = dir ? xb : xf;
    const float* h0 = dir ? h0b : h0f;
    const float* c0 = dir ? c0b : c0f;
    float* hout  = dir ? houtb : houtf;
    float* hbase = hcur + dir * (2 * BB * HH);

    {
        int col = tid & 15;
        int gcol = (col >> 2) * 512 + j0 + (col & 3);
        for (int k = tid >> 4; k < 512; k += 16)
            Ws[col * 512 + k] = Wr[(long)k * G4 + gcol];
    }
    if (tid < 32) {
        int u = tid >> 3, b = tid & 7;
        cst[u * 8 + b] = c0[j0 + u];
        __stcg(&hbase[(j0 + u) * 8 + b], h0[j0 + u]);
    }

    const int ks = tid & 31;
    const int bg = (tid >> 5) & 1;
    const int cg = tid >> 6;
    unsigned phase = 1;

#define GRIDBAR()                                                         \
    do {                                                                  \
        __syncthreads();                                                  \
        if (tid == 0) {                                                   \
            __threadfence();                                              \
            atomicAdd(&g_barcnt, 1u);                                     \
            unsigned tgt = 256u * phase;                                  \
            while (*(volatile unsigned*)&g_barcnt < tgt) {}               \
        }                                                                 \
        __syncthreads();                                                  \
        phase++;                                                          \
    } while (0)

    GRIDBAR();

    for (int s = 0; s < SS; s++) {
        const float* hrd = hbase + (s & 1) * (BB * HH);
        float* hwr = hbase + ((s + 1) & 1) * (BB * HH);

        for (int f = tid; f < BB * HH; f += 256)
            hsT[(f >> 3) * 9 + (f & 7)] = __ldcg(hrd + f);
        __syncthreads();

        float acc[4][4];
#pragma unroll
        for (int c = 0; c < 4; c++)
#pragma unroll
            for (int j = 0; j < 4; j++) acc[c][j] = 0.f;

#pragma unroll 4
        for (int i = 0; i < 16; i++) {
            int k = ks + 32 * i;
            float h0v = hsT[k * 9 + bg * 4 + 0];
            float h1v = hsT[k * 9 + bg * 4 + 1];
            float h2v = hsT[k * 9 + bg * 4 + 2];
            float h3v = hsT[k * 9 + bg * 4 + 3];
#pragma unroll
            for (int c = 0; c < 4; c++) {
                float w = Ws[(cg * 4 + c) * 512 + k];
                acc[c][0] = fmaf(w, h0v, acc[c][0]);
                acc[c][1] = fmaf(w, h1v, acc[c][1]);
                acc[c][2] = fmaf(w, h2v, acc[c][2]);
                acc[c][3] = fmaf(w, h3v, acc[c][3]);
            }
        }
#pragma unroll
        for (int c = 0; c < 4; c++)
#pragma unroll
            for (int j = 0; j < 4; j++)
                part[((cg * 4 + c) * 8 + bg * 4 + j) * 33 + ks] = acc[c][j];
        __syncthreads();

        const int t_real = dir ? (SS - 1 - s) : s;

        if (tid < 128) {
            float ssum = 0.f;
#pragma unroll
            for (int i = 0; i < 32; i++) ssum += part[tid * 33 + i];
            int col = tid >> 3, b = tid & 7;
            int gg = col >> 2, u = col & 3;
            ssum += xp[((long)(b * SS + t_real)) * G4 + gg * 512 + j0 + u];
            part[tid * 33 + 32] = ssum;
        }
        __syncthreads();

        if (tid < 32) {
            int u = tid >> 3, b = tid & 7;
            float ig = part[((0  + u) * 8 + b) * 33 + 32];
            float fg = part[((4  + u) * 8 + b) * 33 + 32];
            float og = part[((8  + u) * 8 + b) * 33 + 32];
            float gg = part[((12 + u) * 8 + b) * 33 + 32];
            float cp = cst[u * 8 + b];
            float hp = hsT[(j0 + u) * 9 + b];
            float cn = sigm(fg) * cp + sigm(ig) * tanhf(gg);
            float hn = sigm(og) * tanhf(cn);
            int active = t_real < len[b];
            float h = active ? hn : hp;
            float c = active ? cn : cp;
            cst[u * 8 + b] = c;
            __stcg(&hwr[(j0 + u) * 8 + b], h);
            hout[((long)(b * SS + t_real)) * HH + j0 + u] = h;
        }
        GRIDBAR();
    }
#undef GRIDBAR
}

// ---------------------------------------------------------------------------
// Host driver
// ---------------------------------------------------------------------------
extern "C" void kernel_launch(void* const* d_in, const int* in_sizes, int n_in,
                              void* d_out, int out_size) {
    const int*   x    = (const int*)  d_in[0];
    const float* emb  = (const float*)d_in[1];
    const float* Wf0  = (const float*)d_in[2];
    const float* bf0  = (const float*)d_in[3];
    const float* Wb0  = (const float*)d_in[4];
    const float* bb0  = (const float*)d_in[5];
    const float* Wf1  = (const float*)d_in[6];
    const float* bf1  = (const float*)d_in[7];
    const float* Wb1  = (const float*)d_in[8];
    const float* bb1  = (const float*)d_in[9];
    const float* h0f  = (const float*)d_in[10];
    const float* c0f  = (const float*)d_in[11];
    const float* h0b  = (const float*)d_in[12];
    const float* c0b  = (const float*)d_in[13];
    const float* Wq   = (const float*)d_in[14];
    const float* bq   = (const float*)d_in[15];
    const float* Wao  = (const float*)d_in[16];
    const float* bao  = (const float*)d_in[17];
    const float* ln1g = (const float*)d_in[18];
    const float* ln1b = (const float*)d_in[19];
    const float* Wh   = (const float*)d_in[20];
    const float* bh   = (const float*)d_in[21];
    const float* ln2g = (const float*)d_in[22];
    const float* ln2b = (const float*)d_in[23];
    const float* Wp   = (const float*)d_in[24];
    const float* ob   = (const float*)d_in[25];
    float* out = (float*)d_out;

    float *embx, *xf, *xb, *hf, *hb, *lay, *query, *scores, *ctx, *pre, *ref,
          *hpre, *hcur;
    __nv_bfloat16 *hhi, *hlo, *wpthi, *wptlo;
    int* len;
    cudaGetSymbolAddress((void**)&embx,   g_embx);
    cudaGetSymbolAddress((void**)&xf,     g_xf);
    cudaGetSymbolAddress((void**)&xb,     g_xb);
    cudaGetSymbolAddress((void**)&hf,     g_hf);
    cudaGetSymbolAddress((void**)&hb,     g_hb);
    cudaGetSymbolAddress((void**)&lay,    g_lay);
    cudaGetSymbolAddress((void**)&query,  g_query);
    cudaGetSymbolAddress((void**)&scores, g_scores);
    cudaGetSymbolAddress((void**)&ctx,    g_ctx);
    cudaGetSymbolAddress((void**)&pre,    g_pre);
    cudaGetSymbolAddress((void**)&ref,    g_ref);
    cudaGetSymbolAddress((void**)&hpre,   g_hpre);
    cudaGetSymbolAddress((void**)&hcur,   g_hcur);
    cudaGetSymbolAddress((void**)&len,    g_len);
    cudaGetSymbolAddress((void**)&hhi,    g_hhi);
    cudaGetSymbolAddress((void**)&hlo,    g_hlo);
    cudaGetSymbolAddress((void**)&wpthi,  g_wpthi);
    cudaGetSymbolAddress((void**)&wptlo,  g_wptlo);

    const int lstm_smem = LSTM_SMEM_FLOATS * 4;
    cudaFuncSetAttribute(lstm_scan, cudaFuncAttributeMaxDynamicSharedMemorySize,
                         lstm_smem);

    len_kernel<<<BB, 512>>>(x, len);
    embed_kernel<<<NROW, 128>>>(x, emb, embx);
    wp_transpose<<<dim3(VV / 32, HH / 32), dim3(32, 8)>>>(Wp, wpthi, wptlo);

    // ---- layer 0 ----
    {
        dim3 g(G4 / 128, NROW / 128, 1);
        gemm_nn<<<g, 256>>>(embx, Wf0, bf0, xf, NROW, G4, EE, EE, G4, G4, 0, 0, 0, 0);
        gemm_nn<<<g, 256>>>(embx, Wb0, bb0, xb, NROW, G4, EE, EE, G4, G4, 0, 0, 0, 0);
    }
    reset_bar<<<1, 1>>>();
    lstm_scan<<<256, 256, lstm_smem>>>(xf, xb,
                                       Wf0 + (long)EE * G4, Wb0 + (long)EE * G4,
                                       h0f, c0f, h0b, c0b, hf, hb, hcur, len);
    build_lay<<<NROW, 256>>>(hf, hb, len, lay);

    // ---- layer 1 ----
    {
        dim3 g(G4 / 128, NROW / 128, 1);
        gemm_nn<<<g, 256>>>(lay, Wf1, bf1, xf, NROW, G4, D2, D2, G4, G4, 0, 0, 0, 0);
        gemm_nn<<<g, 256>>>(lay, Wb1, bb1, xb, NROW, G4, D2, D2, G4, G4, 0, 0, 0, 0);
    }
    reset_bar<<<1, 1>>>();
    lstm_scan<<<256, 256, lstm_smem>>>(xf, xb,
                                       Wf1 + (long)D2 * G4, Wb1 + (long)D2 * G4,
                                       h0f + HH, c0f + HH, h0b + HH, c0b + HH,
                                       hf, hb, hcur, len);
    build_lay<<<NROW, 256>>>(hf, hb, len, lay);  // lay = encoded

    // ---- attention ----
    {
        dim3 g(D2 / 128, NROW / 128, 1);
        gemm_nn<<<g, 256>>>(lay, Wq, bq, query, NROW, D2, D2, D2, D2, D2, 0, 0, 0, 0);
    }
    {
        dim3 g(SS / 64, SS / 64, BB);
        gemm_nt_scores<<<g, 256>>>(query, lay, scores);
    }
    {
        dim3 g(SS, BB, 1);
        softmax_kernel<<<g, 256>>>(scores, len);
    }
    {
        dim3 g(D2 / 128, SS / 128, BB);
        gemm_nn<<<g, 256>>>(scores, lay, nullptr, ctx, SS, D2, SS, SS, D2, D2,
                            (long)SS * SS, (long)SS * D2, (long)SS * D2, 0);
    }
    {
        dim3 g(D2 / 128, NROW / 128, 1);
        gemm_nn<<<g, 256>>>(lay, Wao, bao, pre, NROW, D2, D2, D2, D2, D2, 0, 0, 0, 0);
        gemm_nn<<<g, 256>>>(ctx, Wao + (long)D2 * D2, nullptr, pre,
                            NROW, D2, D2, D2, D2, D2, 0, 0, 0, 1);
    }
    refine_ln<<<NROW, 256>>>(lay, pre, ln1g, ln1b, len, ref);

    // ---- head ----
    {
        dim3 g(HH / 128, NROW / 128, 1);
        gemm_nn<<<g, 256>>>(ref, Wh, bh, hpre, NROW, HH, D2, D2, HH, HH, 0, 0, 0, 0);
    }
    head_ln<<<NROW, 256>>>(hpre, ln2g, ln2b, hhi, hlo);

    // ---- vocab projection (mma.sync split-bf16) ----
    wp_gemm<<<dim3(NROW / 128, VV / 128), 256>>>(hhi, hlo, wpthi, wptlo, ob, out);
}

// round 10
// speedup vs baseline: 1.4018x; 1.1240x over previous
#include <cuda_runtime.h>
#include <cuda_bf16.h>
#include <math.h>
#include <stdint.h>

// ---------------------------------------------------------------------------
// Problem constants: V=32000, E=512, H=512, L=2, B=8, S=512
// ---------------------------------------------------------------------------
#define SS   512
#define BB   8
#define EE   512
#define HH   512
#define D2   1024      // 2H
#define G4   2048      // 4H
#define VV   32000
#define NROW 4096      // B*S

// ---------------------------------------------------------------------------
// Device scratch (no cudaMalloc allowed)
// ---------------------------------------------------------------------------
__device__ float g_embx  [NROW * EE];
__device__ float g_xf    [NROW * G4];
__device__ float g_xb    [NROW * G4];
__device__ float g_hf    [NROW * HH];
__device__ float g_hb    [NROW * HH];
__device__ float g_lay   [NROW * D2];
__device__ float g_query [NROW * D2];
__device__ float g_scores[BB * SS * SS];
__device__ float g_ctx   [NROW * D2];
__device__ float g_pre   [NROW * D2];
__device__ float g_ref   [NROW * D2];
__device__ float g_hpre  [NROW * HH];
__device__ float g_hcur  [2 * 2 * BB * HH];
__device__ int   g_len   [BB];
__device__ unsigned g_barcnt;

// bf16 split operand buffers
__device__ __nv_bfloat16 g_ahi  [NROW * D2];        // A-side hi (max 4096x1024)
__device__ __nv_bfloat16 g_alo  [NROW * D2];        // A-side lo
__device__ __nv_bfloat16 g_bhi  [G4 * D2];          // weight hi (max 2048x1024)
__device__ __nv_bfloat16 g_blo  [G4 * D2];          // weight lo
__device__ __nv_bfloat16 g_hhi  [NROW * HH];        // head hi
__device__ __nv_bfloat16 g_hlo  [NROW * HH];        // head lo
__device__ __nv_bfloat16 g_wpthi[(long)VV * HH];    // Wp^T hi
__device__ __nv_bfloat16 g_wptlo[(long)VV * HH];    // Wp^T lo

__device__ __forceinline__ float sigm(float x) { return 1.f / (1.f + expf(-x)); }

__device__ __forceinline__ uint32_t smem_u32(const void* p) {
    uint32_t a;
    asm("{ .reg .u64 t; cvta.to.shared.u64 t, %1; cvt.u32.u64 %0, t; }"
        : "=r"(a) : "l"(p));
    return a;
}

// mma.sync bf16 (baseline PTX, assembles for sm_103 non-'a')
__device__ __forceinline__ void mma_bf16(float* c, const uint32_t* a,
                                         const uint32_t* b) {
    asm volatile(
        "mma.sync.aligned.m16n8k16.row.col.f32.bf16.bf16.f32 "
        "{%0,%1,%2,%3}, {%4,%5,%6,%7}, {%8,%9}, {%0,%1,%2,%3};"
        : "+f"(c[0]), "+f"(c[1]), "+f"(c[2]), "+f"(c[3])
        : "r"(a[0]), "r"(a[1]), "r"(a[2]), "r"(a[3]), "r"(b[0]), "r"(b[1]));
}

__device__ __forceinline__ void ldsm_x4(uint32_t& r0, uint32_t& r1,
                                        uint32_t& r2, uint32_t& r3,
                                        uint32_t addr) {
    asm volatile("ldmatrix.sync.aligned.m8n8.x4.shared.b16 {%0,%1,%2,%3}, [%4];"
                 : "=r"(r0), "=r"(r1), "=r"(r2), "=r"(r3) : "r"(addr));
}

// ---------------------------------------------------------------------------
// lengths per batch
// ---------------------------------------------------------------------------
__global__ void len_kernel(const int* __restrict__ x, int* __restrict__ len) {
    __shared__ int red[512];
    int b = blockIdx.x, tid = threadIdx.x;
    red[tid] = (x[b * SS + tid] != 0) ? 1 : 0;
    __syncthreads();
    for (int s = 256; s > 0; s >>= 1) {
        if (tid < s) red[tid] += red[tid + s];
        __syncthreads();
    }
    if (tid == 0) len[b] = red[0];
}

// ---------------------------------------------------------------------------
// embedding gather
// ---------------------------------------------------------------------------
__global__ void embed_kernel(const int* __restrict__ x, const float* __restrict__ emb,
                             float* __restrict__ out) {
    int r = blockIdx.x;
    long tok = (long)x[r];
    float4 v = ((const float4*)(emb + tok * EE))[threadIdx.x];
    ((float4*)(out + (long)r * EE))[threadIdx.x] = v;
}

// ---------------------------------------------------------------------------
// split fp32 -> bf16 hi/lo (elementwise, vectorized)
// ---------------------------------------------------------------------------
__global__ void split_f32(const float* __restrict__ in,
                          __nv_bfloat16* __restrict__ hi,
                          __nv_bfloat16* __restrict__ lo, int n4) {
    int i = blockIdx.x * blockDim.x + threadIdx.x;
    if (i >= n4) return;
    float4 v = ((const float4*)in)[i];
    __nv_bfloat16 h0 = __float2bfloat16(v.x);
    __nv_bfloat16 h1 = __float2bfloat16(v.y);
    __nv_bfloat16 h2 = __float2bfloat16(v.z);
    __nv_bfloat16 h3 = __float2bfloat16(v.w);
    __nv_bfloat162 ph0 = {h0, h1}, ph1 = {h2, h3};
    __nv_bfloat162 pl0 = {__float2bfloat16(v.x - __bfloat162float(h0)),
                          __float2bfloat16(v.y - __bfloat162float(h1))};
    __nv_bfloat162 pl1 = {__float2bfloat16(v.z - __bfloat162float(h2)),
                          __float2bfloat16(v.w - __bfloat162float(h3))};
    ((__nv_bfloat162*)hi)[i * 2]     = ph0;
    ((__nv_bfloat162*)hi)[i * 2 + 1] = ph1;
    ((__nv_bfloat162*)lo)[i * 2]     = pl0;
    ((__nv_bfloat162*)lo)[i * 2 + 1] = pl1;
}

// ---------------------------------------------------------------------------
// Weight transpose + split: W[K, N] (row stride ldw) -> T{hi,lo}[N][K]
// grid (N/32, K/32), block (32, 8)
// ---------------------------------------------------------------------------
__global__ void wt_split(const float* __restrict__ W, int ldw, int K,
                         __nv_bfloat16* __restrict__ Thi,
                         __nv_bfloat16* __restrict__ Tlo) {
    __shared__ float tile[32][33];
    int n0 = blockIdx.x * 32, k0 = blockIdx.y * 32;
    int tx = threadIdx.x, ty = threadIdx.y;
#pragma unroll
    for (int i = 0; i < 4; i++)
        tile[ty + i * 8][tx] = W[(long)(k0 + ty + i * 8) * ldw + n0 + tx];
    __syncthreads();
#pragma unroll
    for (int i = 0; i < 4; i++) {
        int n = n0 + ty + i * 8, k = k0 + tx;
        float v = tile[tx][ty + i * 8];
        __nv_bfloat16 hi = __float2bfloat16(v);
        float lo = v - __bfloat162float(hi);
        Thi[(long)n * K + k] = hi;
        Tlo[(long)n * K + k] = __float2bfloat16(lo);
    }
}

// ---------------------------------------------------------------------------
// Generic split-bf16 mma.sync GEMM: C[M,N] = Ahi/lo[M,K] @ B{hi,lo}[N,K]^T
// D = Ahi*Bhi + Ahi*Blo + Alo*Bhi, fp32 accum. Optional bias / accumulate.
// CTA tile 128x128, K-slab 32. 8 warps (4m x 2n), warp tile 32x64.
// SMEM rows padded to 40 bf16 (80B) -> conflict-free ldmatrix.
// M,N multiples of 128; K multiple of 32.
// ---------------------------------------------------------------------------
#define WROW 40

__global__ __launch_bounds__(256, 1) void hgemm(
    const __nv_bfloat16* __restrict__ Ahi, const __nv_bfloat16* __restrict__ Alo,
    const __nv_bfloat16* __restrict__ Bhi, const __nv_bfloat16* __restrict__ Blo,
    const float* __restrict__ bias, float* __restrict__ C,
    int N, int K, int accum)
{
    __shared__ __nv_bfloat16 sAhi[128 * WROW], sAlo[128 * WROW];
    __shared__ __nv_bfloat16 sBhi[128 * WROW], sBlo[128 * WROW];

    const int tid  = threadIdx.x;
    const int warp = tid >> 5, lane = tid & 31;
    const int wm = (warp & 3) * 32;
    const int wn = (warp >> 2) * 64;
    const int m0 = blockIdx.x * 128, n0 = blockIdx.y * 128;
    const int nk = K >> 5;

    const int lr = tid >> 1;
    const int lu = (tid & 1) * 2;
    const __nv_bfloat16* gAhi = Ahi + (long)(m0 + lr) * K + lu * 8;
    const __nv_bfloat16* gAlo = Alo + (long)(m0 + lr) * K + lu * 8;
    const __nv_bfloat16* gBhi = Bhi + (long)(n0 + lr) * K + lu * 8;
    const __nv_bfloat16* gBlo = Blo + (long)(n0 + lr) * K + lu * 8;
    const int so = lr * WROW + lu * 8;

    const int a_r = (lane & 15);
    const int a_c = (lane >> 4) << 3;
    const int b_r = ((lane >> 4) << 3) + (lane & 7);
    const int b_c = ((lane >> 3) & 1) << 3;

    float acc[16][4];
#pragma unroll
    for (int i = 0; i < 16; i++)
#pragma unroll
        for (int j = 0; j < 4; j++) acc[i][j] = 0.f;

    uint4 pAh0, pAh1, pAl0, pAl1, pBh0, pBh1, pBl0, pBl1;
    pAh0 = *(const uint4*)(gAhi);     pAh1 = *(const uint4*)(gAhi + 8);
    pAl0 = *(const uint4*)(gAlo);     pAl1 = *(const uint4*)(gAlo + 8);
    pBh0 = *(const uint4*)(gBhi);     pBh1 = *(const uint4*)(gBhi + 8);
    pBl0 = *(const uint4*)(gBlo);     pBl1 = *(const uint4*)(gBlo + 8);

    for (int kb = 0; kb < nk; kb++) {
        *(uint4*)(sAhi + so) = pAh0;  *(uint4*)(sAhi + so + 8) = pAh1;
        *(uint4*)(sAlo + so) = pAl0;  *(uint4*)(sAlo + so + 8) = pAl1;
        *(uint4*)(sBhi + so) = pBh0;  *(uint4*)(sBhi + so + 8) = pBh1;
        *(uint4*)(sBlo + so) = pBl0;  *(uint4*)(sBlo + so + 8) = pBl1;
        __syncthreads();

        if (kb < nk - 1) {
            int ko = (kb + 1) * 32;
            pAh0 = *(const uint4*)(gAhi + ko);  pAh1 = *(const uint4*)(gAhi + ko + 8);
            pAl0 = *(const uint4*)(gAlo + ko);  pAl1 = *(const uint4*)(gAlo + ko + 8);
            pBh0 = *(const uint4*)(gBhi + ko);  pBh1 = *(const uint4*)(gBhi + ko + 8);
            pBl0 = *(const uint4*)(gBlo + ko);  pBl1 = *(const uint4*)(gBlo + ko + 8);
        }

#pragma unroll
        for (int kh = 0; kh < 32; kh += 16) {
            uint32_t ah[2][4], al[2][4];
#pragma unroll
            for (int mt = 0; mt < 2; mt++) {
                int off = (wm + mt * 16 + a_r) * WROW + kh + a_c;
                ldsm_x4(ah[mt][0], ah[mt][1], ah[mt][2], ah[mt][3],
                        smem_u32(sAhi + off));
                ldsm_x4(al[mt][0], al[mt][1], al[mt][2], al[mt][3],
                        smem_u32(sAlo + off));
            }
            uint32_t bh[8][2], bl[8][2];
#pragma unroll
            for (int p = 0; p < 4; p++) {
                int off = (wn + p * 16 + b_r) * WROW + kh + b_c;
                ldsm_x4(bh[p * 2][0], bh[p * 2][1], bh[p * 2 + 1][0], bh[p * 2 + 1][1],
                        smem_u32(sBhi + off));
                ldsm_x4(bl[p * 2][0], bl[p * 2][1], bl[p * 2 + 1][0], bl[p * 2 + 1][1],
                        smem_u32(sBlo + off));
            }
#pragma unroll
            for (int mt = 0; mt < 2; mt++)
#pragma unroll
                for (int nt = 0; nt < 8; nt++) {
                    float* c = acc[mt * 8 + nt];
                    mma_bf16(c, ah[mt], bh[nt]);
                    mma_bf16(c, ah[mt], bl[nt]);
                    mma_bf16(c, al[mt], bh[nt]);
                }
        }
        __syncthreads();
    }

    const int g  = lane >> 2;
    const int c2 = (lane & 3) * 2;
#pragma unroll
    for (int nt = 0; nt < 8; nt++) {
        const int col = n0 + wn + nt * 8 + c2;
        float b0 = 0.f, b1 = 0.f;
        if (bias) { b0 = bias[col]; b1 = bias[col + 1]; }
#pragma unroll
        for (int mt = 0; mt < 2; mt++) {
            const float* c = acc[mt * 8 + nt];
            const int r0 = m0 + wm + mt * 16 + g;
            long o0 = (long)r0 * N + col;
            long o1 = (long)(r0 + 8) * N + col;
            float2 v0 = make_float2(c[0] + b0, c[1] + b1);
            float2 v1 = make_float2(c[2] + b0, c[3] + b1);
            if (accum) {
                float2 e0 = *(const float2*)(C + o0);
                float2 e1 = *(const float2*)(C + o1);
                v0.x += e0.x; v0.y += e0.y; v1.x += e1.x; v1.y += e1.y;
            }
            *(float2*)(C + o0) = v0;
            *(float2*)(C + o1) = v1;
        }
    }
}

// ---------------------------------------------------------------------------
// Attention score GEMM (NT), fp32 (small)
// ---------------------------------------------------------------------------
__global__ __launch_bounds__(256) void gemm_nt_scores(
    const float* __restrict__ Q, const float* __restrict__ E,
    float* __restrict__ C)
{
    const int b = blockIdx.z;
    const float* Qb = Q + (long)b * SS * D2;
    const float* Eb = E + (long)b * SS * D2;
    float* Cb = C + (long)b * SS * SS;
    const int m0 = blockIdx.y * 64, n0 = blockIdx.x * 64;
    __shared__ float Qs[16][68];
    __shared__ float Es[16][68];
    const int tid = threadIdx.x;
    const int tx = tid & 15, ty = tid >> 4;
    float acc[4][4];
#pragma unroll
    for (int i = 0; i < 4; i++)
#pragma unroll
        for (int j = 0; j < 4; j++) acc[i][j] = 0.f;

    for (int k0 = 0; k0 < D2; k0 += 16) {
        int row = tid >> 2, q = tid & 3;
        float4 v = *(const float4*)(Qb + (long)(m0 + row) * D2 + k0 + q * 4);
        Qs[q * 4 + 0][row] = v.x; Qs[q * 4 + 1][row] = v.y;
        Qs[q * 4 + 2][row] = v.z; Qs[q * 4 + 3][row] = v.w;
        v = *(const float4*)(Eb + (long)(n0 + row) * D2 + k0 + q * 4);
        Es[q * 4 + 0][row] = v.x; Es[q * 4 + 1][row] = v.y;
        Es[q * 4 + 2][row] = v.z; Es[q * 4 + 3][row] = v.w;
        __syncthreads();
#pragma unroll
        for (int k = 0; k < 16; k++) {
            float4 a4 = *(const float4*)&Qs[k][ty * 4];
            float4 b4 = *(const float4*)&Es[k][tx * 4];
            float ar[4] = {a4.x, a4.y, a4.z, a4.w};
            float br[4] = {b4.x, b4.y, b4.z, b4.w};
#pragma unroll
            for (int i = 0; i < 4; i++)
#pragma unroll
                for (int j = 0; j < 4; j++)
                    acc[i][j] = fmaf(ar[i], br[j], acc[i][j]);
        }
        __syncthreads();
    }
    const float scale = 0.03125f;
#pragma unroll
    for (int i = 0; i < 4; i++)
#pragma unroll
        for (int j = 0; j < 4; j++)
            Cb[(long)(m0 + ty * 4 + i) * SS + n0 + tx * 4 + j] = acc[i][j] * scale;
}

// ---------------------------------------------------------------------------
// Batched ctx GEMM (fp32, small): ctx[b] = attn[b] @ enc[b]
// 128x128x16 tiles, per-batch via blockIdx.z
// ---------------------------------------------------------------------------
__global__ __launch_bounds__(256, 2) void gemm_ctx(
    const float* __restrict__ A, const float* __restrict__ W,
    float* __restrict__ C)
{
    A += (long)blockIdx.z * SS * SS;
    W += (long)blockIdx.z * SS * D2;
    C += (long)blockIdx.z * SS * D2;
    const int m0 = blockIdx.y * 128, n0 = blockIdx.x * 128;
    __shared__ float As[2][16][132];
    __shared__ float Bs[2][16][132];
    const int tid = threadIdx.x;
    const int tx = tid & 15, ty = tid >> 4;

    const int arow = tid >> 1;
    const int akq  = (tid & 1) * 8;
    const int brow = tid >> 4;
    const int bcol = (tid & 15) * 8;

    const float* Aptr = A + (long)(m0 + arow) * SS + akq;
    const float* Bptr = W + (long)brow * D2 + n0 + bcol;

    float4 pa0, pa1, pb0, pb1;
    pa0 = *(const float4*)(Aptr);
    pa1 = *(const float4*)(Aptr + 4);
    pb0 = *(const float4*)(Bptr);
    pb1 = *(const float4*)(Bptr + 4);
    {
        As[0][akq + 0][arow] = pa0.x; As[0][akq + 1][arow] = pa0.y;
        As[0][akq + 2][arow] = pa0.z; As[0][akq + 3][arow] = pa0.w;
        As[0][akq + 4][arow] = pa1.x; As[0][akq + 5][arow] = pa1.y;
        As[0][akq + 6][arow] = pa1.z; As[0][akq + 7][arow] = pa1.w;
        *(float4*)&Bs[0][brow][bcol]     = pb0;
        *(float4*)&Bs[0][brow][bcol + 4] = pb1;
    }
    __syncthreads();

    float acc[8][8];
#pragma unroll
    for (int i = 0; i < 8; i++)
#pragma unroll
        for (int j = 0; j < 8; j++) acc[i][j] = 0.f;

    int buf = 0;
    for (int k0 = 0; k0 < SS; k0 += 16) {
        const int nxt = buf ^ 1;
        const bool more = (k0 + 16) < SS;
        if (more) {
            pa0 = *(const float4*)(Aptr + k0 + 16);
            pa1 = *(const float4*)(Aptr + k0 + 20);
            pb0 = *(const float4*)(Bptr + (long)(k0 + 16) * D2);
            pb1 = *(const float4*)(Bptr + (long)(k0 + 16) * D2 + 4);
        }
#pragma unroll
        for (int k = 0; k < 16; k++) {
            float4 a0 = *(const float4*)&As[buf][k][ty * 4];
            float4 a1 = *(const float4*)&As[buf][k][ty * 4 + 64];
            float4 b0 = *(const float4*)&Bs[buf][k][tx * 4];
            float4 b1 = *(const float4*)&Bs[buf][k][tx * 4 + 64];
            float ar[8] = {a0.x, a0.y, a0.z, a0.w, a1.x, a1.y, a1.z, a1.w};
            float br[8] = {b0.x, b0.y, b0.z, b0.w, b1.x, b1.y, b1.z, b1.w};
#pragma unroll
            for (int i = 0; i < 8; i++)
#pragma unroll
                for (int j = 0; j < 8; j++)
                    acc[i][j] = fmaf(ar[i], br[j], acc[i][j]);
        }
        if (more) {
            As[nxt][akq + 0][arow] = pa0.x; As[nxt][akq + 1][arow] = pa0.y;
            As[nxt][akq + 2][arow] = pa0.z; As[nxt][akq + 3][arow] = pa0.w;
            As[nxt][akq + 4][arow] = pa1.x; As[nxt][akq + 5][arow] = pa1.y;
            As[nxt][akq + 6][arow] = pa1.z; As[nxt][akq + 7][arow] = pa1.w;
            *(float4*)&Bs[nxt][brow][bcol]     = pb0;
            *(float4*)&Bs[nxt][brow][bcol + 4] = pb1;
        }
        __syncthreads();
        buf = nxt;
    }

#pragma unroll
    for (int ih = 0; ih < 2; ih++) {
#pragma unroll
        for (int i = 0; i < 4; i++) {
            const int ri = ih * 4 + i;
            const int m = m0 + ih * 64 + ty * 4 + i;
            long off = (long)m * D2 + n0 + tx * 4;
            *(float4*)(C + off) = make_float4(acc[ri][0], acc[ri][1],
                                              acc[ri][2], acc[ri][3]);
            *(float4*)(C + off + 64) = make_float4(acc[ri][4], acc[ri][5],
                                                   acc[ri][6], acc[ri][7]);
        }
    }
}

// ---------------------------------------------------------------------------
// Masked softmax per (b, q) row
// ---------------------------------------------------------------------------
__global__ void softmax_kernel(float* __restrict__ sc, const int* __restrict__ len) {
    const int q = blockIdx.x, b = blockIdx.y;
    float* row = sc + ((long)b * SS + q) * SS;
    const int L = len[b];
    const int t = threadIdx.x;
    __shared__ float red[256];
    if (q >= L) {
        for (int i = t; i < SS; i += 256) row[i] = 0.f;
        return;
    }
    float m = -3.402823466e38f;
    for (int i = t; i < L; i += 256) m = fmaxf(m, row[i]);
    red[t] = m; __syncthreads();
    for (int s = 128; s > 0; s >>= 1) {
        if (t < s) red[t] = fmaxf(red[t], red[t + s]);
        __syncthreads();
    }
    m = red[0]; __syncthreads();
    float sum = 0.f;
    for (int i = t; i < L; i += 256) sum += expf(row[i] - m);
    red[t] = sum; __syncthreads();
    for (int s = 128; s > 0; s >>= 1) {
        if (t < s) red[t] += red[t + s];
        __syncthreads();
    }
    float inv = 1.f / red[0];
    for (int i = t; i < SS; i += 256)
        row[i] = (i < L) ? expf(row[i] - m) * inv : 0.f;
}

// ---------------------------------------------------------------------------
// Build layer input
// ---------------------------------------------------------------------------
__global__ void build_lay(const float* __restrict__ hf, const float* __restrict__ hb,
                          const int* __restrict__ len, float* __restrict__ lay) {
    int r = blockIdx.x;
    int b = r >> 9, tt = r & 511;
    int active = tt < len[b];
    int t = threadIdx.x;
    for (int i = t; i < D2; i += 256) {
        float v = 0.f;
        if (active) v = (i < HH) ? hf[(long)r * HH + i] : hb[(long)r * HH + i - HH];
        lay[(long)r * D2 + i] = v;
    }
}

// ---------------------------------------------------------------------------
// refined = LN(encoded + tanh(pre)) masked by valid
// ---------------------------------------------------------------------------
__global__ void refine_ln(const float* __restrict__ enc, const float* __restrict__ pre,
                          const float* __restrict__ g, const float* __restrict__ bta,
                          const int* __restrict__ len, float* __restrict__ out) {
    int r = blockIdx.x;
    int b = r >> 9, tt = r & 511;
    int t = threadIdx.x;
    __shared__ float r1[256], r2[256];
    float v[4];
    float s = 0.f, s2 = 0.f;
#pragma unroll
    for (int i = 0; i < 4; i++) {
        int idx = t + i * 256;
        float xx = enc[(long)r * D2 + idx] + tanhf(pre[(long)r * D2 + idx]);
        v[i] = xx; s += xx; s2 += xx * xx;
    }
    r1[t] = s; r2[t] = s2; __syncthreads();
    for (int st = 128; st > 0; st >>= 1) {
        if (t < st) { r1[t] += r1[t + st]; r2[t] += r2[t + st]; }
        __syncthreads();
    }
    float mean = r1[0] * (1.f / 1024.f);
    float var = r2[0] * (1.f / 1024.f) - mean * mean;
    float inv = rsqrtf(var + 1e-5f);
    int active = tt < len[b];
#pragma unroll
    for (int i = 0; i < 4; i++) {
        int idx = t + i * 256;
        float o = (v[i] - mean) * inv * g[idx] + bta[idx];
        out[(long)r * D2 + idx] = active ? o : 0.f;
    }
}

// ---------------------------------------------------------------------------
// head = LN(gelu_exact(hpre)) -> emit bf16 hi/lo split
// ---------------------------------------------------------------------------
__global__ void head_ln(const float* __restrict__ hpre, const float* __restrict__ g,
                        const float* __restrict__ bta,
                        __nv_bfloat16* __restrict__ hhi,
                        __nv_bfloat16* __restrict__ hlo) {
    int r = blockIdx.x;
    int t = threadIdx.x;
    __shared__ float r1[256], r2[256];
    float v[2];
    float s = 0.f, s2 = 0.f;
#pragma unroll
    for (int i = 0; i < 2; i++) {
        int idx = t + i * 256;
        float xx = hpre[(long)r * HH + idx];
        float ge = 0.5f * xx * (1.f + erff(xx * 0.70710678118654752f));
        v[i] = ge; s += ge; s2 += ge * ge;
    }
    r1[t] = s; r2[t] = s2; __syncthreads();
    for (int st = 128; st > 0; st >>= 1) {
        if (t < st) { r1[t] += r1[t + st]; r2[t] += r2[t + st]; }
        __syncthreads();
    }
    float mean = r1[0] * (1.f / 512.f);
    float var = r2[0] * (1.f / 512.f) - mean * mean;
    float inv = rsqrtf(var + 1e-5f);
#pragma unroll
    for (int i = 0; i < 2; i++) {
        int idx = t + i * 256;
        float o = (v[i] - mean) * inv * g[idx] + bta[idx];
        __nv_bfloat16 hi = __float2bfloat16(o);
        float lo = o - __bfloat162float(hi);
        hhi[(long)r * HH + idx] = hi;
        hlo[(long)r * HH + idx] = __float2bfloat16(lo);
    }
}

// ---------------------------------------------------------------------------
// Reset grid barrier counter
// ---------------------------------------------------------------------------
__global__ void reset_bar() { g_barcnt = 0u; }

// ---------------------------------------------------------------------------
// Persistent BiLSTM scan (unchanged from passing version).
// ---------------------------------------------------------------------------
#define LSTM_SMEM_FLOATS (16 * 512 + 512 * 9 + 128 * 33 + 32)

__global__ __launch_bounds__(256, 2) void lstm_scan(
    const float* __restrict__ xf, const float* __restrict__ xb,
    const float* __restrict__ Wrf, const float* __restrict__ Wrb,
    const float* __restrict__ h0f, const float* __restrict__ c0f,
    const float* __restrict__ h0b, const float* __restrict__ c0b,
    float* __restrict__ houtf, float* __restrict__ houtb,
    float* __restrict__ hcur, const int* __restrict__ len)
{
    extern __shared__ float sm[];
    float* Ws   = sm;
    float* hsT  = sm + 16 * 512;
    float* part = hsT + 512 * 9;
    float* cst  = part + 128 * 33;

    const int tid = threadIdx.x;
    const int dir = blockIdx.x >> 7;
    const int kb  = blockIdx.x & 127;
    const int j0  = kb * 4;
    const float* Wr = dir ? Wrb : Wrf;
    const float* xp = dir ? xb : xf;
    const float* h0 = dir ? h0b : h0f;
    const float* c0 = dir ? c0b : c0f;
    float* hout  = dir ? houtb : houtf;
    float* hbase = hcur + dir * (2 * BB * HH);

    {
        int col = tid & 15;
        int gcol = (col >> 2) * 512 + j0 + (col & 3);
        for (int k = tid >> 4; k < 512; k += 16)
            Ws[col * 512 + k] = Wr[(long)k * G4 + gcol];
    }
    if (tid < 32) {
        int u = tid >> 3, b = tid & 7;
        cst[u * 8 + b] = c0[j0 + u];
        __stcg(&hbase[(j0 + u) * 8 + b], h0[j0 + u]);
    }

    const int ks = tid & 31;
    const int bg = (tid >> 5) & 1;
    const int cg = tid >> 6;
    unsigned phase = 1;

#define GRIDBAR()                                                         \
    do {                                                                  \
        __syncthreads();                                                  \
        if (tid == 0) {                                                   \
            __threadfence();                                              \
            atomicAdd(&g_barcnt, 1u);                                     \
            unsigned tgt = 256u * phase;                                  \
            while (*(volatile unsigned*)&g_barcnt < tgt) {}               \
        }                                                                 \
        __syncthreads();                                                  \
        phase++;                                                          \
    } while (0)

    GRIDBAR();

    for (int s = 0; s < SS; s++) {
        const float* hrd = hbase + (s & 1) * (BB * HH);
        float* hwr = hbase + ((s + 1) & 1) * (BB * HH);

        for (int f = tid; f < BB * HH; f += 256)
            hsT[(f >> 3) * 9 + (f & 7)] = __ldcg(hrd + f);
        __syncthreads();

        float acc[4][4];
#pragma unroll
        for (int c = 0; c < 4; c++)
#pragma unroll
            for (int j = 0; j < 4; j++) acc[c][j] = 0.f;

#pragma unroll 4
        for (int i = 0; i < 16; i++) {
            int k = ks + 32 * i;
            float h0v = hsT[k * 9 + bg * 4 + 0];
            float h1v = hsT[k * 9 + bg * 4 + 1];
            float h2v = hsT[k * 9 + bg * 4 + 2];
            float h3v = hsT[k * 9 + bg * 4 + 3];
#pragma unroll
            for (int c = 0; c < 4; c++) {
                float w = Ws[(cg * 4 + c) * 512 + k];
                acc[c][0] = fmaf(w, h0v, acc[c][0]);
                acc[c][1] = fmaf(w, h1v, acc[c][1]);
                acc[c][2] = fmaf(w, h2v, acc[c][2]);
                acc[c][3] = fmaf(w, h3v, acc[c][3]);
            }
        }
#pragma unroll
        for (int c = 0; c < 4; c++)
#pragma unroll
            for (int j = 0; j < 4; j++)
                part[((cg * 4 + c) * 8 + bg * 4 + j) * 33 + ks] = acc[c][j];
        __syncthreads();

        const int t_real = dir ? (SS - 1 - s) : s;

        if (tid < 128) {
            float ssum = 0.f;
#pragma unroll
            for (int i = 0; i < 32; i++) ssum += part[tid * 33 + i];
            int col = tid >> 3, b = tid & 7;
            int gg = col >> 2, u = col & 3;
            ssum += xp[((long)(b * SS + t_real)) * G4 + gg * 512 + j0 + u];
            part[tid * 33 + 32] = ssum;
        }
        __syncthreads();

        if (tid < 32) {
            int u = tid >> 3, b = tid & 7;
            float ig = part[((0  + u) * 8 + b) * 33 + 32];
            float fg = part[((4  + u) * 8 + b) * 33 + 32];
            float og = part[((8  + u) * 8 + b) * 33 + 32];
            float gg = part[((12 + u) * 8 + b) * 33 + 32];
            float cp = cst[u * 8 + b];
            float hp = hsT[(j0 + u) * 9 + b];
            float cn = sigm(fg) * cp + sigm(ig) * tanhf(gg);
            float hn = sigm(og) * tanhf(cn);
            int active = t_real < len[b];
            float h = active ? hn : hp;
            float c = active ? cn : cp;
            cst[u * 8 + b] = c;
            __stcg(&hwr[(j0 + u) * 8 + b], h);
            hout[((long)(b * SS + t_real)) * HH + j0 + u] = h;
        }
        GRIDBAR();
    }
#undef GRIDBAR
}

// ---------------------------------------------------------------------------
// Host driver
// ---------------------------------------------------------------------------
extern "C" void kernel_launch(void* const* d_in, const int* in_sizes, int n_in,
                              void* d_out, int out_size) {
    const int*   x    = (const int*)  d_in[0];
    const float* emb  = (const float*)d_in[1];
    const float* Wf0  = (const float*)d_in[2];
    const float* bf0  = (const float*)d_in[3];
    const float* Wb0  = (const float*)d_in[4];
    const float* bb0  = (const float*)d_in[5];
    const float* Wf1  = (const float*)d_in[6];
    const float* bf1  = (const float*)d_in[7];
    const float* Wb1  = (const float*)d_in[8];
    const float* bb1  = (const float*)d_in[9];
    const float* h0f  = (const float*)d_in[10];
    const float* c0f  = (const float*)d_in[11];
    const float* h0b  = (const float*)d_in[12];
    const float* c0b  = (const float*)d_in[13];
    const float* Wq   = (const float*)d_in[14];
    const float* bq   = (const float*)d_in[15];
    const float* Wao  = (const float*)d_in[16];
    const float* bao  = (const float*)d_in[17];
    const float* ln1g = (const float*)d_in[18];
    const float* ln1b = (const float*)d_in[19];
    const float* Wh   = (const float*)d_in[20];
    const float* bh   = (const float*)d_in[21];
    const float* ln2g = (const float*)d_in[22];
    const float* ln2b = (const float*)d_in[23];
    const float* Wp   = (const float*)d_in[24];
    const float* ob   = (const float*)d_in[25];
    float* out = (float*)d_out;

    float *embx, *xf, *xb, *hf, *hb, *lay, *query, *scores, *ctx, *pre, *ref,
          *hpre, *hcur;
    __nv_bfloat16 *ahi, *alo, *bhi, *blo, *hhi, *hlo, *wpthi, *wptlo;
    int* len;
    cudaGetSymbolAddress((void**)&embx,   g_embx);
    cudaGetSymbolAddress((void**)&xf,     g_xf);
    cudaGetSymbolAddress((void**)&xb,     g_xb);
    cudaGetSymbolAddress((void**)&hf,     g_hf);
    cudaGetSymbolAddress((void**)&hb,     g_hb);
    cudaGetSymbolAddress((void**)&lay,    g_lay);
    cudaGetSymbolAddress((void**)&query,  g_query);
    cudaGetSymbolAddress((void**)&scores, g_scores);
    cudaGetSymbolAddress((void**)&ctx,    g_ctx);
    cudaGetSymbolAddress((void**)&pre,    g_pre);
    cudaGetSymbolAddress((void**)&ref,    g_ref);
    cudaGetSymbolAddress((void**)&hpre,   g_hpre);
    cudaGetSymbolAddress((void**)&hcur,   g_hcur);
    cudaGetSymbolAddress((void**)&len,    g_len);
    cudaGetSymbolAddress((void**)&ahi,    g_ahi);
    cudaGetSymbolAddress((void**)&alo,    g_alo);
    cudaGetSymbolAddress((void**)&bhi,    g_bhi);
    cudaGetSymbolAddress((void**)&blo,    g_blo);
    cudaGetSymbolAddress((void**)&hhi,    g_hhi);
    cudaGetSymbolAddress((void**)&hlo,    g_hlo);
    cudaGetSymbolAddress((void**)&wpthi,  g_wpthi);
    cudaGetSymbolAddress((void**)&wptlo,  g_wptlo);

    const int lstm_smem = LSTM_SMEM_FLOATS * 4;
    cudaFuncSetAttribute(lstm_scan, cudaFuncAttributeMaxDynamicSharedMemorySize,
                         lstm_smem);

    len_kernel<<<BB, 512>>>(x, len);
    embed_kernel<<<NROW, 128>>>(x, emb, embx);
    // Wp split (independent, large — launch early)
    wt_split<<<dim3(VV / 32, HH / 32), dim3(32, 8)>>>(Wp, VV, HH, wpthi, wptlo);

    // ---- layer 0 projections (tensor path) ----
    split_f32<<<(NROW * EE / 4 + 255) / 256, 256>>>(embx, ahi, alo, NROW * EE / 4);
    wt_split<<<dim3(G4 / 32, EE / 32), dim3(32, 8)>>>(Wf0, G4, EE, bhi, blo);
    hgemm<<<dim3(NROW / 128, G4 / 128), 256>>>(ahi, alo, bhi, blo, bf0, xf, G4, EE, 0);
    wt_split<<<dim3(G4 / 32, EE / 32), dim3(32, 8)>>>(Wb0, G4, EE, bhi, blo);
    hgemm<<<dim3(NROW / 128, G4 / 128), 256>>>(ahi, alo, bhi, blo, bb0, xb, G4, EE, 0);

    reset_bar<<<1, 1>>>();
    lstm_scan<<<256, 256, lstm_smem>>>(xf, xb,
                                       Wf0 + (long)EE * G4, Wb0 + (long)EE * G4,
                                       h0f, c0f, h0b, c0b, hf, hb, hcur, len);
    build_lay<<<NROW, 256>>>(hf, hb, len, lay);

    // ---- layer 1 projections ----
    split_f32<<<(NROW * D2 / 4 + 255) / 256, 256>>>(lay, ahi, alo, NROW * D2 / 4);
    wt_split<<<dim3(G4 / 32, D2 / 32), dim3(32, 8)>>>(Wf1, G4, D2, bhi, blo);
    hgemm<<<dim3(NROW / 128, G4 / 128), 256>>>(ahi, alo, bhi, blo, bf1, xf, G4, D2, 0);
    wt_split<<<dim3(G4 / 32, D2 / 32), dim3(32, 8)>>>(Wb1, G4, D2, bhi, blo);
    hgemm<<<dim3(NROW / 128, G4 / 128), 256>>>(ahi, alo, bhi, blo, bb1, xb, G4, D2, 0);

    reset_bar<<<1, 1>>>();
    lstm_scan<<<256, 256, lstm_smem>>>(xf, xb,
                                       Wf1 + (long)D2 * G4, Wb1 + (long)D2 * G4,
                                       h0f + HH, c0f + HH, h0b + HH, c0b + HH,
                                       hf, hb, hcur, len);
    build_lay<<<NROW, 256>>>(hf, hb, len, lay);  // lay = encoded

    // ---- attention ----
    split_f32<<<(NROW * D2 / 4 + 255) / 256, 256>>>(lay, ahi, alo, NROW * D2 / 4);
    wt_split<<<dim3(D2 / 32, D2 / 32), dim3(32, 8)>>>(Wq, D2, D2, bhi, blo);
    hgemm<<<dim3(NROW / 128, D2 / 128), 256>>>(ahi, alo, bhi, blo, bq, query, D2, D2, 0);
    {
        dim3 g(SS / 64, SS / 64, BB);
        gemm_nt_scores<<<g, 256>>>(query, lay, scores);
    }
    {
        dim3 g(SS, BB, 1);
        softmax_kernel<<<g, 256>>>(scores, len);
    }
    {
        dim3 g(D2 / 128, SS / 128, BB);
        gemm_ctx<<<g, 256>>>(scores, lay, ctx);
    }
    // refined pre-activation: enc@Wao[:D2] + ctx@Wao[D2:] + bao
    wt_split<<<dim3(D2 / 32, D2 / 32), dim3(32, 8)>>>(Wao, D2, D2, bhi, blo);
    hgemm<<<dim3(NROW / 128, D2 / 128), 256>>>(ahi, alo, bhi, blo, bao, pre, D2, D2, 0);
    split_f32<<<(NROW * D2 / 4 + 255) / 256, 256>>>(ctx, ahi, alo, NROW * D2 / 4);
    wt_split<<<dim3(D2 / 32, D2 / 32), dim3(32, 8)>>>(Wao + (long)D2 * D2, D2, D2,
                                                      bhi, blo);
    hgemm<<<dim3(NROW / 128, D2 / 128), 256>>>(ahi, alo, bhi, blo, nullptr, pre,
                                               D2, D2, 1);
    refine_ln<<<NROW, 256>>>(lay, pre, ln1g, ln1b, len, ref);

    // ---- head ----
    split_f32<<<(NROW * D2 / 4 + 255) / 256, 256>>>(ref, ahi, alo, NROW * D2 / 4);
    wt_split<<<dim3(HH / 32, D2 / 32), dim3(32, 8)>>>(Wh, HH, D2, bhi, blo);
    hgemm<<<dim3(NROW / 128, HH / 128), 256>>>(ahi, alo, bhi, blo, bh, hpre, HH, D2, 0);
    head_ln<<<NROW, 256>>>(hpre, ln2g, ln2b, hhi, hlo);

    // ---- vocab projection ----
    hgemm<<<dim3(NROW / 128, VV / 128), 256>>>(hhi, hlo, wpthi, wptlo, ob, out,
                                               VV, HH, 0);
}

// round 11
// speedup vs baseline: 1.4724x; 1.0504x over previous
#include <cuda_runtime.h>
#include <cuda_bf16.h>
#include <math.h>
#include <stdint.h>

// ---------------------------------------------------------------------------
// Problem constants: V=32000, E=512, H=512, L=2, B=8, S=512
// ---------------------------------------------------------------------------
#define SS   512
#define BB   8
#define EE   512
#define HH   512
#define D2   1024      // 2H
#define G4   2048      // 4H
#define VV   32000
#define NROW 4096      // B*S

// ---------------------------------------------------------------------------
// Device scratch (no cudaMalloc allowed)
// ---------------------------------------------------------------------------
__device__ float g_embx  [NROW * EE];
__device__ float g_xf    [NROW * G4];
__device__ float g_xb    [NROW * G4];
__device__ float g_hf    [NROW * HH];
__device__ float g_hb    [NROW * HH];
__device__ float g_lay   [NROW * D2];
__device__ float g_query [NROW * D2];
__device__ float g_scores[BB * SS * SS];
__device__ float g_ctx   [NROW * D2];
__device__ float g_pre   [NROW * D2];
__device__ float g_ref   [NROW * D2];
__device__ float g_hpre  [NROW * HH];
__device__ float g_hcur  [2 * 2 * BB * HH];
__device__ int   g_len   [BB];
__device__ unsigned g_barcnt;

// bf16 split operand buffers (A-side and B-side, both 4M elements)
__device__ __nv_bfloat16 g_ahi  [NROW * D2];
__device__ __nv_bfloat16 g_alo  [NROW * D2];
__device__ __nv_bfloat16 g_bhi  [NROW * D2];
__device__ __nv_bfloat16 g_blo  [NROW * D2];
__device__ __nv_bfloat16 g_hhi  [NROW * HH];
__device__ __nv_bfloat16 g_hlo  [NROW * HH];
__device__ __nv_bfloat16 g_wpthi[(long)VV * HH];
__device__ __nv_bfloat16 g_wptlo[(long)VV * HH];

__device__ __forceinline__ float sigm(float x) { return 1.f / (1.f + expf(-x)); }

__device__ __forceinline__ uint32_t smem_u32(const void* p) {
    uint32_t a;
    asm("{ .reg .u64 t; cvta.to.shared.u64 t, %1; cvt.u32.u64 %0, t; }"
        : "=r"(a) : "l"(p));
    return a;
}

__device__ __forceinline__ void mma_bf16(float* c, const uint32_t* a,
                                         const uint32_t* b) {
    asm volatile(
        "mma.sync.aligned.m16n8k16.row.col.f32.bf16.bf16.f32 "
        "{%0,%1,%2,%3}, {%4,%5,%6,%7}, {%8,%9}, {%0,%1,%2,%3};"
        : "+f"(c[0]), "+f"(c[1]), "+f"(c[2]), "+f"(c[3])
        : "r"(a[0]), "r"(a[1]), "r"(a[2]), "r"(a[3]), "r"(b[0]), "r"(b[1]));
}

__device__ __forceinline__ void ldsm_x4(uint32_t& r0, uint32_t& r1,
                                        uint32_t& r2, uint32_t& r3,
                                        uint32_t addr) {
    asm volatile("ldmatrix.sync.aligned.m8n8.x4.shared.b16 {%0,%1,%2,%3}, [%4];"
                 : "=r"(r0), "=r"(r1), "=r"(r2), "=r"(r3) : "r"(addr));
}

#define CP_ASYNC16(dst, src) \
    asm volatile("cp.async.cg.shared.global [%0], [%1], 16;" \
                 :: "r"(dst), "l"(src) : "memory")
#define CP_COMMIT() asm volatile("cp.async.commit_group;" ::: "memory")
#define CP_WAIT0()  asm volatile("cp.async.wait_group 0;" ::: "memory")
#define CP_WAIT1()  asm volatile("cp.async.wait_group 1;" ::: "memory")

// ---------------------------------------------------------------------------
// lengths per batch
// ---------------------------------------------------------------------------
__global__ void len_kernel(const int* __restrict__ x, int* __restrict__ len) {
    __shared__ int red[512];
    int b = blockIdx.x, tid = threadIdx.x;
    red[tid] = (x[b * SS + tid] != 0) ? 1 : 0;
    __syncthreads();
    for (int s = 256; s > 0; s >>= 1) {
        if (tid < s) red[tid] += red[tid + s];
        __syncthreads();
    }
    if (tid == 0) len[b] = red[0];
}

// ---------------------------------------------------------------------------
// embedding gather
// ---------------------------------------------------------------------------
__global__ void embed_kernel(const int* __restrict__ x, const float* __restrict__ emb,
                             float* __restrict__ out) {
    int r = blockIdx.x;
    long tok = (long)x[r];
    float4 v = ((const float4*)(emb + tok * EE))[threadIdx.x];
    ((float4*)(out + (long)r * EE))[threadIdx.x] = v;
}

// ---------------------------------------------------------------------------
// split fp32 -> bf16 hi/lo
// ---------------------------------------------------------------------------
__global__ void split_f32(const float* __restrict__ in,
                          __nv_bfloat16* __restrict__ hi,
                          __nv_bfloat16* __restrict__ lo, int n4) {
    int i = blockIdx.x * blockDim.x + threadIdx.x;
    if (i >= n4) return;
    float4 v = ((const float4*)in)[i];
    __nv_bfloat16 h0 = __float2bfloat16(v.x);
    __nv_bfloat16 h1 = __float2bfloat16(v.y);
    __nv_bfloat16 h2 = __float2bfloat16(v.z);
    __nv_bfloat16 h3 = __float2bfloat16(v.w);
    __nv_bfloat162 ph0 = {h0, h1}, ph1 = {h2, h3};
    __nv_bfloat162 pl0 = {__float2bfloat16(v.x - __bfloat162float(h0)),
                          __float2bfloat16(v.y - __bfloat162float(h1))};
    __nv_bfloat162 pl1 = {__float2bfloat16(v.z - __bfloat162float(h2)),
                          __float2bfloat16(v.w - __bfloat162float(h3))};
    ((__nv_bfloat162*)hi)[i * 2]     = ph0;
    ((__nv_bfloat162*)hi)[i * 2 + 1] = ph1;
    ((__nv_bfloat162*)lo)[i * 2]     = pl0;
    ((__nv_bfloat162*)lo)[i * 2 + 1] = pl1;
}

// ---------------------------------------------------------------------------
// Transpose + split: W[K, N] (row stride ldw) -> T{hi,lo}[N][K]
// grid (N/32, K/32, batch), block (32, 8); strides in elements
// ---------------------------------------------------------------------------
__global__ void wt_split(const float* __restrict__ W, int ldw, int K,
                         __nv_bfloat16* __restrict__ Thi,
                         __nv_bfloat16* __restrict__ Tlo,
                         long strW, long strT) {
    __shared__ float tile[32][33];
    W   += (long)blockIdx.z * strW;
    Thi += (long)blockIdx.z * strT;
    Tlo += (long)blockIdx.z * strT;
    int n0 = blockIdx.x * 32, k0 = blockIdx.y * 32;
    int tx = threadIdx.x, ty = threadIdx.y;
#pragma unroll
    for (int i = 0; i < 4; i++)
        tile[ty + i * 8][tx] = W[(long)(k0 + ty + i * 8) * ldw + n0 + tx];
    __syncthreads();
#pragma unroll
    for (int i = 0; i < 4; i++) {
        int n = n0 + ty + i * 8, k = k0 + tx;
        float v = tile[tx][ty + i * 8];
        __nv_bfloat16 hi = __float2bfloat16(v);
        float lo = v - __bfloat162float(hi);
        Thi[(long)n * K + k] = hi;
        Tlo[(long)n * K + k] = __float2bfloat16(lo);
    }
}

// ---------------------------------------------------------------------------
// Generic split-bf16 mma.sync GEMM, cp.async double-buffered.
// C[M,N] = scale*(Ahi/lo[M,K] @ B{hi,lo}[N,K]^T) + bias (+C if accum)
// CTA tile 128x128, K-slab 32, 8 warps (4m x 2n), warp tile 32x64.
// SMEM rows padded to 40 bf16 -> conflict-free ldmatrix.
// grid (M/128, N/128, batch); dynamic smem 81920 B.
// ---------------------------------------------------------------------------
#define WROW 40
#define HS_ARR   (128 * WROW)          // elements per array
#define HS_PERBUF (4 * HS_ARR)         // elements per buffer block
#define HGEMM_SMEM (2 * HS_PERBUF * 2) // bytes

__global__ __launch_bounds__(256) void hgemm(
    const __nv_bfloat16* __restrict__ Ahi, const __nv_bfloat16* __restrict__ Alo,
    const __nv_bfloat16* __restrict__ Bhi, const __nv_bfloat16* __restrict__ Blo,
    const float* __restrict__ bias, float* __restrict__ C,
    int N, int K, int ldc, float scale, int accum,
    long strA, long strB, long strC)
{
    extern __shared__ __nv_bfloat16 hs[];
    Ahi += (long)blockIdx.z * strA;  Alo += (long)blockIdx.z * strA;
    Bhi += (long)blockIdx.z * strB;  Blo += (long)blockIdx.z * strB;
    C   += (long)blockIdx.z * strC;

    const int tid  = threadIdx.x;
    const int warp = tid >> 5, lane = tid & 31;
    const int wm = (warp & 3) * 32;
    const int wn = (warp >> 2) * 64;
    const int m0 = blockIdx.x * 128, n0 = blockIdx.y * 128;
    const int nk = K >> 5;

    const int lr = tid >> 1;
    const int lu = (tid & 1) * 16;    // element offset within 32-elem slab row
    const __nv_bfloat16* gAhi = Ahi + (long)(m0 + lr) * K + lu;
    const __nv_bfloat16* gAlo = Alo + (long)(m0 + lr) * K + lu;
    const __nv_bfloat16* gBhi = Bhi + (long)(n0 + lr) * K + lu;
    const __nv_bfloat16* gBlo = Blo + (long)(n0 + lr) * K + lu;
    const uint32_t sbase = smem_u32(hs);
    const uint32_t so = (lr * WROW + lu) * 2;   // byte offset within array

    const int a_r = (lane & 15);
    const int a_c = (lane >> 4) << 3;
    const int b_r = ((lane >> 4) << 3) + (lane & 7);
    const int b_c = ((lane >> 3) & 1) << 3;

    float acc[16][4];
#pragma unroll
    for (int i = 0; i < 16; i++)
#pragma unroll
        for (int j = 0; j < 4; j++) acc[i][j] = 0.f;

    // --- async loader for one K-slab into buffer buf ---
#define ISSUE(kb, buf)                                                       \
    do {                                                                     \
        const int _ko = (kb) * 32;                                           \
        uint32_t _d = sbase + (uint32_t)(buf) * (HS_PERBUF * 2) + so;        \
        CP_ASYNC16(_d,                  gAhi + _ko);                         \
        CP_ASYNC16(_d + 16,             gAhi + _ko + 8);                     \
        CP_ASYNC16(_d + HS_ARR * 2,     gAlo + _ko);                         \
        CP_ASYNC16(_d + HS_ARR * 2 + 16, gAlo + _ko + 8);                    \
        CP_ASYNC16(_d + HS_ARR * 4,     gBhi + _ko);                         \
        CP_ASYNC16(_d + HS_ARR * 4 + 16, gBhi + _ko + 8);                    \
        CP_ASYNC16(_d + HS_ARR * 6,     gBlo + _ko);                         \
        CP_ASYNC16(_d + HS_ARR * 6 + 16, gBlo + _ko + 8);                    \
    } while (0)

    ISSUE(0, 0);
    CP_COMMIT();

    for (int kb = 0; kb < nk; kb++) {
        if (kb + 1 < nk) {
            ISSUE(kb + 1, (kb + 1) & 1);
            CP_COMMIT();
            CP_WAIT1();
        } else {
            CP_WAIT0();
        }
        __syncthreads();

        const uint32_t bufb = sbase + (uint32_t)(kb & 1) * (HS_PERBUF * 2);
#pragma unroll
        for (int kh = 0; kh < 32; kh += 16) {
            uint32_t ah[2][4], al[2][4];
#pragma unroll
            for (int mt = 0; mt < 2; mt++) {
                uint32_t off = bufb + ((wm + mt * 16 + a_r) * WROW + kh + a_c) * 2;
                ldsm_x4(ah[mt][0], ah[mt][1], ah[mt][2], ah[mt][3], off);
                ldsm_x4(al[mt][0], al[mt][1], al[mt][2], al[mt][3],
                        off + HS_ARR * 2);
            }
            uint32_t bh[8][2], bl[8][2];
#pragma unroll
            for (int p = 0; p < 4; p++) {
                uint32_t off = bufb + HS_ARR * 4 +
                               ((wn + p * 16 + b_r) * WROW + kh + b_c) * 2;
                ldsm_x4(bh[p * 2][0], bh[p * 2][1], bh[p * 2 + 1][0],
                        bh[p * 2 + 1][1], off);
                ldsm_x4(bl[p * 2][0], bl[p * 2][1], bl[p * 2 + 1][0],
                        bl[p * 2 + 1][1], off + HS_ARR * 2);
            }
#pragma unroll
            for (int mt = 0; mt < 2; mt++)
#pragma unroll
                for (int nt = 0; nt < 8; nt++) {
                    float* c = acc[mt * 8 + nt];
                    mma_bf16(c, ah[mt], bh[nt]);
                    mma_bf16(c, ah[mt], bl[nt]);
                    mma_bf16(c, al[mt], bh[nt]);
                }
        }
        __syncthreads();
    }
#undef ISSUE

    const int g  = lane >> 2;
    const int c2 = (lane & 3) * 2;
#pragma unroll
    for (int nt = 0; nt < 8; nt++) {
        const int col = n0 + wn + nt * 8 + c2;
        float b0 = 0.f, b1 = 0.f;
        if (bias) { b0 = bias[col]; b1 = bias[col + 1]; }
#pragma unroll
        for (int mt = 0; mt < 2; mt++) {
            const float* c = acc[mt * 8 + nt];
            const int r0 = m0 + wm + mt * 16 + g;
            long o0 = (long)r0 * ldc + col;
            long o1 = (long)(r0 + 8) * ldc + col;
            float2 v0 = make_float2(c[0] * scale + b0, c[1] * scale + b1);
            float2 v1 = make_float2(c[2] * scale + b0, c[3] * scale + b1);
            if (accum) {
                float2 e0 = *(const float2*)(C + o0);
                float2 e1 = *(const float2*)(C + o1);
                v0.x += e0.x; v0.y += e0.y; v1.x += e1.x; v1.y += e1.y;
            }
            *(float2*)(C + o0) = v0;
            *(float2*)(C + o1) = v1;
        }
    }
}

// ---------------------------------------------------------------------------
// Masked softmax per (b, q) row
// ---------------------------------------------------------------------------
__global__ void softmax_kernel(float* __restrict__ sc, const int* __restrict__ len) {
    const int q = blockIdx.x, b = blockIdx.y;
    float* row = sc + ((long)b * SS + q) * SS;
    const int L = len[b];
    const int t = threadIdx.x;
    __shared__ float red[256];
    if (q >= L) {
        for (int i = t; i < SS; i += 256) row[i] = 0.f;
        return;
    }
    float m = -3.402823466e38f;
    for (int i = t; i < L; i += 256) m = fmaxf(m, row[i]);
    red[t] = m; __syncthreads();
    for (int s = 128; s > 0; s >>= 1) {
        if (t < s) red[t] = fmaxf(red[t], red[t + s]);
        __syncthreads();
    }
    m = red[0]; __syncthreads();
    float sum = 0.f;
    for (int i = t; i < L; i += 256) sum += expf(row[i] - m);
    red[t] = sum; __syncthreads();
    for (int s = 128; s > 0; s >>= 1) {
        if (t < s) red[t] += red[t + s];
        __syncthreads();
    }
    float inv = 1.f / red[0];
    for (int i = t; i < SS; i += 256)
        row[i] = (i < L) ? expf(row[i] - m) * inv : 0.f;
}

// ---------------------------------------------------------------------------
// Build layer input
// ---------------------------------------------------------------------------
__global__ void build_lay(const float* __restrict__ hf, const float* __restrict__ hb,
                          const int* __restrict__ len, float* __restrict__ lay) {
    int r = blockIdx.x;
    int b = r >> 9, tt = r & 511;
    int active = tt < len[b];
    int t = threadIdx.x;
    for (int i = t; i < D2; i += 256) {
        float v = 0.f;
        if (active) v = (i < HH) ? hf[(long)r * HH + i] : hb[(long)r * HH + i - HH];
        lay[(long)r * D2 + i] = v;
    }
}

// ---------------------------------------------------------------------------
// refined = LN(encoded + tanh(pre)) masked by valid
// ---------------------------------------------------------------------------
__global__ void refine_ln(const float* __restrict__ enc, const float* __restrict__ pre,
                          const float* __restrict__ g, const float* __restrict__ bta,
                          const int* __restrict__ len, float* __restrict__ out) {
    int r = blockIdx.x;
    int b = r >> 9, tt = r & 511;
    int t = threadIdx.x;
    __shared__ float r1[256], r2[256];
    float v[4];
    float s = 0.f, s2 = 0.f;
#pragma unroll
    for (int i = 0; i < 4; i++) {
        int idx = t + i * 256;
        float xx = enc[(long)r * D2 + idx] + tanhf(pre[(long)r * D2 + idx]);
        v[i] = xx; s += xx; s2 += xx * xx;
    }
    r1[t] = s; r2[t] = s2; __syncthreads();
    for (int st = 128; st > 0; st >>= 1) {
        if (t < st) { r1[t] += r1[t + st]; r2[t] += r2[t + st]; }
        __syncthreads();
    }
    float mean = r1[0] * (1.f / 1024.f);
    float var = r2[0] * (1.f / 1024.f) - mean * mean;
    float inv = rsqrtf(var + 1e-5f);
    int active = tt < len[b];
#pragma unroll
    for (int i = 0; i < 4; i++) {
        int idx = t + i * 256;
        float o = (v[i] - mean) * inv * g[idx] + bta[idx];
        out[(long)r * D2 + idx] = active ? o : 0.f;
    }
}

// ---------------------------------------------------------------------------
// head = LN(gelu_exact(hpre)) -> emit bf16 hi/lo split
// ---------------------------------------------------------------------------
__global__ void head_ln(const float* __restrict__ hpre, const float* __restrict__ g,
                        const float* __restrict__ bta,
                        __nv_bfloat16* __restrict__ hhi,
                        __nv_bfloat16* __restrict__ hlo) {
    int r = blockIdx.x;
    int t = threadIdx.x;
    __shared__ float r1[256], r2[256];
    float v[2];
    float s = 0.f, s2 = 0.f;
#pragma unroll
    for (int i = 0; i < 2; i++) {
        int idx = t + i * 256;
        float xx = hpre[(long)r * HH + idx];
        float ge = 0.5f * xx * (1.f + erff(xx * 0.70710678118654752f));
        v[i] = ge; s += ge; s2 += ge * ge;
    }
    r1[t] = s; r2[t] = s2; __syncthreads();
    for (int st = 128; st > 0; st >>= 1) {
        if (t < st) { r1[t] += r1[t + st]; r2[t] += r2[t + st]; }
        __syncthreads();
    }
    float mean = r1[0] * (1.f / 512.f);
    float var = r2[0] * (1.f / 512.f) - mean * mean;
    float inv = rsqrtf(var + 1e-5f);
#pragma unroll
    for (int i = 0; i < 2; i++) {
        int idx = t + i * 256;
        float o = (v[i] - mean) * inv * g[idx] + bta[idx];
        __nv_bfloat16 hi = __float2bfloat16(o);
        float lo = o - __bfloat162float(hi);
        hhi[(long)r * HH + idx] = hi;
        hlo[(long)r * HH + idx] = __float2bfloat16(lo);
    }
}

// ---------------------------------------------------------------------------
// Reset grid barrier counter
// ---------------------------------------------------------------------------
__global__ void reset_bar() { g_barcnt = 0u; }

// ---------------------------------------------------------------------------
// Persistent BiLSTM scan (unchanged from passing version).
// ---------------------------------------------------------------------------
#define LSTM_SMEM_FLOATS (16 * 512 + 512 * 9 + 128 * 33 + 32)

__global__ __launch_bounds__(256, 2) void lstm_scan(
    const float* __restrict__ xf, const float* __restrict__ xb,
    const float* __restrict__ Wrf, const float* __restrict__ Wrb,
    const float* __restrict__ h0f, const float* __restrict__ c0f,
    const float* __restrict__ h0b, const float* __restrict__ c0b,
    float* __restrict__ houtf, float* __restrict__ houtb,
    float* __restrict__ hcur, const int* __restrict__ len)
{
    extern __shared__ float sm[];
    float* Ws   = sm;
    float* hsT  = sm + 16 * 512;
    float* part = hsT + 512 * 9;
    float* cst  = part + 128 * 33;

    const int tid = threadIdx.x;
    const int dir = blockIdx.x >> 7;
    const int kb  = blockIdx.x & 127;
    const int j0  = kb * 4;
    const float* Wr = dir ? Wrb : Wrf;
    const float* xp = dir ? xb : xf;
    const float* h0 = dir ? h0b : h0f;
    const float* c0 = dir ? c0b : c0f;
    float* hout  = dir ? houtb : houtf;
    float* hbase = hcur + dir * (2 * BB * HH);

    {
        int col = tid & 15;
        int gcol = (col >> 2) * 512 + j0 + (col & 3);
        for (int k = tid >> 4; k < 512; k += 16)
            Ws[col * 512 + k] = Wr[(long)k * G4 + gcol];
    }
    if (tid < 32) {
        int u = tid >> 3, b = tid & 7;
        cst[u * 8 + b] = c0[j0 + u];
        __stcg(&hbase[(j0 + u) * 8 + b], h0[j0 + u]);
    }

    const int ks = tid & 31;
    const int bg = (tid >> 5) & 1;
    const int cg = tid >> 6;
    unsigned phase = 1;

#define GRIDBAR()                                                         \
    do {                                                                  \
        __syncthreads();                                                  \
        if (tid == 0) {                                                   \
            __threadfence();                                              \
            atomicAdd(&g_barcnt, 1u);                                     \
            unsigned tgt = 256u * phase;                                  \
            while (*(volatile unsigned*)&g_barcnt < tgt) {}               \
        }                                                                 \
        __syncthreads();                                                  \
        phase++;                                                          \
    } while (0)

    GRIDBAR();

    for (int s = 0; s < SS; s++) {
        const float* hrd = hbase + (s & 1) * (BB * HH);
        float* hwr = hbase + ((s + 1) & 1) * (BB * HH);

        for (int f = tid; f < BB * HH; f += 256)
            hsT[(f >> 3) * 9 + (f & 7)] = __ldcg(hrd + f);
        __syncthreads();

        float acc[4][4];
#pragma unroll
        for (int c = 0; c < 4; c++)
#pragma unroll
            for (int j = 0; j < 4; j++) acc[c][j] = 0.f;

#pragma unroll 4
        for (int i = 0; i < 16; i++) {
            int k = ks + 32 * i;
            float h0v = hsT[k * 9 + bg * 4 + 0];
            float h1v = hsT[k * 9 + bg * 4 + 1];
            float h2v = hsT[k * 9 + bg * 4 + 2];
            float h3v = hsT[k * 9 + bg * 4 + 3];
#pragma unroll
            for (int c = 0; c < 4; c++) {
                float w = Ws[(cg * 4 + c) * 512 + k];
                acc[c][0] = fmaf(w, h0v, acc[c][0]);
                acc[c][1] = fmaf(w, h1v, acc[c][1]);
                acc[c][2] = fmaf(w, h2v, acc[c][2]);
                acc[c][3] = fmaf(w, h3v, acc[c][3]);
            }
        }
#pragma unroll
        for (int c = 0; c < 4; c++)
#pragma unroll
            for (int j = 0; j < 4; j++)
                part[((cg * 4 + c) * 8 + bg * 4 + j) * 33 + ks] = acc[c][j];
        __syncthreads();

        const int t_real = dir ? (SS - 1 - s) : s;

        if (tid < 128) {
            float ssum = 0.f;
#pragma unroll
            for (int i = 0; i < 32; i++) ssum += part[tid * 33 + i];
            int col = tid >> 3, b = tid & 7;
            int gg = col >> 2, u = col & 3;
            ssum += xp[((long)(b * SS + t_real)) * G4 + gg * 512 + j0 + u];
            part[tid * 33 + 32] = ssum;
        }
        __syncthreads();

        if (tid < 32) {
            int u = tid >> 3, b = tid & 7;
            float ig = part[((0  + u) * 8 + b) * 33 + 32];
            float fg = part[((4  + u) * 8 + b) * 33 + 32];
            float og = part[((8  + u) * 8 + b) * 33 + 32];
            float gg = part[((12 + u) * 8 + b) * 33 + 32];
            float cp = cst[u * 8 + b];
            float hp = hsT[(j0 + u) * 9 + b];
            float cn = sigm(fg) * cp + sigm(ig) * tanhf(gg);
            float hn = sigm(og) * tanhf(cn);
            int active = t_real < len[b];
            float h = active ? hn : hp;
            float c = active ? cn : cp;
            cst[u * 8 + b] = c;
            __stcg(&hwr[(j0 + u) * 8 + b], h);
            hout[((long)(b * SS + t_real)) * HH + j0 + u] = h;
        }
        GRIDBAR();
    }
#undef GRIDBAR
}

// ---------------------------------------------------------------------------
// Host driver
// ---------------------------------------------------------------------------
extern "C" void kernel_launch(void* const* d_in, const int* in_sizes, int n_in,
                              void* d_out, int out_size) {
    const int*   x    = (const int*)  d_in[0];
    const float* emb  = (const float*)d_in[1];
    const float* Wf0  = (const float*)d_in[2];
    const float* bf0  = (const float*)d_in[3];
    const float* Wb0  = (const float*)d_in[4];
    const float* bb0  = (const float*)d_in[5];
    const float* Wf1  = (const float*)d_in[6];
    const float* bf1  = (const float*)d_in[7];
    const float* Wb1  = (const float*)d_in[8];
    const float* bb1  = (const float*)d_in[9];
    const float* h0f  = (const float*)d_in[10];
    const float* c0f  = (const float*)d_in[11];
    const float* h0b  = (const float*)d_in[12];
    const float* c0b  = (const float*)d_in[13];
    const float* Wq   = (const float*)d_in[14];
    const float* bq   = (const float*)d_in[15];
    const float* Wao  = (const float*)d_in[16];
    const float* bao  = (const float*)d_in[17];
    const float* ln1g = (const float*)d_in[18];
    const float* ln1b = (const float*)d_in[19];
    const float* Wh   = (const float*)d_in[20];
    const float* bh   = (const float*)d_in[21];
    const float* ln2g = (const float*)d_in[22];
    const float* ln2b = (const float*)d_in[23];
    const float* Wp   = (const float*)d_in[24];
    const float* ob   = (const float*)d_in[25];
    float* out = (float*)d_out;

    float *embx, *xf, *xb, *hf, *hb, *lay, *query, *scores, *ctx, *pre, *ref,
          *hpre, *hcur;
    __nv_bfloat16 *ahi, *alo, *bhi, *blo, *hhi, *hlo, *wpthi, *wptlo;
    int* len;
    cudaGetSymbolAddress((void**)&embx,   g_embx);
    cudaGetSymbolAddress((void**)&xf,     g_xf);
    cudaGetSymbolAddress((void**)&xb,     g_xb);
    cudaGetSymbolAddress((void**)&hf,     g_hf);
    cudaGetSymbolAddress((void**)&hb,     g_hb);
    cudaGetSymbolAddress((void**)&lay,    g_lay);
    cudaGetSymbolAddress((void**)&query,  g_query);
    cudaGetSymbolAddress((void**)&scores, g_scores);
    cudaGetSymbolAddress((void**)&ctx,    g_ctx);
    cudaGetSymbolAddress((void**)&pre,    g_pre);
    cudaGetSymbolAddress((void**)&ref,    g_ref);
    cudaGetSymbolAddress((void**)&hpre,   g_hpre);
    cudaGetSymbolAddress((void**)&hcur,   g_hcur);
    cudaGetSymbolAddress((void**)&len,    g_len);
    cudaGetSymbolAddress((void**)&ahi,    g_ahi);
    cudaGetSymbolAddress((void**)&alo,    g_alo);
    cudaGetSymbolAddress((void**)&bhi,    g_bhi);
    cudaGetSymbolAddress((void**)&blo,    g_blo);
    cudaGetSymbolAddress((void**)&hhi,    g_hhi);
    cudaGetSymbolAddress((void**)&hlo,    g_hlo);
    cudaGetSymbolAddress((void**)&wpthi,  g_wpthi);
    cudaGetSymbolAddress((void**)&wptlo,  g_wptlo);

    const int lstm_smem = LSTM_SMEM_FLOATS * 4;
    cudaFuncSetAttribute(lstm_scan, cudaFuncAttributeMaxDynamicSharedMemorySize,
                         lstm_smem);
    cudaFuncSetAttribute(hgemm, cudaFuncAttributeMaxDynamicSharedMemorySize,
                         HGEMM_SMEM);

    len_kernel<<<BB, 512>>>(x, len);
    embed_kernel<<<NROW, 128>>>(x, emb, embx);
    wt_split<<<dim3(VV / 32, HH / 32), dim3(32, 8)>>>(Wp, VV, HH, wpthi, wptlo, 0, 0);

    // ---- layer 0 projections ----
    split_f32<<<(NROW * EE / 4 + 255) / 256, 256>>>(embx, ahi, alo, NROW * EE / 4);
    wt_split<<<dim3(G4 / 32, EE / 32), dim3(32, 8)>>>(Wf0, G4, EE, bhi, blo, 0, 0);
    hgemm<<<dim3(NROW / 128, G4 / 128), 256, HGEMM_SMEM>>>(
        ahi, alo, bhi, blo, bf0, xf, G4, EE, G4, 1.f, 0, 0, 0, 0);
    wt_split<<<dim3(G4 / 32, EE / 32), dim3(32, 8)>>>(Wb0, G4, EE, bhi, blo, 0, 0);
    hgemm<<<dim3(NROW / 128, G4 / 128), 256, HGEMM_SMEM>>>(
        ahi, alo, bhi, blo, bb0, xb, G4, EE, G4, 1.f, 0, 0, 0, 0);

    reset_bar<<<1, 1>>>();
    lstm_scan<<<256, 256, lstm_smem>>>(xf, xb,
                                       Wf0 + (long)EE * G4, Wb0 + (long)EE * G4,
                                       h0f, c0f, h0b, c0b, hf, hb, hcur, len);
    build_lay<<<NROW, 256>>>(hf, hb, len, lay);

    // ---- layer 1 projections ----
    split_f32<<<(NROW * D2 / 4 + 255) / 256, 256>>>(lay, ahi, alo, NROW * D2 / 4);
    wt_split<<<dim3(G4 / 32, D2 / 32), dim3(32, 8)>>>(Wf1, G4, D2, bhi, blo, 0, 0);
    hgemm<<<dim3(NROW / 128, G4 / 128), 256, HGEMM_SMEM>>>(
        ahi, alo, bhi, blo, bf1, xf, G4, D2, G4, 1.f, 0, 0, 0, 0);
    wt_split<<<dim3(G4 / 32, D2 / 32), dim3(32, 8)>>>(Wb1, G4, D2, bhi, blo, 0, 0);
    hgemm<<<dim3(NROW / 128, G4 / 128), 256, HGEMM_SMEM>>>(
        ahi, alo, bhi, blo, bb1, xb, G4, D2, G4, 1.f, 0, 0, 0, 0);

    reset_bar<<<1, 1>>>();
    lstm_scan<<<256, 256, lstm_smem>>>(xf, xb,
                                       Wf1 + (long)D2 * G4, Wb1 + (long)D2 * G4,
                                       h0f + HH, c0f + HH, h0b + HH, c0b + HH,
                                       hf, hb, hcur, len);
    build_lay<<<NROW, 256>>>(hf, hb, len, lay);  // lay = encoded

    // ---- attention ----
    // enc split -> (ahi, alo)
    split_f32<<<(NROW * D2 / 4 + 255) / 256, 256>>>(lay, ahi, alo, NROW * D2 / 4);
    // query = enc @ Wq + bq
    wt_split<<<dim3(D2 / 32, D2 / 32), dim3(32, 8)>>>(Wq, D2, D2, bhi, blo, 0, 0);
    hgemm<<<dim3(NROW / 128, D2 / 128), 256, HGEMM_SMEM>>>(
        ahi, alo, bhi, blo, bq, query, D2, D2, D2, 1.f, 0, 0, 0, 0);
    // scores[b] = scale * query[b] @ enc[b]^T  (B = enc rows, NT natural)
    split_f32<<<(NROW * D2 / 4 + 255) / 256, 256>>>(query, bhi, blo, NROW * D2 / 4);
    hgemm<<<dim3(SS / 128, SS / 128, BB), 256, HGEMM_SMEM>>>(
        bhi, blo, ahi, alo, nullptr, scores, SS, D2, SS, 0.03125f, 0,
        (long)SS * D2, (long)SS * D2, (long)SS * SS);
    softmax_kernel<<<dim3(SS, BB), 256>>>(scores, len);
    // ctx[b] = attn[b] @ enc[b] : B = enc^T per batch
    wt_split<<<dim3(D2 / 32, SS / 32, BB), dim3(32, 8)>>>(
        lay, D2, SS, bhi, blo, (long)SS * D2, (long)D2 * SS);
    split_f32<<<(BB * SS * SS / 4 + 255) / 256, 256>>>(scores, ahi, alo,
                                                       BB * SS * SS / 4);
    hgemm<<<dim3(SS / 128, D2 / 128, BB), 256, HGEMM_SMEM>>>(
        ahi, alo, bhi, blo, nullptr, ctx, D2, SS, D2, 1.f, 0,
        (long)SS * SS, (long)D2 * SS, (long)SS * D2);
    // pre = enc @ Wao[:D2] + ctx @ Wao[D2:] + bao
    split_f32<<<(NROW * D2 / 4 + 255) / 256, 256>>>(lay, ahi, alo, NROW * D2 / 4);
    wt_split<<<dim3(D2 / 32, D2 / 32), dim3(32, 8)>>>(Wao, D2, D2, bhi, blo, 0, 0);
    hgemm<<<dim3(NROW / 128, D2 / 128), 256, HGEMM_SMEM>>>(
        ahi, alo, bhi, blo, bao, pre, D2, D2, D2, 1.f, 0, 0, 0, 0);
    split_f32<<<(NROW * D2 / 4 + 255) / 256, 256>>>(ctx, ahi, alo, NROW * D2 / 4);
    wt_split<<<dim3(D2 / 32, D2 / 32), dim3(32, 8)>>>(Wao + (long)D2 * D2, D2, D2,
                                                      bhi, blo, 0, 0);
    hgemm<<<dim3(NROW / 128, D2 / 128), 256, HGEMM_SMEM>>>(
        ahi, alo, bhi, blo, nullptr, pre, D2, D2, D2, 1.f, 1, 0, 0, 0);
    refine_ln<<<NROW, 256>>>(lay, pre, ln1g, ln1b, len, ref);

    // ---- head ----
    split_f32<<<(NROW * D2 / 4 + 255) / 256, 256>>>(ref, ahi, alo, NROW * D2 / 4);
    wt_split<<<dim3(HH / 32, D2 / 32), dim3(32, 8)>>>(Wh, HH, D2, bhi, blo, 0, 0);
    hgemm<<<dim3(NROW / 128, HH / 128), 256, HGEMM_SMEM>>>(
        ahi, alo, bhi, blo, bh, hpre, HH, D2, HH, 1.f, 0, 0, 0, 0);
    head_ln<<<NROW, 256>>>(hpre, ln2g, ln2b, hhi, hlo);

    // ---- vocab projection ----
    hgemm<<<dim3(NROW / 128, VV / 128), 256, HGEMM_SMEM>>>(
        hhi, hlo, wpthi, wptlo, ob, out, VV, HH, VV, 1.f, 0, 0, 0, 0);
}

// round 12
// speedup vs baseline: 1.6512x; 1.1214x over previous
#include <cuda_runtime.h>
#include <cuda_bf16.h>
#include <math.h>
#include <stdint.h>

// ---------------------------------------------------------------------------
// Problem constants: V=32000, E=512, H=512, L=2, B=8, S=512
// ---------------------------------------------------------------------------
#define SS   512
#define BB   8
#define EE   512
#define HH   512
#define D2   1024      // 2H
#define G4   2048      // 4H
#define VV   32000
#define NROW 4096      // B*S

// ---------------------------------------------------------------------------
// Device scratch (no cudaMalloc allowed)
// ---------------------------------------------------------------------------
__device__ float g_embx  [NROW * EE];
__device__ float g_xf    [NROW * G4];
__device__ float g_xb    [NROW * G4];
__device__ float g_hf    [NROW * HH];
__device__ float g_hb    [NROW * HH];
__device__ float g_lay   [NROW * D2];
__device__ float g_query [NROW * D2];
__device__ float g_scores[BB * SS * SS];
__device__ float g_ctx   [NROW * D2];
__device__ float g_pre   [NROW * D2];
__device__ float g_ref   [NROW * D2];
__device__ float g_hpre  [NROW * HH];
__device__ float g_hcur  [2 * 2 * BB * HH];
__device__ int   g_len   [BB];
__device__ unsigned g_barcnt2[2];

// bf16 split operand buffers
__device__ __nv_bfloat16 g_ahi  [NROW * D2];
__device__ __nv_bfloat16 g_alo  [NROW * D2];
__device__ __nv_bfloat16 g_bhi  [NROW * D2];
__device__ __nv_bfloat16 g_blo  [NROW * D2];
__device__ __nv_bfloat16 g_hhi  [NROW * HH];
__device__ __nv_bfloat16 g_hlo  [NROW * HH];
__device__ __nv_bfloat16 g_wpthi[(long)VV * HH];
__device__ __nv_bfloat16 g_wptlo[(long)VV * HH];

__device__ __forceinline__ float sigm(float x) { return 1.f / (1.f + expf(-x)); }

__device__ __forceinline__ uint32_t smem_u32(const void* p) {
    uint32_t a;
    asm("{ .reg .u64 t; cvta.to.shared.u64 t, %1; cvt.u32.u64 %0, t; }"
        : "=r"(a) : "l"(p));
    return a;
}

__device__ __forceinline__ void mma_bf16(float* c, const uint32_t* a,
                                         const uint32_t* b) {
    asm volatile(
        "mma.sync.aligned.m16n8k16.row.col.f32.bf16.bf16.f32 "
        "{%0,%1,%2,%3}, {%4,%5,%6,%7}, {%8,%9}, {%0,%1,%2,%3};"
        : "+f"(c[0]), "+f"(c[1]), "+f"(c[2]), "+f"(c[3])
        : "r"(a[0]), "r"(a[1]), "r"(a[2]), "r"(a[3]), "r"(b[0]), "r"(b[1]));
}

__device__ __forceinline__ void ldsm_x4(uint32_t& r0, uint32_t& r1,
                                        uint32_t& r2, uint32_t& r3,
                                        uint32_t addr) {
    asm volatile("ldmatrix.sync.aligned.m8n8.x4.shared.b16 {%0,%1,%2,%3}, [%4];"
                 : "=r"(r0), "=r"(r1), "=r"(r2), "=r"(r3) : "r"(addr));
}

#define CP_ASYNC16(dst, src) \
    asm volatile("cp.async.cg.shared.global [%0], [%1], 16;" \
                 :: "r"(dst), "l"(src) : "memory")
#define CP_COMMIT() asm volatile("cp.async.commit_group;" ::: "memory")
#define CP_WAIT0()  asm volatile("cp.async.wait_group 0;" ::: "memory")
#define CP_WAIT1()  asm volatile("cp.async.wait_group 1;" ::: "memory")

// ---------------------------------------------------------------------------
// lengths per batch
// ---------------------------------------------------------------------------
__global__ void len_kernel(const int* __restrict__ x, int* __restrict__ len) {
    __shared__ int red[512];
    int b = blockIdx.x, tid = threadIdx.x;
    red[tid] = (x[b * SS + tid] != 0) ? 1 : 0;
    __syncthreads();
    for (int s = 256; s > 0; s >>= 1) {
        if (tid < s) red[tid] += red[tid + s];
        __syncthreads();
    }
    if (tid == 0) len[b] = red[0];
}

// ---------------------------------------------------------------------------
// embedding gather
// ---------------------------------------------------------------------------
__global__ void embed_kernel(const int* __restrict__ x, const float* __restrict__ emb,
                             float* __restrict__ out) {
    int r = blockIdx.x;
    long tok = (long)x[r];
    float4 v = ((const float4*)(emb + tok * EE))[threadIdx.x];
    ((float4*)(out + (long)r * EE))[threadIdx.x] = v;
}

// ---------------------------------------------------------------------------
// split fp32 -> bf16 hi/lo
// ---------------------------------------------------------------------------
__global__ void split_f32(const float* __restrict__ in,
                          __nv_bfloat16* __restrict__ hi,
                          __nv_bfloat16* __restrict__ lo, int n4) {
    int i = blockIdx.x * blockDim.x + threadIdx.x;
    if (i >= n4) return;
    float4 v = ((const float4*)in)[i];
    __nv_bfloat16 h0 = __float2bfloat16(v.x);
    __nv_bfloat16 h1 = __float2bfloat16(v.y);
    __nv_bfloat16 h2 = __float2bfloat16(v.z);
    __nv_bfloat16 h3 = __float2bfloat16(v.w);
    __nv_bfloat162 ph0 = {h0, h1}, ph1 = {h2, h3};
    __nv_bfloat162 pl0 = {__float2bfloat16(v.x - __bfloat162float(h0)),
                          __float2bfloat16(v.y - __bfloat162float(h1))};
    __nv_bfloat162 pl1 = {__float2bfloat16(v.z - __bfloat162float(h2)),
                          __float2bfloat16(v.w - __bfloat162float(h3))};
    ((__nv_bfloat162*)hi)[i * 2]     = ph0;
    ((__nv_bfloat162*)hi)[i * 2 + 1] = ph1;
    ((__nv_bfloat162*)lo)[i * 2]     = pl0;
    ((__nv_bfloat162*)lo)[i * 2 + 1] = pl1;
}

// ---------------------------------------------------------------------------
// Transpose + split: W[K, N] (row stride ldw) -> T{hi,lo}[N][K]
// ---------------------------------------------------------------------------
__global__ void wt_split(const float* __restrict__ W, int ldw, int K,
                         __nv_bfloat16* __restrict__ Thi,
                         __nv_bfloat16* __restrict__ Tlo,
                         long strW, long strT) {
    __shared__ float tile[32][33];
    W   += (long)blockIdx.z * strW;
    Thi += (long)blockIdx.z * strT;
    Tlo += (long)blockIdx.z * strT;
    int n0 = blockIdx.x * 32, k0 = blockIdx.y * 32;
    int tx = threadIdx.x, ty = threadIdx.y;
#pragma unroll
    for (int i = 0; i < 4; i++)
        tile[ty + i * 8][tx] = W[(long)(k0 + ty + i * 8) * ldw + n0 + tx];
    __syncthreads();
#pragma unroll
    for (int i = 0; i < 4; i++) {
        int n = n0 + ty + i * 8, k = k0 + tx;
        float v = tile[tx][ty + i * 8];
        __nv_bfloat16 hi = __float2bfloat16(v);
        float lo = v - __bfloat162float(hi);
        Thi[(long)n * K + k] = hi;
        Tlo[(long)n * K + k] = __float2bfloat16(lo);
    }
}

// ---------------------------------------------------------------------------
// Generic split-bf16 mma.sync GEMM, cp.async double-buffered (as R11).
// ---------------------------------------------------------------------------
#define WROW 40
#define HS_ARR   (128 * WROW)
#define HS_PERBUF (4 * HS_ARR)
#define HGEMM_SMEM (2 * HS_PERBUF * 2)

__global__ __launch_bounds__(256) void hgemm(
    const __nv_bfloat16* __restrict__ Ahi, const __nv_bfloat16* __restrict__ Alo,
    const __nv_bfloat16* __restrict__ Bhi, const __nv_bfloat16* __restrict__ Blo,
    const float* __restrict__ bias, float* __restrict__ C,
    int N, int K, int ldc, float scale, int accum,
    long strA, long strB, long strC)
{
    extern __shared__ __nv_bfloat16 hs[];
    Ahi += (long)blockIdx.z * strA;  Alo += (long)blockIdx.z * strA;
    Bhi += (long)blockIdx.z * strB;  Blo += (long)blockIdx.z * strB;
    C   += (long)blockIdx.z * strC;

    const int tid  = threadIdx.x;
    const int warp = tid >> 5, lane = tid & 31;
    const int wm = (warp & 3) * 32;
    const int wn = (warp >> 2) * 64;
    const int m0 = blockIdx.x * 128, n0 = blockIdx.y * 128;
    const int nk = K >> 5;

    const int lr = tid >> 1;
    const int lu = (tid & 1) * 16;
    const __nv_bfloat16* gAhi = Ahi + (long)(m0 + lr) * K + lu;
    const __nv_bfloat16* gAlo = Alo + (long)(m0 + lr) * K + lu;
    const __nv_bfloat16* gBhi = Bhi + (long)(n0 + lr) * K + lu;
    const __nv_bfloat16* gBlo = Blo + (long)(n0 + lr) * K + lu;
    const uint32_t sbase = smem_u32(hs);
    const uint32_t so = (lr * WROW + lu) * 2;

    const int a_r = (lane & 15);
    const int a_c = (lane >> 4) << 3;
    const int b_r = ((lane >> 4) << 3) + (lane & 7);
    const int b_c = ((lane >> 3) & 1) << 3;

    float acc[16][4];
#pragma unroll
    for (int i = 0; i < 16; i++)
#pragma unroll
        for (int j = 0; j < 4; j++) acc[i][j] = 0.f;

#define ISSUE(kb, buf)                                                       \
    do {                                                                     \
        const int _ko = (kb) * 32;                                           \
        uint32_t _d = sbase + (uint32_t)(buf) * (HS_PERBUF * 2) + so;        \
        CP_ASYNC16(_d,                  gAhi + _ko);                         \
        CP_ASYNC16(_d + 16,             gAhi + _ko + 8);                     \
        CP_ASYNC16(_d + HS_ARR * 2,     gAlo + _ko);                         \
        CP_ASYNC16(_d + HS_ARR * 2 + 16, gAlo + _ko + 8);                    \
        CP_ASYNC16(_d + HS_ARR * 4,     gBhi + _ko);                         \
        CP_ASYNC16(_d + HS_ARR * 4 + 16, gBhi + _ko + 8);                    \
        CP_ASYNC16(_d + HS_ARR * 6,     gBlo + _ko);                         \
        CP_ASYNC16(_d + HS_ARR * 6 + 16, gBlo + _ko + 8);                    \
    } while (0)

    ISSUE(0, 0);
    CP_COMMIT();

    for (int kb = 0; kb < nk; kb++) {
        if (kb + 1 < nk) {
            ISSUE(kb + 1, (kb + 1) & 1);
            CP_COMMIT();
            CP_WAIT1();
        } else {
            CP_WAIT0();
        }
        __syncthreads();

        const uint32_t bufb = sbase + (uint32_t)(kb & 1) * (HS_PERBUF * 2);
#pragma unroll
        for (int kh = 0; kh < 32; kh += 16) {
            uint32_t ah[2][4], al[2][4];
#pragma unroll
            for (int mt = 0; mt < 2; mt++) {
                uint32_t off = bufb + ((wm + mt * 16 + a_r) * WROW + kh + a_c) * 2;
                ldsm_x4(ah[mt][0], ah[mt][1], ah[mt][2], ah[mt][3], off);
                ldsm_x4(al[mt][0], al[mt][1], al[mt][2], al[mt][3],
                        off + HS_ARR * 2);
            }
            uint32_t bh[8][2], bl[8][2];
#pragma unroll
            for (int p = 0; p < 4; p++) {
                uint32_t off = bufb + HS_ARR * 4 +
                               ((wn + p * 16 + b_r) * WROW + kh + b_c) * 2;
                ldsm_x4(bh[p * 2][0], bh[p * 2][1], bh[p * 2 + 1][0],
                        bh[p * 2 + 1][1], off);
                ldsm_x4(bl[p * 2][0], bl[p * 2][1], bl[p * 2 + 1][0],
                        bl[p * 2 + 1][1], off + HS_ARR * 2);
            }
#pragma unroll
            for (int mt = 0; mt < 2; mt++)
#pragma unroll
                for (int nt = 0; nt < 8; nt++) {
                    float* c = acc[mt * 8 + nt];
                    mma_bf16(c, ah[mt], bh[nt]);
                    mma_bf16(c, ah[mt], bl[nt]);
                    mma_bf16(c, al[mt], bh[nt]);
                }
        }
        __syncthreads();
    }
#undef ISSUE

    const int g  = lane >> 2;
    const int c2 = (lane & 3) * 2;
#pragma unroll
    for (int nt = 0; nt < 8; nt++) {
        const int col = n0 + wn + nt * 8 + c2;
        float b0 = 0.f, b1 = 0.f;
        if (bias) { b0 = bias[col]; b1 = bias[col + 1]; }
#pragma unroll
        for (int mt = 0; mt < 2; mt++) {
            const float* c = acc[mt * 8 + nt];
            const int r0 = m0 + wm + mt * 16 + g;
            long o0 = (long)r0 * ldc + col;
            long o1 = (long)(r0 + 8) * ldc + col;
            float2 v0 = make_float2(c[0] * scale + b0, c[1] * scale + b1);
            float2 v1 = make_float2(c[2] * scale + b0, c[3] * scale + b1);
            if (accum) {
                float2 e0 = *(const float2*)(C + o0);
                float2 e1 = *(const float2*)(C + o1);
                v0.x += e0.x; v0.y += e0.y; v1.x += e1.x; v1.y += e1.y;
            }
            *(float2*)(C + o0) = v0;
            *(float2*)(C + o1) = v1;
        }
    }
}

// ---------------------------------------------------------------------------
// Masked softmax per (b, q) row
// ---------------------------------------------------------------------------
__global__ void softmax_kernel(float* __restrict__ sc, const int* __restrict__ len) {
    const int q = blockIdx.x, b = blockIdx.y;
    float* row = sc + ((long)b * SS + q) * SS;
    const int L = len[b];
    const int t = threadIdx.x;
    __shared__ float red[256];
    if (q >= L) {
        for (int i = t; i < SS; i += 256) row[i] = 0.f;
        return;
    }
    float m = -3.402823466e38f;
    for (int i = t; i < L; i += 256) m = fmaxf(m, row[i]);
    red[t] = m; __syncthreads();
    for (int s = 128; s > 0; s >>= 1) {
        if (t < s) red[t] = fmaxf(red[t], red[t + s]);
        __syncthreads();
    }
    m = red[0]; __syncthreads();
    float sum = 0.f;
    for (int i = t; i < L; i += 256) sum += expf(row[i] - m);
    red[t] = sum; __syncthreads();
    for (int s = 128; s > 0; s >>= 1) {
        if (t < s) red[t] += red[t + s];
        __syncthreads();
    }
    float inv = 1.f / red[0];
    for (int i = t; i < SS; i += 256)
        row[i] = (i < L) ? expf(row[i] - m) * inv : 0.f;
}

// ---------------------------------------------------------------------------
// Build layer input
// ---------------------------------------------------------------------------
__global__ void build_lay(const float* __restrict__ hf, const float* __restrict__ hb,
                          const int* __restrict__ len, float* __restrict__ lay) {
    int r = blockIdx.x;
    int b = r >> 9, tt = r & 511;
    int active = tt < len[b];
    int t = threadIdx.x;
    for (int i = t; i < D2; i += 256) {
        float v = 0.f;
        if (active) v = (i < HH) ? hf[(long)r * HH + i] : hb[(long)r * HH + i - HH];
        lay[(long)r * D2 + i] = v;
    }
}

// ---------------------------------------------------------------------------
// refined = LN(encoded + tanh(pre)) masked by valid
// ---------------------------------------------------------------------------
__global__ void refine_ln(const float* __restrict__ enc, const float* __restrict__ pre,
                          const float* __restrict__ g, const float* __restrict__ bta,
                          const int* __restrict__ len, float* __restrict__ out) {
    int r = blockIdx.x;
    int b = r >> 9, tt = r & 511;
    int t = threadIdx.x;
    __shared__ float r1[256], r2[256];
    float v[4];
    float s = 0.f, s2 = 0.f;
#pragma unroll
    for (int i = 0; i < 4; i++) {
        int idx = t + i * 256;
        float xx = enc[(long)r * D2 + idx] + tanhf(pre[(long)r * D2 + idx]);
        v[i] = xx; s += xx; s2 += xx * xx;
    }
    r1[t] = s; r2[t] = s2; __syncthreads();
    for (int st = 128; st > 0; st >>= 1) {
        if (t < st) { r1[t] += r1[t + st]; r2[t] += r2[t + st]; }
        __syncthreads();
    }
    float mean = r1[0] * (1.f / 1024.f);
    float var = r2[0] * (1.f / 1024.f) - mean * mean;
    float inv = rsqrtf(var + 1e-5f);
    int active = tt < len[b];
#pragma unroll
    for (int i = 0; i < 4; i++) {
        int idx = t + i * 256;
        float o = (v[i] - mean) * inv * g[idx] + bta[idx];
        out[(long)r * D2 + idx] = active ? o : 0.f;
    }
}

// ---------------------------------------------------------------------------
// head = LN(gelu_exact(hpre)) -> emit bf16 hi/lo split
// ---------------------------------------------------------------------------
__global__ void head_ln(const float* __restrict__ hpre, const float* __restrict__ g,
                        const float* __restrict__ bta,
                        __nv_bfloat16* __restrict__ hhi,
                        __nv_bfloat16* __restrict__ hlo) {
    int r = blockIdx.x;
    int t = threadIdx.x;
    __shared__ float r1[256], r2[256];
    float v[2];
    float s = 0.f, s2 = 0.f;
#pragma unroll
    for (int i = 0; i < 2; i++) {
        int idx = t + i * 256;
        float xx = hpre[(long)r * HH + idx];
        float ge = 0.5f * xx * (1.f + erff(xx * 0.70710678118654752f));
        v[i] = ge; s += ge; s2 += ge * ge;
    }
    r1[t] = s; r2[t] = s2; __syncthreads();
    for (int st = 128; st > 0; st >>= 1) {
        if (t < st) { r1[t] += r1[t + st]; r2[t] += r2[t + st]; }
        __syncthreads();
    }
    float mean = r1[0] * (1.f / 512.f);
    float var = r2[0] * (1.f / 512.f) - mean * mean;
    float inv = rsqrtf(var + 1e-5f);
#pragma unroll
    for (int i = 0; i < 2; i++) {
        int idx = t + i * 256;
        float o = (v[i] - mean) * inv * g[idx] + bta[idx];
        __nv_bfloat16 hi = __float2bfloat16(o);
        float lo = o - __bfloat162float(hi);
        hhi[(long)r * HH + idx] = hi;
        hlo[(long)r * HH + idx] = __float2bfloat16(lo);
    }
}

// ---------------------------------------------------------------------------
// Reset grid barrier counters
// ---------------------------------------------------------------------------
__global__ void reset_bar() { g_barcnt2[0] = 0u; g_barcnt2[1] = 0u; }

// ---------------------------------------------------------------------------
// Persistent BiLSTM scan — tensor-core GEMV version.
// 256 blocks: 0-127 fwd, 128-255 bwd (per-direction barriers, 128 arrivals).
// Block owns 4 hidden units = 16 gate cols. Weights staged once as bf16 hi/lo
// B-operand [16 cols][520]; h staged per step as bf16 hi/lo A-operand
// [16 rows][520] (rows 0-7 = batches, rows 8-15 zero pad).
// Warp w computes K slice [w*64, w*64+64) with m16n8k16 split-bf16 mma
// (AhiBhi + AhiBlo + AloBhi); cross-warp reduce via 1024-float smem.
// ---------------------------------------------------------------------------
#define LROW 520
#define LS_W   (16 * LROW)                 // elems per weight/operand array
#define LSTM_SMEM (4 * LS_W * 2 + 1024 * 4 + 128 * 4 + 32 * 4)

__global__ __launch_bounds__(256, 2) void lstm_scan(
    const float* __restrict__ xf, const float* __restrict__ xb,
    const float* __restrict__ Wrf, const float* __restrict__ Wrb,
    const float* __restrict__ h0f, const float* __restrict__ c0f,
    const float* __restrict__ h0b, const float* __restrict__ c0b,
    float* __restrict__ houtf, float* __restrict__ houtb,
    float* __restrict__ hcur, const int* __restrict__ len)
{
    extern __shared__ char smraw[];
    __nv_bfloat16* sWhi = (__nv_bfloat16*)smraw;
    __nv_bfloat16* sWlo = sWhi + LS_W;
    __nv_bfloat16* sAhi = sWlo + LS_W;
    __nv_bfloat16* sAlo = sAhi + LS_W;
    float* part  = (float*)(sAlo + LS_W);   // [8 warps][128]
    float* gates = part + 1024;             // [128]
    float* cst   = gates + 128;             // [32]

    const int tid  = threadIdx.x;
    const int warp = tid >> 5, lane = tid & 31;
    const int dir = blockIdx.x >> 7;
    const int kb  = blockIdx.x & 127;
    const int j0  = kb * 4;
    const float* Wr = dir ? Wrb : Wrf;
    const float* xp = dir ? xb : xf;
    const float* h0 = dir ? h0b : h0f;
    const float* c0 = dir ? c0b : c0f;
    float* hout  = dir ? houtb : houtf;
    float* hbase = hcur + dir * (2 * BB * HH);
    volatile unsigned* barp = &g_barcnt2[dir];

    // one-time weight stage (bf16 hi/lo, [col][k])
    {
        int col = tid & 15;
        int gcol = (col >> 2) * 512 + j0 + (col & 3);
        for (int k = tid >> 4; k < 512; k += 16) {
            float v = Wr[(long)k * G4 + gcol];
            __nv_bfloat16 hi = __float2bfloat16(v);
            sWhi[col * LROW + k] = hi;
            sWlo[col * LROW + k] = __float2bfloat16(v - __bfloat162float(hi));
        }
    }
    // zero A pad rows 8..15 (never rewritten)
    for (int f = tid; f < 8 * LROW; f += 256) {
        sAhi[8 * LROW + f] = __float2bfloat16(0.f);
        sAlo[8 * LROW + f] = __float2bfloat16(0.f);
    }
    if (tid < 32) {
        int u = tid >> 3, b = tid & 7;
        cst[u * 8 + b] = c0[j0 + u];
        __stcg(&hbase[(j0 + u) * 8 + b], h0[j0 + u]);
    }

    const uint32_t sAhiB = smem_u32(sAhi), sAloB = smem_u32(sAlo);
    const uint32_t sWhiB = smem_u32(sWhi), sWloB = smem_u32(sWlo);
    const int kbase = warp * 64;
    const uint32_t aoff = ((lane & 15) * LROW + kbase + ((lane >> 4) << 3)) * 2;
    const uint32_t boff = ((((lane >> 4) << 3) + (lane & 7)) * LROW + kbase +
                          (((lane >> 3) & 1) << 3)) * 2;

    unsigned phase = 1;
#define GRIDBAR()                                                         \
    do {                                                                  \
        __syncthreads();                                                  \
        if (tid == 0) {                                                   \
            __threadfence();                                              \
            atomicAdd((unsigned*)barp, 1u);                               \
            unsigned tgt = 128u * phase;                                  \
            while (*barp < tgt) {}                                        \
        }                                                                 \
        __syncthreads();                                                  \
        phase++;                                                          \
    } while (0)

    GRIDBAR();   // init h visible

    for (int s = 0; s < SS; s++) {
        const float* hrd = hbase + (s & 1) * (BB * HH);
        float* hwr = hbase + ((s + 1) & 1) * (BB * HH);
        const int t_real = dir ? (SS - 1 - s) : s;

        // prefetches (resolve during staging + mma)
        float xpv = 0.f;
        if (tid < 128) {
            int col = tid >> 3, b = tid & 7;
            xpv = __ldg(&xp[((long)(b * SS + t_real)) * G4 +
                            (col >> 2) * 512 + j0 + (col & 3)]);
        }
        float hpv = 0.f;
        if (tid < 32)
            hpv = __ldcg(&hrd[(j0 + (tid >> 3)) * 8 + (tid & 7)]);

        // stage h -> bf16 hi/lo A operand (rows = batch)
        {
            int b = tid & 7, kp = tid >> 3;   // kp 0..31
#pragma unroll
            for (int i = 0; i < 8; i++) {
                int k = (kp + 32 * i) * 2;
                float v0 = __ldcg(hrd + k * 8 + b);
                float v1 = __ldcg(hrd + (k + 1) * 8 + b);
                __nv_bfloat16 hh0 = __float2bfloat16(v0);
                __nv_bfloat16 hh1 = __float2bfloat16(v1);
                __nv_bfloat162 ph = {hh0, hh1};
                __nv_bfloat162 pl = {__float2bfloat16(v0 - __bfloat162float(hh0)),
                                     __float2bfloat16(v1 - __bfloat162float(hh1))};
                *(__nv_bfloat162*)&sAhi[b * LROW + k] = ph;
                *(__nv_bfloat162*)&sAlo[b * LROW + k] = pl;
            }
        }
        __syncthreads();

        // mma GEMV: warp's 64-wide K slice, dual accumulator sets
        float acA[2][4], acB[2][4];
#pragma unroll
        for (int nt = 0; nt < 2; nt++)
#pragma unroll
            for (int j = 0; j < 4; j++) { acA[nt][j] = 0.f; acB[nt][j] = 0.f; }
#pragma unroll
        for (int kk = 0; kk < 4; kk++) {
            uint32_t ah[4], al[4], bh4[4], bl4[4];
            ldsm_x4(ah[0], ah[1], ah[2], ah[3], sAhiB + aoff + kk * 32);
            ldsm_x4(al[0], al[1], al[2], al[3], sAloB + aoff + kk * 32);
            ldsm_x4(bh4[0], bh4[1], bh4[2], bh4[3], sWhiB + boff + kk * 32);
            ldsm_x4(bl4[0], bl4[1], bl4[2], bl4[3], sWloB + boff + kk * 32);
            float (*ac)[4] = (kk & 1) ? acB : acA;
            uint32_t bh0[2] = {bh4[0], bh4[1]}, bh1[2] = {bh4[2], bh4[3]};
            uint32_t bl0[2] = {bl4[0], bl4[1]}, bl1[2] = {bl4[2], bl4[3]};
            mma_bf16(ac[0], ah, bh0);
            mma_bf16(ac[0], ah, bl0);
            mma_bf16(ac[0], al, bh0);
            mma_bf16(ac[1], ah, bh1);
            mma_bf16(ac[1], ah, bl1);
            mma_bf16(ac[1], al, bh1);
        }
        {
            int g = lane >> 2, c2 = (lane & 3) * 2;
#pragma unroll
            for (int nt = 0; nt < 2; nt++) {
                part[warp * 128 + (nt * 8 + c2) * 8 + g]       = acA[nt][0] + acB[nt][0];
                part[warp * 128 + (nt * 8 + c2 + 1) * 8 + g]   = acA[nt][1] + acB[nt][1];
            }
        }
        __syncthreads();

        // cross-warp reduce + xp add
        if (tid < 128) {
            float ssum = xpv;
#pragma unroll
            for (int w = 0; w < 8; w++) ssum += part[w * 128 + tid];
            gates[tid] = ssum;
        }
        __syncthreads();

        // pointwise LSTM update
        if (tid < 32) {
            int u = tid >> 3, b = tid & 7;
            float ig = gates[(u) * 8 + b];
            float fg = gates[(4 + u) * 8 + b];
            float og = gates[(8 + u) * 8 + b];
            float gg = gates[(12 + u) * 8 + b];
            float cp = cst[u * 8 + b];
            float cn = sigm(fg) * cp + sigm(ig) * tanhf(gg);
            float hn = sigm(og) * tanhf(cn);
            int active = t_real < len[b];
            float h = active ? hn : hpv;
            float c = active ? cn : cp;
            cst[u * 8 + b] = c;
            __stcg(&hwr[(j0 + u) * 8 + b], h);
            hout[((long)(b * SS + t_real)) * HH + j0 + u] = h;
        }
        GRIDBAR();
    }
#undef GRIDBAR
}

// ---------------------------------------------------------------------------
// Host driver
// ---------------------------------------------------------------------------
extern "C" void kernel_launch(void* const* d_in, const int* in_sizes, int n_in,
                              void* d_out, int out_size) {
    const int*   x    = (const int*)  d_in[0];
    const float* emb  = (const float*)d_in[1];
    const float* Wf0  = (const float*)d_in[2];
    const float* bf0  = (const float*)d_in[3];
    const float* Wb0  = (const float*)d_in[4];
    const float* bb0  = (const float*)d_in[5];
    const float* Wf1  = (const float*)d_in[6];
    const float* bf1  = (const float*)d_in[7];
    const float* Wb1  = (const float*)d_in[8];
    const float* bb1  = (const float*)d_in[9];
    const float* h0f  = (const float*)d_in[10];
    const float* c0f  = (const float*)d_in[11];
    const float* h0b  = (const float*)d_in[12];
    const float* c0b  = (const float*)d_in[13];
    const float* Wq   = (const float*)d_in[14];
    const float* bq   = (const float*)d_in[15];
    const float* Wao  = (const float*)d_in[16];
    const float* bao  = (const float*)d_in[17];
    const float* ln1g = (const float*)d_in[18];
    const float* ln1b = (const float*)d_in[19];
    const float* Wh   = (const float*)d_in[20];
    const float* bh   = (const float*)d_in[21];
    const float* ln2g = (const float*)d_in[22];
    const float* ln2b = (const float*)d_in[23];
    const float* Wp   = (const float*)d_in[24];
    const float* ob   = (const float*)d_in[25];
    float* out = (float*)d_out;

    float *embx, *xf, *xb, *hf, *hb, *lay, *query, *scores, *ctx, *pre, *ref,
          *hpre, *hcur;
    __nv_bfloat16 *ahi, *alo, *bhi, *blo, *hhi, *hlo, *wpthi, *wptlo;
    int* len;
    cudaGetSymbolAddress((void**)&embx,   g_embx);
    cudaGetSymbolAddress((void**)&xf,     g_xf);
    cudaGetSymbolAddress((void**)&xb,     g_xb);
    cudaGetSymbolAddress((void**)&hf,     g_hf);
    cudaGetSymbolAddress((void**)&hb,     g_hb);
    cudaGetSymbolAddress((void**)&lay,    g_lay);
    cudaGetSymbolAddress((void**)&query,  g_query);
    cudaGetSymbolAddress((void**)&scores, g_scores);
    cudaGetSymbolAddress((void**)&ctx,    g_ctx);
    cudaGetSymbolAddress((void**)&pre,    g_pre);
    cudaGetSymbolAddress((void**)&ref,    g_ref);
    cudaGetSymbolAddress((void**)&hpre,   g_hpre);
    cudaGetSymbolAddress((void**)&hcur,   g_hcur);
    cudaGetSymbolAddress((void**)&len,    g_len);
    cudaGetSymbolAddress((void**)&ahi,    g_ahi);
    cudaGetSymbolAddress((void**)&alo,    g_alo);
    cudaGetSymbolAddress((void**)&bhi,    g_bhi);
    cudaGetSymbolAddress((void**)&blo,    g_blo);
    cudaGetSymbolAddress((void**)&hhi,    g_hhi);
    cudaGetSymbolAddress((void**)&hlo,    g_hlo);
    cudaGetSymbolAddress((void**)&wpthi,  g_wpthi);
    cudaGetSymbolAddress((void**)&wptlo,  g_wptlo);

    cudaFuncSetAttribute(lstm_scan, cudaFuncAttributeMaxDynamicSharedMemorySize,
                         LSTM_SMEM);
    cudaFuncSetAttribute(hgemm, cudaFuncAttributeMaxDynamicSharedMemorySize,
                         HGEMM_SMEM);

    len_kernel<<<BB, 512>>>(x, len);
    embed_kernel<<<NROW, 128>>>(x, emb, embx);
    wt_split<<<dim3(VV / 32, HH / 32), dim3(32, 8)>>>(Wp, VV, HH, wpthi, wptlo, 0, 0);

    // ---- layer 0 projections ----
    split_f32<<<(NROW * EE / 4 + 255) / 256, 256>>>(embx, ahi, alo, NROW * EE / 4);
    wt_split<<<dim3(G4 / 32, EE / 32), dim3(32, 8)>>>(Wf0, G4, EE, bhi, blo, 0, 0);
    hgemm<<<dim3(NROW / 128, G4 / 128), 256, HGEMM_SMEM>>>(
        ahi, alo, bhi, blo, bf0, xf, G4, EE, G4, 1.f, 0, 0, 0, 0);
    wt_split<<<dim3(G4 / 32, EE / 32), dim3(32, 8)>>>(Wb0, G4, EE, bhi, blo, 0, 0);
    hgemm<<<dim3(NROW / 128, G4 / 128), 256, HGEMM_SMEM>>>(
        ahi, alo, bhi, blo, bb0, xb, G4, EE, G4, 1.f, 0, 0, 0, 0);

    reset_bar<<<1, 1>>>();
    lstm_scan<<<256, 256, LSTM_SMEM>>>(xf, xb,
                                       Wf0 + (long)EE * G4, Wb0 + (long)EE * G4,
                                       h0f, c0f, h0b, c0b, hf, hb, hcur, len);
    build_lay<<<NROW, 256>>>(hf, hb, len, lay);

    // ---- layer 1 projections ----
    split_f32<<<(NROW * D2 / 4 + 255) / 256, 256>>>(lay, ahi, alo, NROW * D2 / 4);
    wt_split<<<dim3(G4 / 32, D2 / 32), dim3(32, 8)>>>(Wf1, G4, D2, bhi, blo, 0, 0);
    hgemm<<<dim3(NROW / 128, G4 / 128), 256, HGEMM_SMEM>>>(
        ahi, alo, bhi, blo, bf1, xf, G4, D2, G4, 1.f, 0, 0, 0, 0);
    wt_split<<<dim3(G4 / 32, D2 / 32), dim3(32, 8)>>>(Wb1, G4, D2, bhi, blo, 0, 0);
    hgemm<<<dim3(NROW / 128, G4 / 128), 256, HGEMM_SMEM>>>(
        ahi, alo, bhi, blo, bb1, xb, G4, D2, G4, 1.f, 0, 0, 0, 0);

    reset_bar<<<1, 1>>>();
    lstm_scan<<<256, 256, LSTM_SMEM>>>(xf, xb,
                                       Wf1 + (long)D2 * G4, Wb1 + (long)D2 * G4,
                                       h0f + HH, c0f + HH, h0b + HH, c0b + HH,
                                       hf, hb, hcur, len);
    build_lay<<<NROW, 256>>>(hf, hb, len, lay);  // lay = encoded

    // ---- attention ----
    split_f32<<<(NROW * D2 / 4 + 255) / 256, 256>>>(lay, ahi, alo, NROW * D2 / 4);
    wt_split<<<dim3(D2 / 32, D2 / 32), dim3(32, 8)>>>(Wq, D2, D2, bhi, blo, 0, 0);
    hgemm<<<dim3(NROW / 128, D2 / 128), 256, HGEMM_SMEM>>>(
        ahi, alo, bhi, blo, bq, query, D2, D2, D2, 1.f, 0, 0, 0, 0);
    split_f32<<<(NROW * D2 / 4 + 255) / 256, 256>>>(query, bhi, blo, NROW * D2 / 4);
    hgemm<<<dim3(SS / 128, SS / 128, BB), 256, HGEMM_SMEM>>>(
        bhi, blo, ahi, alo, nullptr, scores, SS, D2, SS, 0.03125f, 0,
        (long)SS * D2, (long)SS * D2, (long)SS * SS);
    softmax_kernel<<<dim3(SS, BB), 256>>>(scores, len);
    wt_split<<<dim3(D2 / 32, SS / 32, BB), dim3(32, 8)>>>(
        lay, D2, SS, bhi, blo, (long)SS * D2, (long)D2 * SS);
    split_f32<<<(BB * SS * SS / 4 + 255) / 256, 256>>>(scores, ahi, alo,
                                                       BB * SS * SS / 4);
    hgemm<<<dim3(SS / 128, D2 / 128, BB), 256, HGEMM_SMEM>>>(
        ahi, alo, bhi, blo, nullptr, ctx, D2, SS, D2, 1.f, 0,
        (long)SS * SS, (long)D2 * SS, (long)SS * D2);
    split_f32<<<(NROW * D2 / 4 + 255) / 256, 256>>>(lay, ahi, alo, NROW * D2 / 4);
    wt_split<<<dim3(D2 / 32, D2 / 32), dim3(32, 8)>>>(Wao, D2, D2, bhi, blo, 0, 0);
    hgemm<<<dim3(NROW / 128, D2 / 128), 256, HGEMM_SMEM>>>(
        ahi, alo, bhi, blo, bao, pre, D2, D2, D2, 1.f, 0, 0, 0, 0);
    split_f32<<<(NROW * D2 / 4 + 255) / 256, 256>>>(ctx, ahi, alo, NROW * D2 / 4);
    wt_split<<<dim3(D2 / 32, D2 / 32), dim3(32, 8)>>>(Wao + (long)D2 * D2, D2, D2,
                                                      bhi, blo, 0, 0);
    hgemm<<<dim3(NROW / 128, D2 / 128), 256, HGEMM_SMEM>>>(
        ahi, alo, bhi, blo, nullptr, pre, D2, D2, D2, 1.f, 1, 0, 0, 0);
    refine_ln<<<NROW, 256>>>(lay, pre, ln1g, ln1b, len, ref);

    // ---- head ----
    split_f32<<<(NROW * D2 / 4 + 255) / 256, 256>>>(ref, ahi, alo, NROW * D2 / 4);
    wt_split<<<dim3(HH / 32, D2 / 32), dim3(32, 8)>>>(Wh, HH, D2, bhi, blo, 0, 0);
    hgemm<<<dim3(NROW / 128, HH / 128), 256, HGEMM_SMEM>>>(
        ahi, alo, bhi, blo, bh, hpre, HH, D2, HH, 1.f, 0, 0, 0, 0);
    head_ln<<<NROW, 256>>>(hpre, ln2g, ln2b, hhi, hlo);

    // ---- vocab projection ----
    hgemm<<<dim3(NROW / 128, VV / 128), 256, HGEMM_SMEM>>>(
        hhi, hlo, wpthi, wptlo, ob, out, VV, HH, VV, 1.f, 0, 0, 0, 0);
}